// round 1
// baseline (speedup 1.0000x reference)
#include <cuda_runtime.h>
#include <math.h>

#define NQ 2048
#define NW 64
#define DD 512
#define D2 1024
#define TEMP_SC 16.0f
#define LN_EPS 1e-5f

// ---------------- scratch (__device__ globals; no allocation allowed) ----------------
__device__ float g_Q1[NQ * DD];   // q @ (ln1w .* w1_top)
__device__ float g_C1[NW * DD];   // c @ (ln1w .* w1_bot)
__device__ float g_s1[DD];        // colsum(ln1w .* w1)
__device__ float g_bb[DD];        // b1 + ln1b @ w1
__device__ float g_qsum[NQ];
__device__ float g_qssq[NQ];
__device__ float g_csum[NW];
__device__ float g_cssq[NW];
__device__ float g_chat[NW * DD]; // l2-normalized class memories
__device__ float g_swc[NW];       // sum_j ln2w_j * chat[w,j]
__device__ float g_sbc[NW];       // sum_j ln2b_j * chat[w,j]
__device__ float g_scal[3];       // sum ln2w^2, sum ln2w*ln2b, sum ln2b^2

// ---------------- per-row stats of q ----------------
__global__ void k_rowstats_q(const float* __restrict__ q) {
    int n = blockIdx.x, tid = threadIdx.x;
    float s = 0.f, ss = 0.f;
    for (int j = tid; j < DD; j += 256) {
        float v = q[n * DD + j];
        s += v; ss += v * v;
    }
    __shared__ float sA[8], sB[8];
    int lane = tid & 31, wid = tid >> 5;
#pragma unroll
    for (int o = 16; o; o >>= 1) {
        s  += __shfl_down_sync(0xffffffffu, s, o);
        ss += __shfl_down_sync(0xffffffffu, ss, o);
    }
    if (lane == 0) { sA[wid] = s; sB[wid] = ss; }
    __syncthreads();
    if (tid == 0) {
        float a = 0.f, b = 0.f;
#pragma unroll
        for (int i = 0; i < 8; i++) { a += sA[i]; b += sB[i]; }
        g_qsum[n] = a; g_qssq[n] = b;
    }
}

// ---------------- class-memory prep: stats, chat, swc/sbc ----------------
__global__ void k_prep_c(const float* __restrict__ cm,
                         const float* __restrict__ ln2w,
                         const float* __restrict__ ln2b) {
    int w = blockIdx.x, tid = threadIdx.x;
    float s = 0.f, ss = 0.f, sw = 0.f, sb = 0.f;
    for (int j = tid; j < DD; j += 256) {
        float v = cm[w * DD + j];
        s += v; ss += v * v;
        sw += ln2w[j] * v; sb += ln2b[j] * v;
    }
    __shared__ float sA[8], sB[8], sC[8], sD[8];
    __shared__ float rbc;
    int lane = tid & 31, wid = tid >> 5;
#pragma unroll
    for (int o = 16; o; o >>= 1) {
        s  += __shfl_down_sync(0xffffffffu, s,  o);
        ss += __shfl_down_sync(0xffffffffu, ss, o);
        sw += __shfl_down_sync(0xffffffffu, sw, o);
        sb += __shfl_down_sync(0xffffffffu, sb, o);
    }
    if (lane == 0) { sA[wid] = s; sB[wid] = ss; sC[wid] = sw; sD[wid] = sb; }
    __syncthreads();
    if (tid == 0) {
        float a = 0.f, b = 0.f, c = 0.f, d = 0.f;
#pragma unroll
        for (int i = 0; i < 8; i++) { a += sA[i]; b += sB[i]; c += sC[i]; d += sD[i]; }
        g_csum[w] = a; g_cssq[w] = b;
        float nn = sqrtf(b);
        float r = 1.f / fmaxf(nn, 1e-12f);
        rbc = r;
        g_swc[w] = r * c;
        g_sbc[w] = r * d;
    }
    __syncthreads();
    float r = rbc;
    for (int j = tid; j < DD; j += 256)
        g_chat[w * DD + j] = cm[w * DD + j] * r;
}

// ---------------- s1 / bb ----------------
__global__ void k_s1bb(const float* __restrict__ w1,
                       const float* __restrict__ ln1w,
                       const float* __restrict__ ln1b,
                       const float* __restrict__ b1) {
    int j = blockIdx.x * blockDim.x + threadIdx.x;
    if (j < DD) {
        float a = 0.f, b = 0.f;
        for (int i = 0; i < D2; i++) {
            float wv = w1[i * DD + j];
            a += ln1w[i] * wv;
            b += ln1b[i] * wv;
        }
        g_s1[j] = a;
        g_bb[j] = b1[j] + b;
    }
}

// ---------------- ln2 global scalars ----------------
__global__ void k_scal(const float* __restrict__ ln2w, const float* __restrict__ ln2b) {
    int tid = threadIdx.x;
    float a = 0.f, b = 0.f, c = 0.f;
    for (int j = tid; j < DD; j += 256) {
        float w = ln2w[j], bb = ln2b[j];
        a += w * w; b += w * bb; c += bb * bb;
    }
    __shared__ float sA[8], sB[8], sC[8];
    int lane = tid & 31, wid = tid >> 5;
#pragma unroll
    for (int o = 16; o; o >>= 1) {
        a += __shfl_down_sync(0xffffffffu, a, o);
        b += __shfl_down_sync(0xffffffffu, b, o);
        c += __shfl_down_sync(0xffffffffu, c, o);
    }
    if (lane == 0) { sA[wid] = a; sB[wid] = b; sC[wid] = c; }
    __syncthreads();
    if (tid == 0) {
        float x = 0.f, y = 0.f, z = 0.f;
#pragma unroll
        for (int i = 0; i < 8; i++) { x += sA[i]; y += sB[i]; z += sC[i]; }
        g_scal[0] = x; g_scal[1] = y; g_scal[2] = z;
    }
}

// ---------------- Q1 / C1: Out[m,j] = sum_i A[m,i]*ln1w[rowoff+i]*w1[(rowoff+i)*512 + j] ----------------
__global__ void k_gemm_fold(const float* __restrict__ A, int M,
                            const float* __restrict__ w1, int rowoff,
                            const float* __restrict__ lnw,
                            float* __restrict__ Out) {
    __shared__ float As[16][65];
    __shared__ float Bs[16][64];
    int m0 = blockIdx.x * 64, j0 = blockIdx.y * 64;
    int tid = threadIdx.x;
    int tr = tid >> 4, tc = tid & 15;
    int r0 = tr * 4, c0 = tc * 4;
    float acc[4][4] = {};
    for (int kc = 0; kc < DD; kc += 16) {
        __syncthreads();
#pragma unroll
        for (int e = 0; e < 4; e++) {
            int idx = tid + e * 256;
            int m = idx >> 4, kk = idx & 15;
            As[kk][m] = A[(m0 + m) * DD + kc + kk] * lnw[rowoff + kc + kk];
        }
#pragma unroll
        for (int e = 0; e < 4; e++) {
            int idx = tid + e * 256;
            int kk = idx >> 6, j = idx & 63;
            Bs[kk][j] = w1[(rowoff + kc + kk) * DD + j0 + j];
        }
        __syncthreads();
#pragma unroll
        for (int kk = 0; kk < 16; kk++) {
            float a0 = As[kk][r0], a1 = As[kk][r0 + 1], a2 = As[kk][r0 + 2], a3 = As[kk][r0 + 3];
            float b0 = Bs[kk][c0], b1 = Bs[kk][c0 + 1], b2 = Bs[kk][c0 + 2], b3 = Bs[kk][c0 + 3];
            acc[0][0] += a0 * b0; acc[0][1] += a0 * b1; acc[0][2] += a0 * b2; acc[0][3] += a0 * b3;
            acc[1][0] += a1 * b0; acc[1][1] += a1 * b1; acc[1][2] += a1 * b2; acc[1][3] += a1 * b3;
            acc[2][0] += a2 * b0; acc[2][1] += a2 * b1; acc[2][2] += a2 * b2; acc[2][3] += a2 * b3;
            acc[3][0] += a3 * b0; acc[3][1] += a3 * b1; acc[3][2] += a3 * b2; acc[3][3] += a3 * b3;
        }
    }
#pragma unroll
    for (int i = 0; i < 4; i++)
#pragma unroll
        for (int j = 0; j < 4; j++)
            Out[(m0 + r0 + i) * DD + j0 + c0 + j] = acc[i][j];
}

// ---------------- main fused kernel: one CTA per n ----------------
#define TPB 256
#define KC 32
#define NCH 64

#define OFF_GT   0                     // 512 * 65 = 33280
#define OFF_BS   33280                 // 2 * 2048 = 4096
#define OFF_T    (OFF_BS + 4096)      // 512
#define OFF_Q1   (OFF_T + 512)        // 512
#define OFF_S1   (OFF_Q1 + 512)       // 512
#define OFF_BB   (OFF_S1 + 512)       // 512
#define OFF_LW   (OFF_BB + 512)       // 512
#define OFF_LB   (OFF_LW + 512)       // 512
#define OFF_MU   (OFF_LB + 512)       // 64
#define OFF_INV  (OFF_MU + 64)        // 64
#define OFF_RED  (OFF_INV + 64)       // 6 * 64
#define SMEM_FLOATS (OFF_RED + 384)   // 40960 floats = 163840 bytes

__global__ void k_main(const float* __restrict__ q,
                       const float* __restrict__ w2,
                       const float* __restrict__ b2,
                       const float* __restrict__ ln2w,
                       const float* __restrict__ ln2b,
                       float* __restrict__ out) {
    extern __shared__ float sm[];
    float* Gt   = sm + OFF_GT;   // [512][65]  (transposed gelu tile, padded)
    float* Bsm  = sm + OFF_BS;   // [2][32][64]
    float* ts   = sm + OFF_T;
    float* Q1s  = sm + OFF_Q1;
    float* s1s  = sm + OFF_S1;
    float* bbs  = sm + OFF_BB;
    float* lws  = sm + OFF_LW;
    float* lbs  = sm + OFF_LB;
    float* mus  = sm + OFF_MU;
    float* invs = sm + OFF_INV;
    float* red  = sm + OFF_RED;  // [6][64]

    const int n = blockIdx.x;
    const int tid = threadIdx.x;

    for (int j = tid; j < DD; j += TPB) {
        Q1s[j] = g_Q1[n * DD + j];
        s1s[j] = g_s1[j];
        bbs[j] = g_bb[j];
        ts[j]  = b2[j] + q[n * DD + j];
        lws[j] = ln2w[j];
        lbs[j] = ln2b[j];
    }
    if (tid < NW) {
        float sx  = g_qsum[n] + g_csum[tid];
        float sxx = g_qssq[n] + g_cssq[tid];
        float m = sx * (1.f / 1024.f);
        float var = sxx * (1.f / 1024.f) - m * m;
        mus[tid]  = m;
        invs[tid] = rsqrtf(var + LN_EPS);
#pragma unroll
        for (int s = 0; s < 6; s++) red[s * NW + tid] = 0.f;
    }
    __syncthreads();

    // build gelu(LN1-decomposed h1) tile, transposed: Gt[k][w]
    for (int r = 0; r < NW; r++) {
        float m = mus[r], iv = invs[r];
#pragma unroll
        for (int jj = 0; jj < DD / TPB; jj++) {
            int j = jj * TPB + tid;
            float h = iv * (Q1s[j] + g_C1[r * DD + j] - m * s1s[j]) + bbs[j];
            float g = 0.5f * h * (1.f + erff(h * 0.70710678118654752f));
            Gt[j * 65 + r] = g;
        }
    }
    __syncthreads();

    const int tr = tid >> 4, tc = tid & 15;
    const int r0 = tr * 4;
    float pre[8];

    for (int j0 = 0; j0 < DD; j0 += NCH) {
        float acc[4][4];
#pragma unroll
        for (int i = 0; i < 4; i++)
#pragma unroll
            for (int j = 0; j < 4; j++) acc[i][j] = 0.f;

        // stage chunk 0 of B (w2 rows 0..31, cols j0..j0+63)
#pragma unroll
        for (int e = 0; e < 8; e++) {
            int idx = tid + e * TPB;
            pre[e] = w2[(idx >> 6) * DD + j0 + (idx & 63)];
        }
#pragma unroll
        for (int e = 0; e < 8; e++) Bsm[tid + e * TPB] = pre[e];
        __syncthreads();

        int buf = 0;
        for (int kc = 0; kc < DD; kc += KC) {
            bool more = (kc + KC < DD);
            if (more) {
#pragma unroll
                for (int e = 0; e < 8; e++) {
                    int idx = tid + e * TPB;
                    pre[e] = w2[(kc + KC + (idx >> 6)) * DD + j0 + (idx & 63)];
                }
            }
            const float* Bp = Bsm + buf * 2048;
#pragma unroll
            for (int kk = 0; kk < KC; kk++) {
                const float* gt = Gt + (kc + kk) * 65 + r0;
                float a0 = gt[0], a1 = gt[1], a2 = gt[2], a3 = gt[3];
                float4 b = *reinterpret_cast<const float4*>(Bp + kk * 64 + tc * 4);
                acc[0][0] += a0 * b.x; acc[0][1] += a0 * b.y; acc[0][2] += a0 * b.z; acc[0][3] += a0 * b.w;
                acc[1][0] += a1 * b.x; acc[1][1] += a1 * b.y; acc[1][2] += a1 * b.z; acc[1][3] += a1 * b.w;
                acc[2][0] += a2 * b.x; acc[2][1] += a2 * b.y; acc[2][2] += a2 * b.z; acc[2][3] += a2 * b.w;
                acc[3][0] += a3 * b.x; acc[3][1] += a3 * b.y; acc[3][2] += a3 * b.z; acc[3][3] += a3 * b.w;
            }
            __syncthreads();
            if (more) {
#pragma unroll
                for (int e = 0; e < 8; e++) Bsm[(buf ^ 1) * 2048 + tid + e * TPB] = pre[e];
                __syncthreads();
                buf ^= 1;
            }
        }

        // fused epilogue: v = acc + t;  accumulate six per-row moments
#pragma unroll
        for (int i = 0; i < 4; i++) {
            int row = r0 + i;
            float p0 = 0.f, p1 = 0.f, pA = 0.f, pB = 0.f, pC = 0.f, pE = 0.f;
#pragma unroll
            for (int j = 0; j < 4; j++) {
                int col = j0 + tc * 4 + j;
                float v  = acc[i][j] + ts[col];
                float wj = lws[col], bj = lbs[col];
                float ch = g_chat[row * DD + col];
                float vw = v * wj;
                p0 += v;       p1 += v * v;
                pA += vw * ch; pB += vw * vw;
                pC += vw * wj; pE += vw * bj;
            }
#pragma unroll
            for (int o = 8; o; o >>= 1) {
                p0 += __shfl_down_sync(0xffffffffu, p0, o, 16);
                p1 += __shfl_down_sync(0xffffffffu, p1, o, 16);
                pA += __shfl_down_sync(0xffffffffu, pA, o, 16);
                pB += __shfl_down_sync(0xffffffffu, pB, o, 16);
                pC += __shfl_down_sync(0xffffffffu, pC, o, 16);
                pE += __shfl_down_sync(0xffffffffu, pE, o, 16);
            }
            if (tc == 0) {
                red[0 * NW + row] += p0; red[1 * NW + row] += p1; red[2 * NW + row] += pA;
                red[3 * NW + row] += pB; red[4 * NW + row] += pC; red[5 * NW + row] += pE;
            }
        }
        __syncthreads();
    }

    if (tid < NW) {
        int w = tid;
        float m0 = red[0 * NW + w], m1 = red[1 * NW + w], A = red[2 * NW + w];
        float B  = red[3 * NW + w], C  = red[4 * NW + w], E = red[5 * NW + w];
        float mu2 = m0 * (1.f / DD);
        float var = m1 * (1.f / DD) - mu2 * mu2;
        float k = rsqrtf(var + LN_EPS);
        float sww = g_scal[0], swb = g_scal[1], sbb = g_scal[2];
        float doty = k * (A - mu2 * g_swc[w]) + g_sbc[w];
        float ny2 = k * k * (B - 2.f * mu2 * C + mu2 * mu2 * sww)
                  + 2.f * k * (E - mu2 * swb) + sbb;
        float ny = sqrtf(fmaxf(ny2, 0.f));
        out[n * NW + w] = TEMP_SC * doty / fmaxf(ny, 1e-12f);
    }
}

// ---------------- launch ----------------
extern "C" void kernel_launch(void* const* d_in, const int* in_sizes, int n_in,
                              void* d_out, int out_size) {
    const float* q    = (const float*)d_in[0];
    const float* cm   = (const float*)d_in[1];
    const float* ln1w = (const float*)d_in[2];
    const float* ln1b = (const float*)d_in[3];
    const float* w1   = (const float*)d_in[4];
    const float* b1   = (const float*)d_in[5];
    const float* w2   = (const float*)d_in[6];
    const float* b2   = (const float*)d_in[7];
    const float* ln2w = (const float*)d_in[8];
    const float* ln2b = (const float*)d_in[9];
    float* out = (float*)d_out;

    float *pQ1, *pC1;
    cudaGetSymbolAddress((void**)&pQ1, g_Q1);
    cudaGetSymbolAddress((void**)&pC1, g_C1);

    cudaFuncSetAttribute(k_main, cudaFuncAttributeMaxDynamicSharedMemorySize,
                         SMEM_FLOATS * (int)sizeof(float));

    k_rowstats_q<<<NQ, 256>>>(q);
    k_prep_c<<<NW, 256>>>(cm, ln2w, ln2b);
    k_s1bb<<<2, 256>>>(w1, ln1w, ln1b, b1);
    k_scal<<<1, 256>>>(ln2w, ln2b);
    k_gemm_fold<<<dim3(NQ / 64, DD / 64), 256>>>(q,  NQ, w1, 0,   ln1w, pQ1);
    k_gemm_fold<<<dim3(NW / 64, DD / 64), 256>>>(cm, NW, w1, 512, ln1w, pC1);
    k_main<<<NQ, TPB, SMEM_FLOATS * sizeof(float)>>>(q, w2, b2, ln2w, ln2b, out);
}

// round 2
// speedup vs baseline: 1.0004x; 1.0004x over previous
#include <cuda_runtime.h>
#include <math.h>

#define NQ 2048
#define NW 64
#define DD 512
#define D2 1024
#define TEMP_SC 16.0f
#define LN_EPS 1e-5f

// ---------------- scratch (__device__ globals; no allocation allowed) ----------------
__device__ float g_Q1[NQ * DD];   // q @ (ln1w .* w1_top)
__device__ float g_C1[NW * DD];   // c @ (ln1w .* w1_bot)
__device__ float g_s1[DD];        // colsum(ln1w .* w1)
__device__ float g_bb[DD];        // b1 + ln1b @ w1
__device__ float g_qsum[NQ];
__device__ float g_qssq[NQ];
__device__ float g_csum[NW];
__device__ float g_cssq[NW];
__device__ float g_chat[NW * DD]; // l2-normalized class memories
__device__ float g_swc[NW];       // sum_j ln2w_j * chat[w,j]
__device__ float g_sbc[NW];       // sum_j ln2b_j * chat[w,j]
__device__ float g_scal[3];       // sum ln2w^2, sum ln2w*ln2b, sum ln2b^2

// ---------------- per-row stats of q ----------------
__global__ void k_rowstats_q(const float* __restrict__ q) {
    int n = blockIdx.x, tid = threadIdx.x;
    float s = 0.f, ss = 0.f;
    for (int j = tid; j < DD; j += 256) {
        float v = q[n * DD + j];
        s += v; ss += v * v;
    }
    __shared__ float sA[8], sB[8];
    int lane = tid & 31, wid = tid >> 5;
#pragma unroll
    for (int o = 16; o; o >>= 1) {
        s  += __shfl_down_sync(0xffffffffu, s, o);
        ss += __shfl_down_sync(0xffffffffu, ss, o);
    }
    if (lane == 0) { sA[wid] = s; sB[wid] = ss; }
    __syncthreads();
    if (tid == 0) {
        float a = 0.f, b = 0.f;
#pragma unroll
        for (int i = 0; i < 8; i++) { a += sA[i]; b += sB[i]; }
        g_qsum[n] = a; g_qssq[n] = b;
    }
}

// ---------------- class-memory prep: stats, chat, swc/sbc ----------------
__global__ void k_prep_c(const float* __restrict__ cm,
                         const float* __restrict__ ln2w,
                         const float* __restrict__ ln2b) {
    int w = blockIdx.x, tid = threadIdx.x;
    float s = 0.f, ss = 0.f, sw = 0.f, sb = 0.f;
    for (int j = tid; j < DD; j += 256) {
        float v = cm[w * DD + j];
        s += v; ss += v * v;
        sw += ln2w[j] * v; sb += ln2b[j] * v;
    }
    __shared__ float sA[8], sB[8], sC[8], sD[8];
    __shared__ float rbc;
    int lane = tid & 31, wid = tid >> 5;
#pragma unroll
    for (int o = 16; o; o >>= 1) {
        s  += __shfl_down_sync(0xffffffffu, s,  o);
        ss += __shfl_down_sync(0xffffffffu, ss, o);
        sw += __shfl_down_sync(0xffffffffu, sw, o);
        sb += __shfl_down_sync(0xffffffffu, sb, o);
    }
    if (lane == 0) { sA[wid] = s; sB[wid] = ss; sC[wid] = sw; sD[wid] = sb; }
    __syncthreads();
    if (tid == 0) {
        float a = 0.f, b = 0.f, c = 0.f, d = 0.f;
#pragma unroll
        for (int i = 0; i < 8; i++) { a += sA[i]; b += sB[i]; c += sC[i]; d += sD[i]; }
        g_csum[w] = a; g_cssq[w] = b;
        float nn = sqrtf(b);
        float r = 1.f / fmaxf(nn, 1e-12f);
        rbc = r;
        g_swc[w] = r * c;
        g_sbc[w] = r * d;
    }
    __syncthreads();
    float r = rbc;
    for (int j = tid; j < DD; j += 256)
        g_chat[w * DD + j] = cm[w * DD + j] * r;
}

// ---------------- s1 / bb ----------------
__global__ void k_s1bb(const float* __restrict__ w1,
                       const float* __restrict__ ln1w,
                       const float* __restrict__ ln1b,
                       const float* __restrict__ b1) {
    int j = blockIdx.x * blockDim.x + threadIdx.x;
    if (j < DD) {
        float a = 0.f, b = 0.f;
        for (int i = 0; i < D2; i++) {
            float wv = w1[i * DD + j];
            a += ln1w[i] * wv;
            b += ln1b[i] * wv;
        }
        g_s1[j] = a;
        g_bb[j] = b1[j] + b;
    }
}

// ---------------- ln2 global scalars ----------------
__global__ void k_scal(const float* __restrict__ ln2w, const float* __restrict__ ln2b) {
    int tid = threadIdx.x;
    float a = 0.f, b = 0.f, c = 0.f;
    for (int j = tid; j < DD; j += 256) {
        float w = ln2w[j], bb = ln2b[j];
        a += w * w; b += w * bb; c += bb * bb;
    }
    __shared__ float sA[8], sB[8], sC[8];
    int lane = tid & 31, wid = tid >> 5;
#pragma unroll
    for (int o = 16; o; o >>= 1) {
        a += __shfl_down_sync(0xffffffffu, a, o);
        b += __shfl_down_sync(0xffffffffu, b, o);
        c += __shfl_down_sync(0xffffffffu, c, o);
    }
    if (lane == 0) { sA[wid] = a; sB[wid] = b; sC[wid] = c; }
    __syncthreads();
    if (tid == 0) {
        float x = 0.f, y = 0.f, z = 0.f;
#pragma unroll
        for (int i = 0; i < 8; i++) { x += sA[i]; y += sB[i]; z += sC[i]; }
        g_scal[0] = x; g_scal[1] = y; g_scal[2] = z;
    }
}

// ---------------- Q1 / C1: Out[m,j] = sum_i A[m,i]*ln1w[rowoff+i]*w1[(rowoff+i)*512 + j] ----------------
__global__ void k_gemm_fold(const float* __restrict__ A, int M,
                            const float* __restrict__ w1, int rowoff,
                            const float* __restrict__ lnw,
                            float* __restrict__ Out) {
    __shared__ float As[16][65];
    __shared__ float Bs[16][64];
    int m0 = blockIdx.x * 64, j0 = blockIdx.y * 64;
    int tid = threadIdx.x;
    int tr = tid >> 4, tc = tid & 15;
    int r0 = tr * 4, c0 = tc * 4;
    float acc[4][4] = {};
    for (int kc = 0; kc < DD; kc += 16) {
        __syncthreads();
#pragma unroll
        for (int e = 0; e < 4; e++) {
            int idx = tid + e * 256;
            int m = idx >> 4, kk = idx & 15;
            As[kk][m] = A[(m0 + m) * DD + kc + kk] * lnw[rowoff + kc + kk];
        }
#pragma unroll
        for (int e = 0; e < 4; e++) {
            int idx = tid + e * 256;
            int kk = idx >> 6, j = idx & 63;
            Bs[kk][j] = w1[(rowoff + kc + kk) * DD + j0 + j];
        }
        __syncthreads();
#pragma unroll
        for (int kk = 0; kk < 16; kk++) {
            float a0 = As[kk][r0], a1 = As[kk][r0 + 1], a2 = As[kk][r0 + 2], a3 = As[kk][r0 + 3];
            float b0 = Bs[kk][c0], b1 = Bs[kk][c0 + 1], b2 = Bs[kk][c0 + 2], b3 = Bs[kk][c0 + 3];
            acc[0][0] += a0 * b0; acc[0][1] += a0 * b1; acc[0][2] += a0 * b2; acc[0][3] += a0 * b3;
            acc[1][0] += a1 * b0; acc[1][1] += a1 * b1; acc[1][2] += a1 * b2; acc[1][3] += a1 * b3;
            acc[2][0] += a2 * b0; acc[2][1] += a2 * b1; acc[2][2] += a2 * b2; acc[2][3] += a2 * b3;
            acc[3][0] += a3 * b0; acc[3][1] += a3 * b1; acc[3][2] += a3 * b2; acc[3][3] += a3 * b3;
        }
    }
#pragma unroll
    for (int i = 0; i < 4; i++)
#pragma unroll
        for (int j = 0; j < 4; j++)
            Out[(m0 + r0 + i) * DD + j0 + c0 + j] = acc[i][j];
}

// ---------------- main fused kernel: one CTA per n ----------------
#define TPB 256
#define KC 32
#define NCH 64

#define OFF_GT   0                     // 512 * 65 = 33280
#define OFF_BS   33280                 // 2 * 2048 = 4096
#define OFF_T    (OFF_BS + 4096)      // 512
#define OFF_Q1   (OFF_T + 512)        // 512
#define OFF_S1   (OFF_Q1 + 512)       // 512
#define OFF_BB   (OFF_S1 + 512)       // 512
#define OFF_LW   (OFF_BB + 512)       // 512
#define OFF_LB   (OFF_LW + 512)       // 512
#define OFF_MU   (OFF_LB + 512)       // 64
#define OFF_INV  (OFF_MU + 64)        // 64
#define OFF_RED  (OFF_INV + 64)       // 6 * 64
#define SMEM_FLOATS (OFF_RED + 384)   // 40960 floats = 163840 bytes

__global__ void k_main(const float* __restrict__ q,
                       const float* __restrict__ w2,
                       const float* __restrict__ b2,
                       const float* __restrict__ ln2w,
                       const float* __restrict__ ln2b,
                       float* __restrict__ out) {
    extern __shared__ float sm[];
    float* Gt   = sm + OFF_GT;   // [512][65]  (transposed gelu tile, padded)
    float* Bsm  = sm + OFF_BS;   // [2][32][64]
    float* ts   = sm + OFF_T;
    float* Q1s  = sm + OFF_Q1;
    float* s1s  = sm + OFF_S1;
    float* bbs  = sm + OFF_BB;
    float* lws  = sm + OFF_LW;
    float* lbs  = sm + OFF_LB;
    float* mus  = sm + OFF_MU;
    float* invs = sm + OFF_INV;
    float* red  = sm + OFF_RED;  // [6][64]

    const int n = blockIdx.x;
    const int tid = threadIdx.x;

    for (int j = tid; j < DD; j += TPB) {
        Q1s[j] = g_Q1[n * DD + j];
        s1s[j] = g_s1[j];
        bbs[j] = g_bb[j];
        ts[j]  = b2[j] + q[n * DD + j];
        lws[j] = ln2w[j];
        lbs[j] = ln2b[j];
    }
    if (tid < NW) {
        float sx  = g_qsum[n] + g_csum[tid];
        float sxx = g_qssq[n] + g_cssq[tid];
        float m = sx * (1.f / 1024.f);
        float var = sxx * (1.f / 1024.f) - m * m;
        mus[tid]  = m;
        invs[tid] = rsqrtf(var + LN_EPS);
#pragma unroll
        for (int s = 0; s < 6; s++) red[s * NW + tid] = 0.f;
    }
    __syncthreads();

    // build gelu(LN1-decomposed h1) tile, transposed: Gt[k][w]
    for (int r = 0; r < NW; r++) {
        float m = mus[r], iv = invs[r];
#pragma unroll
        for (int jj = 0; jj < DD / TPB; jj++) {
            int j = jj * TPB + tid;
            float h = iv * (Q1s[j] + g_C1[r * DD + j] - m * s1s[j]) + bbs[j];
            float g = 0.5f * h * (1.f + erff(h * 0.70710678118654752f));
            Gt[j * 65 + r] = g;
        }
    }
    __syncthreads();

    const int tr = tid >> 4, tc = tid & 15;
    const int r0 = tr * 4;
    float pre[8];

    for (int j0 = 0; j0 < DD; j0 += NCH) {
        float acc[4][4];
#pragma unroll
        for (int i = 0; i < 4; i++)
#pragma unroll
            for (int j = 0; j < 4; j++) acc[i][j] = 0.f;

        // stage chunk 0 of B (w2 rows 0..31, cols j0..j0+63)
#pragma unroll
        for (int e = 0; e < 8; e++) {
            int idx = tid + e * TPB;
            pre[e] = w2[(idx >> 6) * DD + j0 + (idx & 63)];
        }
#pragma unroll
        for (int e = 0; e < 8; e++) Bsm[tid + e * TPB] = pre[e];
        __syncthreads();

        int buf = 0;
        for (int kc = 0; kc < DD; kc += KC) {
            bool more = (kc + KC < DD);
            if (more) {
#pragma unroll
                for (int e = 0; e < 8; e++) {
                    int idx = tid + e * TPB;
                    pre[e] = w2[(kc + KC + (idx >> 6)) * DD + j0 + (idx & 63)];
                }
            }
            const float* Bp = Bsm + buf * 2048;
#pragma unroll
            for (int kk = 0; kk < KC; kk++) {
                const float* gt = Gt + (kc + kk) * 65 + r0;
                float a0 = gt[0], a1 = gt[1], a2 = gt[2], a3 = gt[3];
                float4 b = *reinterpret_cast<const float4*>(Bp + kk * 64 + tc * 4);
                acc[0][0] += a0 * b.x; acc[0][1] += a0 * b.y; acc[0][2] += a0 * b.z; acc[0][3] += a0 * b.w;
                acc[1][0] += a1 * b.x; acc[1][1] += a1 * b.y; acc[1][2] += a1 * b.z; acc[1][3] += a1 * b.w;
                acc[2][0] += a2 * b.x; acc[2][1] += a2 * b.y; acc[2][2] += a2 * b.z; acc[2][3] += a2 * b.w;
                acc[3][0] += a3 * b.x; acc[3][1] += a3 * b.y; acc[3][2] += a3 * b.z; acc[3][3] += a3 * b.w;
            }
            __syncthreads();
            if (more) {
#pragma unroll
                for (int e = 0; e < 8; e++) Bsm[(buf ^ 1) * 2048 + tid + e * TPB] = pre[e];
                __syncthreads();
                buf ^= 1;
            }
        }

        // fused epilogue: v = acc + t;  accumulate six per-row moments
#pragma unroll
        for (int i = 0; i < 4; i++) {
            int row = r0 + i;
            float p0 = 0.f, p1 = 0.f, pA = 0.f, pB = 0.f, pC = 0.f, pE = 0.f;
#pragma unroll
            for (int j = 0; j < 4; j++) {
                int col = j0 + tc * 4 + j;
                float v  = acc[i][j] + ts[col];
                float wj = lws[col], bj = lbs[col];
                float ch = g_chat[row * DD + col];
                float vw = v * wj;
                p0 += v;       p1 += v * v;
                pA += vw * ch; pB += vw * vw;
                pC += vw * wj; pE += vw * bj;
            }
#pragma unroll
            for (int o = 8; o; o >>= 1) {
                p0 += __shfl_down_sync(0xffffffffu, p0, o, 16);
                p1 += __shfl_down_sync(0xffffffffu, p1, o, 16);
                pA += __shfl_down_sync(0xffffffffu, pA, o, 16);
                pB += __shfl_down_sync(0xffffffffu, pB, o, 16);
                pC += __shfl_down_sync(0xffffffffu, pC, o, 16);
                pE += __shfl_down_sync(0xffffffffu, pE, o, 16);
            }
            if (tc == 0) {
                red[0 * NW + row] += p0; red[1 * NW + row] += p1; red[2 * NW + row] += pA;
                red[3 * NW + row] += pB; red[4 * NW + row] += pC; red[5 * NW + row] += pE;
            }
        }
        __syncthreads();
    }

    if (tid < NW) {
        int w = tid;
        float m0 = red[0 * NW + w], m1 = red[1 * NW + w], A = red[2 * NW + w];
        float B  = red[3 * NW + w], C  = red[4 * NW + w], E = red[5 * NW + w];
        float mu2 = m0 * (1.f / DD);
        float var = m1 * (1.f / DD) - mu2 * mu2;
        float k = rsqrtf(var + LN_EPS);
        float sww = g_scal[0], swb = g_scal[1], sbb = g_scal[2];
        float doty = k * (A - mu2 * g_swc[w]) + g_sbc[w];
        float ny2 = k * k * (B - 2.f * mu2 * C + mu2 * mu2 * sww)
                  + 2.f * k * (E - mu2 * swb) + sbb;
        float ny = sqrtf(fmaxf(ny2, 0.f));
        out[n * NW + w] = TEMP_SC * doty / fmaxf(ny, 1e-12f);
    }
}

// ---------------- launch ----------------
extern "C" void kernel_launch(void* const* d_in, const int* in_sizes, int n_in,
                              void* d_out, int out_size) {
    const float* q    = (const float*)d_in[0];
    const float* cm   = (const float*)d_in[1];
    const float* ln1w = (const float*)d_in[2];
    const float* ln1b = (const float*)d_in[3];
    const float* w1   = (const float*)d_in[4];
    const float* b1   = (const float*)d_in[5];
    const float* w2   = (const float*)d_in[6];
    const float* b2   = (const float*)d_in[7];
    const float* ln2w = (const float*)d_in[8];
    const float* ln2b = (const float*)d_in[9];
    float* out = (float*)d_out;

    float *pQ1, *pC1;
    cudaGetSymbolAddress((void**)&pQ1, g_Q1);
    cudaGetSymbolAddress((void**)&pC1, g_C1);

    cudaFuncSetAttribute(k_main, cudaFuncAttributeMaxDynamicSharedMemorySize,
                         SMEM_FLOATS * (int)sizeof(float));

    k_rowstats_q<<<NQ, 256>>>(q);
    k_prep_c<<<NW, 256>>>(cm, ln2w, ln2b);
    k_s1bb<<<2, 256>>>(w1, ln1w, ln1b, b1);
    k_scal<<<1, 256>>>(ln2w, ln2b);
    k_gemm_fold<<<dim3(NQ / 64, DD / 64), 256>>>(q,  NQ, w1, 0,   ln1w, pQ1);
    k_gemm_fold<<<dim3(NW / 64, DD / 64), 256>>>(cm, NW, w1, 512, ln1w, pC1);
    k_main<<<NQ, TPB, SMEM_FLOATS * sizeof(float)>>>(q, w2, b2, ln2w, ln2b, out);
}

// round 5
// speedup vs baseline: 2.1855x; 2.1846x over previous
#include <cuda_runtime.h>
#include <cuda_bf16.h>
#include <math.h>
#include <stdint.h>
#include <cstdint>

#define NQ 2048
#define NW 64
#define DD 512
#define D2 1024
#define TEMP_SC 16.0f
#define LN_EPS 1e-5f

// ---------------- scratch ----------------
__device__ float g_Q1[NQ * DD];
__device__ float g_C1[NW * DD];
__device__ float g_s1[DD];
__device__ float g_bb[DD];
__device__ float g_qsum[NQ];
__device__ float g_qssq[NQ];
__device__ float g_csum[NW];
__device__ float g_cssq[NW];
__device__ float g_chatT[DD * NW];     // [j][w]
__device__ float g_swc[NW];
__device__ float g_sbc[NW];
__device__ float g_scal[3];
__device__ __align__(128) __nv_bfloat16 g_w2thi[DD * DD];  // w2^T [j][k] hi
__device__ __align__(128) __nv_bfloat16 g_w2tlo[DD * DD];  // w2^T [j][k] lo
__device__ float g_part[24 * NQ * NW]; // [ch*6+m][n*64+w]

#define SWZ(o) ((o) ^ (((o) >> 3) & 0x70))

// ================= helpers =================
__device__ __forceinline__ uint32_t smem_u32(const void* p) {
    uint32_t a;
    asm("{ .reg .u64 t; cvta.to.shared.u64 t, %1; cvt.u32.u64 %0, t; }" : "=r"(a) : "l"(p));
    return a;
}
__device__ __forceinline__ void cp16(uint32_t s, const void* g) {
    asm volatile("cp.async.cg.shared.global [%0], [%1], 16;" :: "r"(s), "l"(g));
}
__device__ __forceinline__ void ldsm4(uint32_t* r, uint32_t a) {
    asm volatile("ldmatrix.sync.aligned.m8n8.x4.shared.b16 {%0,%1,%2,%3}, [%4];"
                 : "=r"(r[0]), "=r"(r[1]), "=r"(r[2]), "=r"(r[3]) : "r"(a));
}
__device__ __forceinline__ void mma16816(float* d, const uint32_t* a, const uint32_t* b) {
    asm volatile("mma.sync.aligned.m16n8k16.row.col.f32.bf16.bf16.f32 "
                 "{%0,%1,%2,%3}, {%4,%5,%6,%7}, {%8,%9}, {%0,%1,%2,%3};"
                 : "+f"(d[0]), "+f"(d[1]), "+f"(d[2]), "+f"(d[3])
                 : "r"(a[0]), "r"(a[1]), "r"(a[2]), "r"(a[3]), "r"(b[0]), "r"(b[1]));
}

// ================= phase A =================
__global__ void k_rowstats_q(const float* __restrict__ q) {
    int n = blockIdx.x, tid = threadIdx.x;
    float s = 0.f, ss = 0.f;
    for (int j = tid; j < DD; j += 256) { float v = q[n * DD + j]; s += v; ss += v * v; }
    __shared__ float sA[8], sB[8];
    int lane = tid & 31, wid = tid >> 5;
#pragma unroll
    for (int o = 16; o; o >>= 1) {
        s  += __shfl_down_sync(0xffffffffu, s, o);
        ss += __shfl_down_sync(0xffffffffu, ss, o);
    }
    if (lane == 0) { sA[wid] = s; sB[wid] = ss; }
    __syncthreads();
    if (tid == 0) {
        float a = 0.f, b = 0.f;
#pragma unroll
        for (int i = 0; i < 8; i++) { a += sA[i]; b += sB[i]; }
        g_qsum[n] = a; g_qssq[n] = b;
    }
}

__global__ void k_prep_c(const float* __restrict__ cm,
                         const float* __restrict__ ln2w,
                         const float* __restrict__ ln2b) {
    int w = blockIdx.x, tid = threadIdx.x;
    float s = 0.f, ss = 0.f, sw = 0.f, sb = 0.f;
    for (int j = tid; j < DD; j += 256) {
        float v = cm[w * DD + j];
        s += v; ss += v * v; sw += ln2w[j] * v; sb += ln2b[j] * v;
    }
    __shared__ float sA[8], sB[8], sC[8], sD[8];
    __shared__ float rbc;
    int lane = tid & 31, wid = tid >> 5;
#pragma unroll
    for (int o = 16; o; o >>= 1) {
        s  += __shfl_down_sync(0xffffffffu, s,  o);
        ss += __shfl_down_sync(0xffffffffu, ss, o);
        sw += __shfl_down_sync(0xffffffffu, sw, o);
        sb += __shfl_down_sync(0xffffffffu, sb, o);
    }
    if (lane == 0) { sA[wid] = s; sB[wid] = ss; sC[wid] = sw; sD[wid] = sb; }
    __syncthreads();
    if (tid == 0) {
        float a = 0.f, b = 0.f, c = 0.f, d = 0.f;
#pragma unroll
        for (int i = 0; i < 8; i++) { a += sA[i]; b += sB[i]; c += sC[i]; d += sD[i]; }
        g_csum[w] = a; g_cssq[w] = b;
        float r = 1.f / fmaxf(sqrtf(b), 1e-12f);
        rbc = r; g_swc[w] = r * c; g_sbc[w] = r * d;
    }
    __syncthreads();
    float r = rbc;
    for (int j = tid; j < DD; j += 256)
        g_chatT[j * NW + w] = cm[w * DD + j] * r;
}

__global__ void k_s1bb(const float* __restrict__ w1, const float* __restrict__ ln1w,
                       const float* __restrict__ ln1b, const float* __restrict__ b1) {
    int j = blockIdx.x * blockDim.x + threadIdx.x;
    if (j < DD) {
        float a = 0.f, b = 0.f;
        for (int i = 0; i < D2; i++) {
            float wv = w1[i * DD + j];
            a += ln1w[i] * wv; b += ln1b[i] * wv;
        }
        g_s1[j] = a; g_bb[j] = b1[j] + b;
    }
}

__global__ void k_scal(const float* __restrict__ ln2w, const float* __restrict__ ln2b) {
    int tid = threadIdx.x;
    float a = 0.f, b = 0.f, c = 0.f;
    for (int j = tid; j < DD; j += 256) {
        float w = ln2w[j], bb = ln2b[j];
        a += w * w; b += w * bb; c += bb * bb;
    }
    __shared__ float sA[8], sB[8], sC[8];
    int lane = tid & 31, wid = tid >> 5;
#pragma unroll
    for (int o = 16; o; o >>= 1) {
        a += __shfl_down_sync(0xffffffffu, a, o);
        b += __shfl_down_sync(0xffffffffu, b, o);
        c += __shfl_down_sync(0xffffffffu, c, o);
    }
    if (lane == 0) { sA[wid] = a; sB[wid] = b; sC[wid] = c; }
    __syncthreads();
    if (tid == 0) {
        float x = 0.f, y = 0.f, z = 0.f;
#pragma unroll
        for (int i = 0; i < 8; i++) { x += sA[i]; y += sB[i]; z += sC[i]; }
        g_scal[0] = x; g_scal[1] = y; g_scal[2] = z;
    }
}

// w2 transpose + bf16 hi/lo split
__global__ void k_w2split(const float* __restrict__ w2) {
    __shared__ float t[32][33];
    int bx = blockIdx.x * 32, by = blockIdx.y * 32;
    int tx = threadIdx.x, ty = threadIdx.y;
#pragma unroll
    for (int i = 0; i < 4; i++)
        t[ty + i * 8][tx] = w2[(by + ty + i * 8) * DD + bx + tx];
    __syncthreads();
#pragma unroll
    for (int i = 0; i < 4; i++) {
        int j = bx + ty + i * 8, k = by + tx;
        float v = t[tx][ty + i * 8];
        __nv_bfloat16 h = __float2bfloat16(v);
        g_w2thi[j * DD + k] = h;
        g_w2tlo[j * DD + k] = __float2bfloat16(v - __bfloat162float(h));
    }
}

// Q1 / C1 fold GEMM
__global__ void k_gemm_fold(const float* __restrict__ A, int M,
                            const float* __restrict__ w1, int rowoff,
                            const float* __restrict__ lnw,
                            float* __restrict__ Out) {
    __shared__ float As[16][65];
    __shared__ float Bs[16][64];
    int m0 = blockIdx.x * 64, j0 = blockIdx.y * 64;
    int tid = threadIdx.x;
    int tr = tid >> 4, tc = tid & 15;
    int r0 = tr * 4, c0 = tc * 4;
    float acc[4][4] = {};
    for (int kc = 0; kc < DD; kc += 16) {
        __syncthreads();
#pragma unroll
        for (int e = 0; e < 4; e++) {
            int idx = tid + e * 256;
            int m = idx >> 4, kk = idx & 15;
            As[kk][m] = A[(m0 + m) * DD + kc + kk] * lnw[rowoff + kc + kk];
        }
#pragma unroll
        for (int e = 0; e < 4; e++) {
            int idx = tid + e * 256;
            int kk = idx >> 6, j = idx & 63;
            Bs[kk][j] = w1[(rowoff + kc + kk) * DD + j0 + j];
        }
        __syncthreads();
#pragma unroll
        for (int kk = 0; kk < 16; kk++) {
            float a0 = As[kk][r0], a1 = As[kk][r0 + 1], a2 = As[kk][r0 + 2], a3 = As[kk][r0 + 3];
            float b0 = Bs[kk][c0], b1 = Bs[kk][c0 + 1], b2 = Bs[kk][c0 + 2], b3 = Bs[kk][c0 + 3];
            acc[0][0] += a0 * b0; acc[0][1] += a0 * b1; acc[0][2] += a0 * b2; acc[0][3] += a0 * b3;
            acc[1][0] += a1 * b0; acc[1][1] += a1 * b1; acc[1][2] += a1 * b2; acc[1][3] += a1 * b3;
            acc[2][0] += a2 * b0; acc[2][1] += a2 * b1; acc[2][2] += a2 * b2; acc[2][3] += a2 * b3;
            acc[3][0] += a3 * b0; acc[3][1] += a3 * b1; acc[3][2] += a3 * b2; acc[3][3] += a3 * b3;
        }
    }
#pragma unroll
    for (int i = 0; i < 4; i++)
#pragma unroll
        for (int j = 0; j < 4; j++)
            Out[(m0 + r0 + i) * DD + j0 + c0 + j] = acc[i][j];
}

// ================= main HMMA kernel =================
// smem layout (bytes)
#define OFF_A    0          // 2 x (hi 16KB | lo 16KB) = 65536
#define OFF_B    65536      // 2 x (hi 16KB | lo 16KB) = 65536
#define OFF_C1   131072     // 2 x 64*68*4 = 34816
#define OFF_CH   165888     // 128*68*4 = 34816
#define OFF_META 200704     // 4864 floats = 19456
#define SMEM_TC  220160
// meta float offsets
#define M_Q10  0
#define M_Q11  512
#define M_S1   1024
#define M_BB   1536
#define M_TS   2048   // [2][128]
#define M_LW   2304
#define M_LB   2432
#define M_MU   2560
#define M_IV   2688
#define M_RED  2816   // [2][128][8]

__device__ __forceinline__ void cp_chunk(uint32_t sb, int p, int j0, int kc, int tid) {
    uint32_t bh = sb + OFF_B + p * 32768;
    uint32_t bl = bh + 16384;
    const char* gh = (const char*)g_w2thi + (size_t)j0 * 1024 + (size_t)kc * 128;
    const char* gl = (const char*)g_w2tlo + (size_t)j0 * 1024 + (size_t)kc * 128;
#pragma unroll
    for (int i = 0; i < 4; i++) {
        int u = tid + i * 256;
        int row = u >> 3, c16 = u & 7;
        uint32_t o = (uint32_t)(row * 128 + c16 * 16);
        uint32_t so = SWZ(o);
        cp16(bh + so, gh + (size_t)row * 1024 + c16 * 16);
        cp16(bl + so, gl + (size_t)row * 1024 + c16 * 16);
    }
    uint32_t cb = sb + OFF_C1 + p * 17408;
    const char* gc = (const char*)g_C1 + (size_t)kc * 256;
#pragma unroll
    for (int i = 0; i < 4; i++) {
        int u = tid + i * 256;
        int w = u >> 4, c16 = u & 15;
        cp16(cb + (uint32_t)(w * 272 + c16 * 16), gc + (size_t)w * 2048 + c16 * 16);
    }
    asm volatile("cp.async.commit_group;" ::: "memory");
}

__device__ __forceinline__ void buildA(char* smem, int p, int kc, int tid,
                                       const float* meta) {
    int r = tid >> 1, w = r & 63, rn = r >> 6;
    int kh = (tid & 1) * 32;
    float mu = meta[M_MU + r], iv = meta[M_IV + r];
    const float* Q1p = meta + (rn ? M_Q11 : M_Q10);
    const float* s1s = meta + M_S1;
    const float* bbs = meta + M_BB;
    const float* c1p = (const float*)(smem + OFF_C1 + p * 17408) + w * 68 + kh;
    char* ah = smem + OFF_A + p * 32768;
    char* al = ah + 16384;
#pragma unroll
    for (int kk = 0; kk < 32; kk += 2) {
        int j = kc * 64 + kh + kk;
        float c1a = c1p[kk], c1b = c1p[kk + 1];
        float ha = iv * (Q1p[j] + c1a - mu * s1s[j]) + bbs[j];
        float hb = iv * (Q1p[j + 1] + c1b - mu * s1s[j + 1]) + bbs[j + 1];
        float ga = 0.5f * ha * (1.f + erff(ha * 0.70710678118654752f));
        float gb = 0.5f * hb * (1.f + erff(hb * 0.70710678118654752f));
        __nv_bfloat16 ea = __float2bfloat16(ga), eb = __float2bfloat16(gb);
        __nv_bfloat162 hp; hp.x = ea; hp.y = eb;
        __nv_bfloat162 lp;
        lp.x = __float2bfloat16(ga - __bfloat162float(ea));
        lp.y = __float2bfloat16(gb - __bfloat162float(eb));
        uint32_t o = (uint32_t)(r * 128 + (kh + kk) * 2);
        uint32_t so = SWZ(o);
        *(__nv_bfloat162*)(ah + so) = hp;
        *(__nv_bfloat162*)(al + so) = lp;
    }
}

__global__ void __launch_bounds__(256, 1)
k_tc2(const float* __restrict__ q, const float* __restrict__ b2,
      const float* __restrict__ ln2w, const float* __restrict__ ln2b) {
    extern __shared__ char smem[];
    const uint32_t sb = smem_u32(smem);
    const int tid = threadIdx.x, lane = tid & 31, wid = tid >> 5;
    const int pair = blockIdx.x >> 2, ch = blockIdx.x & 3;
    const int n0 = pair * 2, j0 = ch * 128;
    float* meta = (float*)(smem + OFF_META);
    float* chs = (float*)(smem + OFF_CH);

    // ---- prologue loads ----
    for (int j = tid; j < DD; j += 256) {
        meta[M_Q10 + j] = g_Q1[n0 * DD + j];
        meta[M_Q11 + j] = g_Q1[(n0 + 1) * DD + j];
        meta[M_S1 + j] = g_s1[j];
        meta[M_BB + j] = g_bb[j];
    }
    if (tid < 128) {
        int lc = tid;
        float b2j = b2[j0 + lc];
        meta[M_TS + lc]       = b2j + q[n0 * DD + j0 + lc];
        meta[M_TS + 128 + lc] = b2j + q[(n0 + 1) * DD + j0 + lc];
        meta[M_LW + lc] = ln2w[j0 + lc];
        meta[M_LB + lc] = ln2b[j0 + lc];
        int rn = lc >> 6, w = lc & 63;
        float sx  = g_qsum[n0 + rn] + g_csum[w];
        float sxx = g_qssq[n0 + rn] + g_cssq[w];
        float m = sx * (1.f / 1024.f);
        float var = sxx * (1.f / 1024.f) - m * m;
        meta[M_MU + lc] = m;
        meta[M_IV + lc] = rsqrtf(var + LN_EPS);
    }
#pragma unroll
    for (int i = 0; i < 32; i++) {
        int u = tid + i * 256;           // 8192 = 128*64
        int lc = u >> 6, w = u & 63;
        chs[lc * 68 + w] = g_chatT[(j0 + lc) * NW + w];
    }
    cp_chunk(sb, 0, j0, 0, tid);
    asm volatile("cp.async.wait_group 0;" ::: "memory");
    __syncthreads();
    buildA(smem, 0, 0, tid, meta);
    __syncthreads();

    // ---- mainloop ----
    const int wm = wid & 3, wn = wid >> 2;
    const int arow = ((lane >> 3) & 1) * 8 + (lane & 7);
    const int acol = lane >> 4;
    const int brow = (lane >> 4) * 8 + (lane & 7);
    const int bcol = (lane >> 3) & 1;

    float d[16][4];
#pragma unroll
    for (int i = 0; i < 16; i++)
#pragma unroll
        for (int j = 0; j < 4; j++) d[i][j] = 0.f;

    int bufc = 0;
    for (int kc = 0; kc < 8; kc++) {
        if (kc < 7) cp_chunk(sb, bufc ^ 1, j0, kc + 1, tid);
        uint32_t Ah = sb + OFF_A + bufc * 32768, Al = Ah + 16384;
        uint32_t Bh = sb + OFF_B + bufc * 32768, Bl = Bh + 16384;
#pragma unroll
        for (int s = 0; s < 4; s++) {
            uint32_t ahi[2][4], alo[2][4], bhi[4][4], blo[4][4];
#pragma unroll
            for (int tm = 0; tm < 2; tm++) {
                uint32_t o = (uint32_t)((32 * wm + 16 * tm + arow) * 128 + (2 * s + acol) * 16);
                uint32_t so = SWZ(o);
                ldsm4(ahi[tm], Ah + so);
                ldsm4(alo[tm], Al + so);
            }
#pragma unroll
            for (int u = 0; u < 4; u++) {
                uint32_t o = (uint32_t)((64 * wn + 16 * u + brow) * 128 + (2 * s + bcol) * 16);
                uint32_t so = SWZ(o);
                ldsm4(bhi[u], Bh + so);
                ldsm4(blo[u], Bl + so);
            }
#pragma unroll
            for (int tm = 0; tm < 2; tm++)
#pragma unroll
                for (int u = 0; u < 4; u++) {
                    mma16816(d[tm * 8 + 2 * u],     ahi[tm], &bhi[u][0]);
                    mma16816(d[tm * 8 + 2 * u],     alo[tm], &bhi[u][0]);
                    mma16816(d[tm * 8 + 2 * u],     ahi[tm], &blo[u][0]);
                    mma16816(d[tm * 8 + 2 * u + 1], ahi[tm], &bhi[u][2]);
                    mma16816(d[tm * 8 + 2 * u + 1], alo[tm], &bhi[u][2]);
                    mma16816(d[tm * 8 + 2 * u + 1], ahi[tm], &blo[u][2]);
                }
        }
        if (kc < 7) {
            asm volatile("cp.async.wait_group 0;" ::: "memory");
            __syncthreads();
            buildA(smem, bufc ^ 1, kc + 1, tid, meta);
        }
        __syncthreads();
        bufc ^= 1;
    }

    // ---- epilogue: 6 moments per row ----
    const int qr = lane >> 2, qc = lane & 3;
    float* sred = meta + M_RED;
#pragma unroll
    for (int tm = 0; tm < 2; tm++)
#pragma unroll
        for (int h = 0; h < 2; h++) {
            int row = 32 * wm + 16 * tm + 8 * h + qr;
            int w = row & 63, rn = row >> 6;
            float p0 = 0.f, p1 = 0.f, pA = 0.f, pB = 0.f, pC = 0.f, pE = 0.f;
#pragma unroll
            for (int nt = 0; nt < 8; nt++)
#pragma unroll
                for (int c = 0; c < 2; c++) {
                    int lc = 64 * wn + 8 * nt + qc * 2 + c;
                    float v = d[tm * 8 + nt][h * 2 + c] + meta[M_TS + rn * 128 + lc];
                    float wj = meta[M_LW + lc], bj = meta[M_LB + lc];
                    float chv = chs[lc * 68 + w];
                    float vw = v * wj;
                    p0 += v;       p1 += v * v;
                    pA += vw * chv; pB += vw * vw;
                    pC += vw * wj;  pE += vw * bj;
                }
#pragma unroll
            for (int o = 1; o <= 2; o <<= 1) {
                p0 += __shfl_down_sync(0xffffffffu, p0, o, 4);
                p1 += __shfl_down_sync(0xffffffffu, p1, o, 4);
                pA += __shfl_down_sync(0xffffffffu, pA, o, 4);
                pB += __shfl_down_sync(0xffffffffu, pB, o, 4);
                pC += __shfl_down_sync(0xffffffffu, pC, o, 4);
                pE += __shfl_down_sync(0xffffffffu, pE, o, 4);
            }
            if (qc == 0) {
                float* rp = sred + (wn * 128 + row) * 8;
                rp[0] = p0; rp[1] = p1; rp[2] = pA;
                rp[3] = pB; rp[4] = pC; rp[5] = pE;
            }
        }
    __syncthreads();
    if (tid < 128) {
        int row = tid;
        int gidx = pair * 128 + row;
#pragma unroll
        for (int m = 0; m < 6; m++) {
            float v = sred[row * 8 + m] + sred[(128 + row) * 8 + m];
            g_part[(ch * 6 + m) * (NQ * NW) + gidx] = v;
        }
    }
}

// ================= final combine =================
__global__ void k_fin(float* __restrict__ out) {
    int idx = blockIdx.x * 256 + threadIdx.x;
    float m[6];
#pragma unroll
    for (int mi = 0; mi < 6; mi++) {
        float v = 0.f;
#pragma unroll
        for (int c = 0; c < 4; c++) v += g_part[(c * 6 + mi) * (NQ * NW) + idx];
        m[mi] = v;
    }
    int w = idx & 63;
    float mu2 = m[0] * (1.f / DD);
    float var = m[1] * (1.f / DD) - mu2 * mu2;
    float k = rsqrtf(var + LN_EPS);
    float sww = g_scal[0], swb = g_scal[1], sbb = g_scal[2];
    float doty = k * (m[2] - mu2 * g_swc[w]) + g_sbc[w];
    float ny2 = k * k * (m[3] - 2.f * mu2 * m[4] + mu2 * mu2 * sww)
              + 2.f * k * (m[5] - mu2 * swb) + sbb;
    float ny = sqrtf(fmaxf(ny2, 0.f));
    out[idx] = TEMP_SC * doty / fmaxf(ny, 1e-12f);
}

// ================= launch =================
extern "C" void kernel_launch(void* const* d_in, const int* in_sizes, int n_in,
                              void* d_out, int out_size) {
    const float* q    = (const float*)d_in[0];
    const float* cm   = (const float*)d_in[1];
    const float* ln1w = (const float*)d_in[2];
    const float* ln1b = (const float*)d_in[3];
    const float* w1   = (const float*)d_in[4];
    const float* b1   = (const float*)d_in[5];
    const float* w2   = (const float*)d_in[6];
    const float* b2   = (const float*)d_in[7];
    const float* ln2w = (const float*)d_in[8];
    const float* ln2b = (const float*)d_in[9];
    float* out = (float*)d_out;

    float *pQ1, *pC1;
    cudaGetSymbolAddress((void**)&pQ1, g_Q1);
    cudaGetSymbolAddress((void**)&pC1, g_C1);

    cudaFuncSetAttribute(k_tc2, cudaFuncAttributeMaxDynamicSharedMemorySize, SMEM_TC);

    k_rowstats_q<<<NQ, 256>>>(q);
    k_prep_c<<<NW, 256>>>(cm, ln2w, ln2b);
    k_s1bb<<<2, 256>>>(w1, ln1w, ln1b, b1);
    k_scal<<<1, 256>>>(ln2w, ln2b);
    k_w2split<<<dim3(16, 16), dim3(32, 8)>>>(w2);
    k_gemm_fold<<<dim3(NQ / 64, DD / 64), 256>>>(q,  NQ, w1, 0,   ln1w, pQ1);
    k_gemm_fold<<<dim3(NW / 64, DD / 64), 256>>>(cm, NW, w1, 512, ln1w, pC1);
    k_tc2<<<NQ * 2, 256, SMEM_TC>>>(q, b2, ln2w, ln2b);
    k_fin<<<NQ * NW / 256, 256>>>(out);
}

// round 6
// speedup vs baseline: 2.5947x; 1.1872x over previous
#include <cuda_runtime.h>
#include <cuda_fp16.h>
#include <math.h>
#include <stdint.h>
#include <cstdint>

#define NQ 2048
#define NW 64
#define DD 512
#define D2 1024
#define TEMP_SC 16.0f
#define LN_EPS 1e-5f

// ---------------- scratch ----------------
__device__ float g_Q1[NQ * DD];
__device__ float g_C1[NW * DD];
__device__ float g_QW[NQ * DD];        // Q1 @ w2
__device__ float g_CW[NW * DD];        // C1 @ w2
__device__ float g_s1[DD];
__device__ float g_bb[DD];
__device__ float g_s1w[DD];            // s1 @ w2
__device__ float g_bbw[DD];            // bb @ w2
__device__ float g_qsum[NQ];
__device__ float g_qssq[NQ];
__device__ float g_csum[NW];
__device__ float g_cssq[NW];
__device__ float g_chatT[DD * NW];     // [j][w]
__device__ float g_swc[NW];
__device__ float g_sbc[NW];
__device__ float g_scal[3];
__device__ __align__(128) __half g_w2th[DD * DD];  // w2^T [j][k] fp16
__device__ float g_part[24 * NQ * NW]; // [ch*6+m][n*64+w]

#define SWZ(o) ((o) ^ (((o) >> 3) & 0x70))

// ================= helpers =================
__device__ __forceinline__ uint32_t smem_u32(const void* p) {
    uint32_t a;
    asm("{ .reg .u64 t; cvta.to.shared.u64 t, %1; cvt.u32.u64 %0, t; }" : "=r"(a) : "l"(p));
    return a;
}
__device__ __forceinline__ void cp16(uint32_t s, const void* g) {
    asm volatile("cp.async.cg.shared.global [%0], [%1], 16;" :: "r"(s), "l"(g));
}
__device__ __forceinline__ void ldsm4(uint32_t* r, uint32_t a) {
    asm volatile("ldmatrix.sync.aligned.m8n8.x4.shared.b16 {%0,%1,%2,%3}, [%4];"
                 : "=r"(r[0]), "=r"(r[1]), "=r"(r[2]), "=r"(r[3]) : "r"(a));
}
__device__ __forceinline__ void mma16816h(float* d, const uint32_t* a, const uint32_t* b) {
    asm volatile("mma.sync.aligned.m16n8k16.row.col.f32.f16.f16.f32 "
                 "{%0,%1,%2,%3}, {%4,%5,%6,%7}, {%8,%9}, {%0,%1,%2,%3};"
                 : "+f"(d[0]), "+f"(d[1]), "+f"(d[2]), "+f"(d[3])
                 : "r"(a[0]), "r"(a[1]), "r"(a[2]), "r"(a[3]), "r"(b[0]), "r"(b[1]));
}

// ================= phase A =================
__global__ void k_rowstats_q(const float* __restrict__ q) {
    int n = blockIdx.x, tid = threadIdx.x;
    float s = 0.f, ss = 0.f;
    for (int j = tid; j < DD; j += 256) { float v = q[n * DD + j]; s += v; ss += v * v; }
    __shared__ float sA[8], sB[8];
    int lane = tid & 31, wid = tid >> 5;
#pragma unroll
    for (int o = 16; o; o >>= 1) {
        s  += __shfl_down_sync(0xffffffffu, s, o);
        ss += __shfl_down_sync(0xffffffffu, ss, o);
    }
    if (lane == 0) { sA[wid] = s; sB[wid] = ss; }
    __syncthreads();
    if (tid == 0) {
        float a = 0.f, b = 0.f;
#pragma unroll
        for (int i = 0; i < 8; i++) { a += sA[i]; b += sB[i]; }
        g_qsum[n] = a; g_qssq[n] = b;
    }
}

__global__ void k_prep_c(const float* __restrict__ cm,
                         const float* __restrict__ ln2w,
                         const float* __restrict__ ln2b) {
    int w = blockIdx.x, tid = threadIdx.x;
    float s = 0.f, ss = 0.f, sw = 0.f, sb = 0.f;
    for (int j = tid; j < DD; j += 256) {
        float v = cm[w * DD + j];
        s += v; ss += v * v; sw += ln2w[j] * v; sb += ln2b[j] * v;
    }
    __shared__ float sA[8], sB[8], sC[8], sD[8];
    __shared__ float rbc;
    int lane = tid & 31, wid = tid >> 5;
#pragma unroll
    for (int o = 16; o; o >>= 1) {
        s  += __shfl_down_sync(0xffffffffu, s,  o);
        ss += __shfl_down_sync(0xffffffffu, ss, o);
        sw += __shfl_down_sync(0xffffffffu, sw, o);
        sb += __shfl_down_sync(0xffffffffu, sb, o);
    }
    if (lane == 0) { sA[wid] = s; sB[wid] = ss; sC[wid] = sw; sD[wid] = sb; }
    __syncthreads();
    if (tid == 0) {
        float a = 0.f, b = 0.f, c = 0.f, d = 0.f;
#pragma unroll
        for (int i = 0; i < 8; i++) { a += sA[i]; b += sB[i]; c += sC[i]; d += sD[i]; }
        g_csum[w] = a; g_cssq[w] = b;
        float r = 1.f / fmaxf(sqrtf(b), 1e-12f);
        rbc = r; g_swc[w] = r * c; g_sbc[w] = r * d;
    }
    __syncthreads();
    float r = rbc;
    for (int j = tid; j < DD; j += 256)
        g_chatT[j * NW + w] = cm[w * DD + j] * r;
}

__global__ void k_s1bb(const float* __restrict__ w1, const float* __restrict__ ln1w,
                       const float* __restrict__ ln1b, const float* __restrict__ b1) {
    int j = blockIdx.x * blockDim.x + threadIdx.x;
    if (j < DD) {
        float a = 0.f, b = 0.f;
        for (int i = 0; i < D2; i++) {
            float wv = w1[i * DD + j];
            a += ln1w[i] * wv; b += ln1b[i] * wv;
        }
        g_s1[j] = a; g_bb[j] = b1[j] + b;
    }
}

__global__ void k_vw2(const float* __restrict__ w2) {
    int j = blockIdx.x * blockDim.x + threadIdx.x;
    if (j < DD) {
        float a = 0.f, b = 0.f;
        for (int k = 0; k < DD; k++) {
            float wv = w2[k * DD + j];
            a += g_s1[k] * wv; b += g_bb[k] * wv;
        }
        g_s1w[j] = a; g_bbw[j] = b;
    }
}

__global__ void k_scal(const float* __restrict__ ln2w, const float* __restrict__ ln2b) {
    int tid = threadIdx.x;
    float a = 0.f, b = 0.f, c = 0.f;
    for (int j = tid; j < DD; j += 256) {
        float w = ln2w[j], bb = ln2b[j];
        a += w * w; b += w * bb; c += bb * bb;
    }
    __shared__ float sA[8], sB[8], sC[8];
    int lane = tid & 31, wid = tid >> 5;
#pragma unroll
    for (int o = 16; o; o >>= 1) {
        a += __shfl_down_sync(0xffffffffu, a, o);
        b += __shfl_down_sync(0xffffffffu, b, o);
        c += __shfl_down_sync(0xffffffffu, c, o);
    }
    if (lane == 0) { sA[wid] = a; sB[wid] = b; sC[wid] = c; }
    __syncthreads();
    if (tid == 0) {
        float x = 0.f, y = 0.f, z = 0.f;
#pragma unroll
        for (int i = 0; i < 8; i++) { x += sA[i]; y += sB[i]; z += sC[i]; }
        g_scal[0] = x; g_scal[1] = y; g_scal[2] = z;
    }
}

// w2 transpose to fp16 [j][k]
__global__ void k_w2h(const float* __restrict__ w2) {
    __shared__ float t[32][33];
    int bx = blockIdx.x * 32, by = blockIdx.y * 32;
    int tx = threadIdx.x, ty = threadIdx.y;
#pragma unroll
    for (int i = 0; i < 4; i++)
        t[ty + i * 8][tx] = w2[(by + ty + i * 8) * DD + bx + tx];
    __syncthreads();
#pragma unroll
    for (int i = 0; i < 4; i++) {
        int j = bx + ty + i * 8, k = by + tx;
        g_w2th[j * DD + k] = __float2half(t[tx][ty + i * 8]);
    }
}

// fold GEMM: Out = (A .* lnw_rows) @ w1[rowoff:rowoff+512]
__global__ void k_gemm_fold(const float* __restrict__ A, int M,
                            const float* __restrict__ w1, int rowoff,
                            const float* __restrict__ lnw,
                            float* __restrict__ Out) {
    __shared__ float As[16][65];
    __shared__ float Bs[16][64];
    int m0 = blockIdx.x * 64, j0 = blockIdx.y * 64;
    int tid = threadIdx.x;
    int tr = tid >> 4, tc = tid & 15;
    int r0 = tr * 4, c0 = tc * 4;
    float acc[4][4] = {};
    for (int kc = 0; kc < DD; kc += 16) {
        __syncthreads();
#pragma unroll
        for (int e = 0; e < 4; e++) {
            int idx = tid + e * 256;
            int m = idx >> 4, kk = idx & 15;
            As[kk][m] = A[(m0 + m) * DD + kc + kk] * lnw[rowoff + kc + kk];
        }
#pragma unroll
        for (int e = 0; e < 4; e++) {
            int idx = tid + e * 256;
            int kk = idx >> 6, j = idx & 63;
            Bs[kk][j] = w1[(rowoff + kc + kk) * DD + j0 + j];
        }
        __syncthreads();
#pragma unroll
        for (int kk = 0; kk < 16; kk++) {
            float a0 = As[kk][r0], a1 = As[kk][r0 + 1], a2 = As[kk][r0 + 2], a3 = As[kk][r0 + 3];
            float b0 = Bs[kk][c0], b1 = Bs[kk][c0 + 1], b2 = Bs[kk][c0 + 2], b3 = Bs[kk][c0 + 3];
            acc[0][0] += a0 * b0; acc[0][1] += a0 * b1; acc[0][2] += a0 * b2; acc[0][3] += a0 * b3;
            acc[1][0] += a1 * b0; acc[1][1] += a1 * b1; acc[1][2] += a1 * b2; acc[1][3] += a1 * b3;
            acc[2][0] += a2 * b0; acc[2][1] += a2 * b1; acc[2][2] += a2 * b2; acc[2][3] += a2 * b3;
            acc[3][0] += a3 * b0; acc[3][1] += a3 * b1; acc[3][2] += a3 * b2; acc[3][3] += a3 * b3;
        }
    }
#pragma unroll
    for (int i = 0; i < 4; i++)
#pragma unroll
        for (int j = 0; j < 4; j++)
            Out[(m0 + r0 + i) * DD + j0 + c0 + j] = acc[i][j];
}

// plain GEMM: Out = A @ B   (B row-major [k][j], 512x512)
__global__ void k_gemm_plain(const float* __restrict__ A,
                             const float* __restrict__ B,
                             float* __restrict__ Out) {
    __shared__ float As[16][65];
    __shared__ float Bs[16][64];
    int m0 = blockIdx.x * 64, j0 = blockIdx.y * 64;
    int tid = threadIdx.x;
    int tr = tid >> 4, tc = tid & 15;
    int r0 = tr * 4, c0 = tc * 4;
    float acc[4][4] = {};
    for (int kc = 0; kc < DD; kc += 16) {
        __syncthreads();
#pragma unroll
        for (int e = 0; e < 4; e++) {
            int idx = tid + e * 256;
            int m = idx >> 4, kk = idx & 15;
            As[kk][m] = A[(m0 + m) * DD + kc + kk];
        }
#pragma unroll
        for (int e = 0; e < 4; e++) {
            int idx = tid + e * 256;
            int kk = idx >> 6, j = idx & 63;
            Bs[kk][j] = B[(kc + kk) * DD + j0 + j];
        }
        __syncthreads();
#pragma unroll
        for (int kk = 0; kk < 16; kk++) {
            float a0 = As[kk][r0], a1 = As[kk][r0 + 1], a2 = As[kk][r0 + 2], a3 = As[kk][r0 + 3];
            float b0 = Bs[kk][c0], b1 = Bs[kk][c0 + 1], b2 = Bs[kk][c0 + 2], b3 = Bs[kk][c0 + 3];
            acc[0][0] += a0 * b0; acc[0][1] += a0 * b1; acc[0][2] += a0 * b2; acc[0][3] += a0 * b3;
            acc[1][0] += a1 * b0; acc[1][1] += a1 * b1; acc[1][2] += a1 * b2; acc[1][3] += a1 * b3;
            acc[2][0] += a2 * b0; acc[2][1] += a2 * b1; acc[2][2] += a2 * b2; acc[2][3] += a2 * b3;
            acc[3][0] += a3 * b0; acc[3][1] += a3 * b1; acc[3][2] += a3 * b2; acc[3][3] += a3 * b3;
        }
    }
#pragma unroll
    for (int i = 0; i < 4; i++)
#pragma unroll
        for (int j = 0; j < 4; j++)
            Out[(m0 + r0 + i) * DD + j0 + c0 + j] = acc[i][j];
}

// ================= main HMMA kernel (fp16 residual, 1 term) =================
// smem layout (bytes)
#define OFF_A    0          // 2 x 16384
#define OFF_B    32768      // 2 x 16384
#define OFF_C1   65536      // 2 x 17408
#define OFF_CH   100352     // 128*68*4 = 34816
#define OFF_CW   135168     // 64*132*4 = 33792
#define OFF_META 168960     // 5376 floats = 21504
#define SMEM_TC  190464
// meta float offsets
#define M_Q10  0
#define M_Q11  512
#define M_S1   1024
#define M_BB   1536
#define M_TS   2048   // [2][128]
#define M_LW   2304
#define M_LB   2432
#define M_MU   2560
#define M_IV   2688
#define M_S1W  2816
#define M_BBW  2944
#define M_QW   3072   // [2][128]
#define M_RED  3328   // [2][128][8]

__device__ __forceinline__ void cp_chunk(uint32_t sb, int p, int j0, int kc, int tid) {
    uint32_t bh = sb + OFF_B + p * 16384;
    const char* gh = (const char*)g_w2th + (size_t)j0 * 1024 + (size_t)kc * 128;
#pragma unroll
    for (int i = 0; i < 4; i++) {
        int u = tid + i * 256;
        int row = u >> 3, c16 = u & 7;
        uint32_t o = (uint32_t)(row * 128 + c16 * 16);
        cp16(bh + SWZ(o), gh + (size_t)row * 1024 + c16 * 16);
    }
    uint32_t cb = sb + OFF_C1 + p * 17408;
    const char* gc = (const char*)g_C1 + (size_t)kc * 256;
#pragma unroll
    for (int i = 0; i < 4; i++) {
        int u = tid + i * 256;
        int w = u >> 4, c16 = u & 15;
        cp16(cb + (uint32_t)(w * 272 + c16 * 16), gc + (size_t)w * 2048 + c16 * 16);
    }
    asm volatile("cp.async.commit_group;" ::: "memory");
}

// build residual tile: gtil = gelu(h) - 0.5h = 0.5*h*erf(h/sqrt2), fp16
__device__ __forceinline__ void buildA(char* smem, int p, int kc, int tid,
                                       const float* meta) {
    int r = tid >> 1, w = r & 63, rn = r >> 6;
    int kh = (tid & 1) * 32;
    float mu = meta[M_MU + r], iv = meta[M_IV + r];
    const float* Q1p = meta + (rn ? M_Q11 : M_Q10);
    const float* s1s = meta + M_S1;
    const float* bbs = meta + M_BB;
    const float* c1p = (const float*)(smem + OFF_C1 + p * 17408) + w * 68 + kh;
    char* ah = smem + OFF_A + p * 16384;
#pragma unroll
    for (int kk = 0; kk < 32; kk += 2) {
        int j = kc * 64 + kh + kk;
        float ha = iv * (Q1p[j] + c1p[kk] - mu * s1s[j]) + bbs[j];
        float hb = iv * (Q1p[j + 1] + c1p[kk + 1] - mu * s1s[j + 1]) + bbs[j + 1];
        float ga = 0.5f * ha * erff(ha * 0.70710678118654752f);
        float gb = 0.5f * hb * erff(hb * 0.70710678118654752f);
        __half2 hp = __floats2half2_rn(ga, gb);
        uint32_t o = (uint32_t)(r * 128 + (kh + kk) * 2);
        *(__half2*)(ah + SWZ(o)) = hp;
    }
}

__global__ void __launch_bounds__(256, 1)
k_tc3(const float* __restrict__ q, const float* __restrict__ b2,
      const float* __restrict__ ln2w, const float* __restrict__ ln2b) {
    extern __shared__ char smem[];
    const uint32_t sb = smem_u32(smem);
    const int tid = threadIdx.x, lane = tid & 31, wid = tid >> 5;
    const int pair = blockIdx.x >> 2, ch = blockIdx.x & 3;
    const int n0 = pair * 2, j0 = ch * 128;
    float* meta = (float*)(smem + OFF_META);
    float* chs = (float*)(smem + OFF_CH);
    float* cws = (float*)(smem + OFF_CW);

    // ---- prologue loads ----
    for (int j = tid; j < DD; j += 256) {
        meta[M_Q10 + j] = g_Q1[n0 * DD + j];
        meta[M_Q11 + j] = g_Q1[(n0 + 1) * DD + j];
        meta[M_S1 + j] = g_s1[j];
        meta[M_BB + j] = g_bb[j];
    }
    if (tid < 128) {
        int lc = tid;
        float b2j = b2[j0 + lc];
        meta[M_TS + lc]       = b2j + q[n0 * DD + j0 + lc];
        meta[M_TS + 128 + lc] = b2j + q[(n0 + 1) * DD + j0 + lc];
        meta[M_LW + lc] = ln2w[j0 + lc];
        meta[M_LB + lc] = ln2b[j0 + lc];
        meta[M_S1W + lc] = g_s1w[j0 + lc];
        meta[M_BBW + lc] = g_bbw[j0 + lc];
        meta[M_QW + lc]       = g_QW[n0 * DD + j0 + lc];
        meta[M_QW + 128 + lc] = g_QW[(n0 + 1) * DD + j0 + lc];
        int rn = lc >> 6, w = lc & 63;
        float sx  = g_qsum[n0 + rn] + g_csum[w];
        float sxx = g_qssq[n0 + rn] + g_cssq[w];
        float m = sx * (1.f / 1024.f);
        float var = sxx * (1.f / 1024.f) - m * m;
        meta[M_MU + lc] = m;
        meta[M_IV + lc] = rsqrtf(var + LN_EPS);
    }
#pragma unroll
    for (int i = 0; i < 32; i++) {
        int u = tid + i * 256;           // chat: 128*64
        int lc = u >> 6, w = u & 63;
        chs[lc * 68 + w] = g_chatT[(j0 + lc) * NW + w];
    }
#pragma unroll
    for (int i = 0; i < 32; i++) {
        int u = tid + i * 256;           // CW: 64*128, coalesced rows
        int w = u >> 7, lc = u & 127;
        cws[w * 132 + lc] = g_CW[w * DD + j0 + lc];
    }
    cp_chunk(sb, 0, j0, 0, tid);
    asm volatile("cp.async.wait_group 0;" ::: "memory");
    __syncthreads();
    buildA(smem, 0, 0, tid, meta);
    __syncthreads();

    // ---- mainloop ----
    const int wm = wid & 3, wn = wid >> 2;
    const int arow = ((lane >> 3) & 1) * 8 + (lane & 7);
    const int acol = lane >> 4;
    const int brow = (lane >> 4) * 8 + (lane & 7);
    const int bcol = (lane >> 3) & 1;

    float d[16][4];
#pragma unroll
    for (int i = 0; i < 16; i++)
#pragma unroll
        for (int j = 0; j < 4; j++) d[i][j] = 0.f;

    int bufc = 0;
    for (int kc = 0; kc < 8; kc++) {
        if (kc < 7) cp_chunk(sb, bufc ^ 1, j0, kc + 1, tid);
        uint32_t Ah = sb + OFF_A + bufc * 16384;
        uint32_t Bh = sb + OFF_B + bufc * 16384;
#pragma unroll
        for (int s = 0; s < 4; s++) {
            uint32_t ahi[2][4], bhi[4][4];
#pragma unroll
            for (int tm = 0; tm < 2; tm++) {
                uint32_t o = (uint32_t)((32 * wm + 16 * tm + arow) * 128 + (2 * s + acol) * 16);
                ldsm4(ahi[tm], Ah + SWZ(o));
            }
#pragma unroll
            for (int u = 0; u < 4; u++) {
                uint32_t o = (uint32_t)((64 * wn + 16 * u + brow) * 128 + (2 * s + bcol) * 16);
                ldsm4(bhi[u], Bh + SWZ(o));
            }
#pragma unroll
            for (int tm = 0; tm < 2; tm++)
#pragma unroll
                for (int u = 0; u < 4; u++) {
                    mma16816h(d[tm * 8 + 2 * u],     ahi[tm], &bhi[u][0]);
                    mma16816h(d[tm * 8 + 2 * u + 1], ahi[tm], &bhi[u][2]);
                }
        }
        if (kc < 7) {
            asm volatile("cp.async.wait_group 0;" ::: "memory");
            __syncthreads();
            buildA(smem, bufc ^ 1, kc + 1, tid, meta);
        }
        __syncthreads();
        bufc ^= 1;
    }

    // ---- epilogue: v = R + 0.5*H + ts; 6 moments per row ----
    const int qr = lane >> 2, qc = lane & 3;
    float* sred = meta + M_RED;
#pragma unroll
    for (int tm = 0; tm < 2; tm++)
#pragma unroll
        for (int h = 0; h < 2; h++) {
            int row = 32 * wm + 16 * tm + 8 * h + qr;
            int w = row & 63, rn = row >> 6;
            float mur = meta[M_MU + row], ivr = meta[M_IV + row];
            float p0 = 0.f, p1 = 0.f, pA = 0.f, pB = 0.f, pC = 0.f, pE = 0.f;
#pragma unroll
            for (int nt = 0; nt < 8; nt++)
#pragma unroll
                for (int c = 0; c < 2; c++) {
                    int lc = 64 * wn + 8 * nt + qc * 2 + c;
                    float Hl = ivr * (meta[M_QW + rn * 128 + lc] + cws[w * 132 + lc]
                                      - mur * meta[M_S1W + lc]) + meta[M_BBW + lc];
                    float v = d[tm * 8 + nt][h * 2 + c] + 0.5f * Hl
                            + meta[M_TS + rn * 128 + lc];
                    float wj = meta[M_LW + lc], bj = meta[M_LB + lc];
                    float chv = chs[lc * 68 + w];
                    float vw = v * wj;
                    p0 += v;       p1 += v * v;
                    pA += vw * chv; pB += vw * vw;
                    pC += vw * wj;  pE += vw * bj;
                }
#pragma unroll
            for (int o = 1; o <= 2; o <<= 1) {
                p0 += __shfl_down_sync(0xffffffffu, p0, o, 4);
                p1 += __shfl_down_sync(0xffffffffu, p1, o, 4);
                pA += __shfl_down_sync(0xffffffffu, pA, o, 4);
                pB += __shfl_down_sync(0xffffffffu, pB, o, 4);
                pC += __shfl_down_sync(0xffffffffu, pC, o, 4);
                pE += __shfl_down_sync(0xffffffffu, pE, o, 4);
            }
            if (qc == 0) {
                float* rp = sred + (wn * 128 + row) * 8;
                rp[0] = p0; rp[1] = p1; rp[2] = pA;
                rp[3] = pB; rp[4] = pC; rp[5] = pE;
            }
        }
    __syncthreads();
    if (tid < 128) {
        int row = tid;
        int gidx = pair * 128 + row;
#pragma unroll
        for (int m = 0; m < 6; m++) {
            float v = sred[row * 8 + m] + sred[(128 + row) * 8 + m];
            g_part[(ch * 6 + m) * (NQ * NW) + gidx] = v;
        }
    }
}

// ================= final combine =================
__global__ void k_fin(float* __restrict__ out) {
    int idx = blockIdx.x * 256 + threadIdx.x;
    float m[6];
#pragma unroll
    for (int mi = 0; mi < 6; mi++) {
        float v = 0.f;
#pragma unroll
        for (int c = 0; c < 4; c++) v += g_part[(c * 6 + mi) * (NQ * NW) + idx];
        m[mi] = v;
    }
    int w = idx & 63;
    float mu2 = m[0] * (1.f / DD);
    float var = m[1] * (1.f / DD) - mu2 * mu2;
    float k = rsqrtf(var + LN_EPS);
    float sww = g_scal[0], swb = g_scal[1], sbb = g_scal[2];
    float doty = k * (m[2] - mu2 * g_swc[w]) + g_sbc[w];
    float ny2 = k * k * (m[3] - 2.f * mu2 * m[4] + mu2 * mu2 * sww)
              + 2.f * k * (m[5] - mu2 * swb) + sbb;
    float ny = sqrtf(fmaxf(ny2, 0.f));
    out[idx] = TEMP_SC * doty / fmaxf(ny, 1e-12f);
}

// ================= launch =================
extern "C" void kernel_launch(void* const* d_in, const int* in_sizes, int n_in,
                              void* d_out, int out_size) {
    const float* q    = (const float*)d_in[0];
    const float* cm   = (const float*)d_in[1];
    const float* ln1w = (const float*)d_in[2];
    const float* ln1b = (const float*)d_in[3];
    const float* w1   = (const float*)d_in[4];
    const float* b1   = (const float*)d_in[5];
    const float* w2   = (const float*)d_in[6];
    const float* b2   = (const float*)d_in[7];
    const float* ln2w = (const float*)d_in[8];
    const float* ln2b = (const float*)d_in[9];
    float* out = (float*)d_out;

    float *pQ1, *pC1, *pQW, *pCW;
    cudaGetSymbolAddress((void**)&pQ1, g_Q1);
    cudaGetSymbolAddress((void**)&pC1, g_C1);
    cudaGetSymbolAddress((void**)&pQW, g_QW);
    cudaGetSymbolAddress((void**)&pCW, g_CW);

    cudaFuncSetAttribute(k_tc3, cudaFuncAttributeMaxDynamicSharedMemorySize, SMEM_TC);

    k_rowstats_q<<<NQ, 256>>>(q);
    k_prep_c<<<NW, 256>>>(cm, ln2w, ln2b);
    k_s1bb<<<2, 256>>>(w1, ln1w, ln1b, b1);
    k_scal<<<1, 256>>>(ln2w, ln2b);
    k_w2h<<<dim3(16, 16), dim3(32, 8)>>>(w2);
    k_gemm_fold<<<dim3(NQ / 64, DD / 64), 256>>>(q,  NQ, w1, 0,   ln1w, pQ1);
    k_gemm_fold<<<dim3(NW / 64, DD / 64), 256>>>(cm, NW, w1, 512, ln1w, pC1);
    k_vw2<<<2, 256>>>(w2);
    k_gemm_plain<<<dim3(NQ / 64, DD / 64), 256>>>(pQ1, w2, pQW);
    k_gemm_plain<<<dim3(NW / 64, DD / 64), 256>>>(pC1, w2, pCW);
    k_tc3<<<NQ * 2, 256, SMEM_TC>>>(q, b2, ln2w, ln2b);
    k_fin<<<NQ * NW / 256, 256>>>(out);
}

// round 7
// speedup vs baseline: 3.8487x; 1.4833x over previous
#include <cuda_runtime.h>
#include <cuda_fp16.h>
#include <math.h>
#include <stdint.h>
#include <cstdint>

#define NQ 2048
#define NW 64
#define DD 512
#define D2 1024
#define TEMP_SC 16.0f
#define LN_EPS 1e-5f

// ---------------- scratch ----------------
__device__ float g_Q1[NQ * DD];
__device__ float g_C1[NW * DD];
__device__ float g_QW[NQ * DD];        // Q1 @ w2
__device__ float g_CW[NW * DD];        // C1 @ w2
__device__ float g_s1[DD];
__device__ float g_bb[DD];
__device__ float g_s1w[DD];            // s1 @ w2
__device__ float g_bbw[DD];            // bb @ w2
__device__ float g_qsum[NQ];
__device__ float g_qssq[NQ];
__device__ float g_csum[NW];
__device__ float g_cssq[NW];
__device__ float g_chatT[DD * NW];     // [j][w]
__device__ float g_swc[NW];
__device__ float g_sbc[NW];
__device__ float g_scal[3];
__device__ __align__(128) __half g_w2th[DD * DD];  // w2^T [j][k] fp16

#define SWZ(o) ((o) ^ (((o) >> 3) & 0x70))

// ================= helpers =================
__device__ __forceinline__ uint32_t smem_u32(const void* p) {
    uint32_t a;
    asm("{ .reg .u64 t; cvta.to.shared.u64 t, %1; cvt.u32.u64 %0, t; }" : "=r"(a) : "l"(p));
    return a;
}
__device__ __forceinline__ void cp16(uint32_t s, const void* g) {
    asm volatile("cp.async.cg.shared.global [%0], [%1], 16;" :: "r"(s), "l"(g));
}
__device__ __forceinline__ void ldsm4(uint32_t* r, uint32_t a) {
    asm volatile("ldmatrix.sync.aligned.m8n8.x4.shared.b16 {%0,%1,%2,%3}, [%4];"
                 : "=r"(r[0]), "=r"(r[1]), "=r"(r[2]), "=r"(r[3]) : "r"(a));
}
__device__ __forceinline__ void mma16816h(float* d, const uint32_t* a, const uint32_t* b) {
    asm volatile("mma.sync.aligned.m16n8k16.row.col.f32.f16.f16.f32 "
                 "{%0,%1,%2,%3}, {%4,%5,%6,%7}, {%8,%9}, {%0,%1,%2,%3};"
                 : "+f"(d[0]), "+f"(d[1]), "+f"(d[2]), "+f"(d[3])
                 : "r"(a[0]), "r"(a[1]), "r"(a[2]), "r"(a[3]), "r"(b[0]), "r"(b[1]));
}

// ================= phase A =================
__global__ void k_rowstats_q(const float* __restrict__ q) {
    int n = blockIdx.x, tid = threadIdx.x;
    float s = 0.f, ss = 0.f;
    for (int j = tid; j < DD; j += 256) { float v = q[n * DD + j]; s += v; ss += v * v; }
    __shared__ float sA[8], sB[8];
    int lane = tid & 31, wid = tid >> 5;
#pragma unroll
    for (int o = 16; o; o >>= 1) {
        s  += __shfl_down_sync(0xffffffffu, s, o);
        ss += __shfl_down_sync(0xffffffffu, ss, o);
    }
    if (lane == 0) { sA[wid] = s; sB[wid] = ss; }
    __syncthreads();
    if (tid == 0) {
        float a = 0.f, b = 0.f;
#pragma unroll
        for (int i = 0; i < 8; i++) { a += sA[i]; b += sB[i]; }
        g_qsum[n] = a; g_qssq[n] = b;
    }
}

__global__ void k_prep_c(const float* __restrict__ cm,
                         const float* __restrict__ ln2w,
                         const float* __restrict__ ln2b) {
    int w = blockIdx.x, tid = threadIdx.x;
    float s = 0.f, ss = 0.f, sw = 0.f, sb = 0.f;
    for (int j = tid; j < DD; j += 256) {
        float v = cm[w * DD + j];
        s += v; ss += v * v; sw += ln2w[j] * v; sb += ln2b[j] * v;
    }
    __shared__ float sA[8], sB[8], sC[8], sD[8];
    __shared__ float rbc;
    int lane = tid & 31, wid = tid >> 5;
#pragma unroll
    for (int o = 16; o; o >>= 1) {
        s  += __shfl_down_sync(0xffffffffu, s,  o);
        ss += __shfl_down_sync(0xffffffffu, ss, o);
        sw += __shfl_down_sync(0xffffffffu, sw, o);
        sb += __shfl_down_sync(0xffffffffu, sb, o);
    }
    if (lane == 0) { sA[wid] = s; sB[wid] = ss; sC[wid] = sw; sD[wid] = sb; }
    __syncthreads();
    if (tid == 0) {
        float a = 0.f, b = 0.f, c = 0.f, d = 0.f;
#pragma unroll
        for (int i = 0; i < 8; i++) { a += sA[i]; b += sB[i]; c += sC[i]; d += sD[i]; }
        g_csum[w] = a; g_cssq[w] = b;
        float r = 1.f / fmaxf(sqrtf(b), 1e-12f);
        rbc = r; g_swc[w] = r * c; g_sbc[w] = r * d;
    }
    __syncthreads();
    float r = rbc;
    for (int j = tid; j < DD; j += 256)
        g_chatT[j * NW + w] = cm[w * DD + j] * r;
}

__global__ void k_s1bb(const float* __restrict__ w1, const float* __restrict__ ln1w,
                       const float* __restrict__ ln1b, const float* __restrict__ b1) {
    int j = blockIdx.x * blockDim.x + threadIdx.x;
    if (j < DD) {
        float a = 0.f, b = 0.f;
        for (int i = 0; i < D2; i++) {
            float wv = w1[i * DD + j];
            a += ln1w[i] * wv; b += ln1b[i] * wv;
        }
        g_s1[j] = a; g_bb[j] = b1[j] + b;
    }
}

__global__ void k_vw2(const float* __restrict__ w2) {
    int j = blockIdx.x * blockDim.x + threadIdx.x;
    if (j < DD) {
        float a = 0.f, b = 0.f;
        for (int k = 0; k < DD; k++) {
            float wv = w2[k * DD + j];
            a += g_s1[k] * wv; b += g_bb[k] * wv;
        }
        g_s1w[j] = a; g_bbw[j] = b;
    }
}

__global__ void k_scal(const float* __restrict__ ln2w, const float* __restrict__ ln2b) {
    int tid = threadIdx.x;
    float a = 0.f, b = 0.f, c = 0.f;
    for (int j = tid; j < DD; j += 256) {
        float w = ln2w[j], bb = ln2b[j];
        a += w * w; b += w * bb; c += bb * bb;
    }
    __shared__ float sA[8], sB[8], sC[8];
    int lane = tid & 31, wid = tid >> 5;
#pragma unroll
    for (int o = 16; o; o >>= 1) {
        a += __shfl_down_sync(0xffffffffu, a, o);
        b += __shfl_down_sync(0xffffffffu, b, o);
        c += __shfl_down_sync(0xffffffffu, c, o);
    }
    if (lane == 0) { sA[wid] = a; sB[wid] = b; sC[wid] = c; }
    __syncthreads();
    if (tid == 0) {
        float x = 0.f, y = 0.f, z = 0.f;
#pragma unroll
        for (int i = 0; i < 8; i++) { x += sA[i]; y += sB[i]; z += sC[i]; }
        g_scal[0] = x; g_scal[1] = y; g_scal[2] = z;
    }
}

// w2 transpose to fp16 [j][k]
__global__ void k_w2h(const float* __restrict__ w2) {
    __shared__ float t[32][33];
    int bx = blockIdx.x * 32, by = blockIdx.y * 32;
    int tx = threadIdx.x, ty = threadIdx.y;
#pragma unroll
    for (int i = 0; i < 4; i++)
        t[ty + i * 8][tx] = w2[(by + ty + i * 8) * DD + bx + tx];
    __syncthreads();
#pragma unroll
    for (int i = 0; i < 4; i++) {
        int j = bx + ty + i * 8, k = by + tx;
        g_w2th[j * DD + k] = __float2half(t[tx][ty + i * 8]);
    }
}

// fold GEMM: Out = (A .* lnw_rows) @ w1[rowoff:rowoff+512]
__global__ void k_gemm_fold(const float* __restrict__ A, int M,
                            const float* __restrict__ w1, int rowoff,
                            const float* __restrict__ lnw,
                            float* __restrict__ Out) {
    __shared__ float As[16][65];
    __shared__ float Bs[16][64];
    int m0 = blockIdx.x * 64, j0 = blockIdx.y * 64;
    int tid = threadIdx.x;
    int tr = tid >> 4, tc = tid & 15;
    int r0 = tr * 4, c0 = tc * 4;
    float acc[4][4] = {};
    for (int kc = 0; kc < DD; kc += 16) {
        __syncthreads();
#pragma unroll
        for (int e = 0; e < 4; e++) {
            int idx = tid + e * 256;
            int m = idx >> 4, kk = idx & 15;
            As[kk][m] = A[(m0 + m) * DD + kc + kk] * lnw[rowoff + kc + kk];
        }
#pragma unroll
        for (int e = 0; e < 4; e++) {
            int idx = tid + e * 256;
            int kk = idx >> 6, j = idx & 63;
            Bs[kk][j] = w1[(rowoff + kc + kk) * DD + j0 + j];
        }
        __syncthreads();
#pragma unroll
        for (int kk = 0; kk < 16; kk++) {
            float a0 = As[kk][r0], a1 = As[kk][r0 + 1], a2 = As[kk][r0 + 2], a3 = As[kk][r0 + 3];
            float b0 = Bs[kk][c0], b1 = Bs[kk][c0 + 1], b2 = Bs[kk][c0 + 2], b3 = Bs[kk][c0 + 3];
            acc[0][0] += a0 * b0; acc[0][1] += a0 * b1; acc[0][2] += a0 * b2; acc[0][3] += a0 * b3;
            acc[1][0] += a1 * b0; acc[1][1] += a1 * b1; acc[1][2] += a1 * b2; acc[1][3] += a1 * b3;
            acc[2][0] += a2 * b0; acc[2][1] += a2 * b1; acc[2][2] += a2 * b2; acc[2][3] += a2 * b3;
            acc[3][0] += a3 * b0; acc[3][1] += a3 * b1; acc[3][2] += a3 * b2; acc[3][3] += a3 * b3;
        }
    }
#pragma unroll
    for (int i = 0; i < 4; i++)
#pragma unroll
        for (int j = 0; j < 4; j++)
            Out[(m0 + r0 + i) * DD + j0 + c0 + j] = acc[i][j];
}

// plain GEMM: Out = A @ B   (B row-major [k][j], 512x512)
__global__ void k_gemm_plain(const float* __restrict__ A,
                             const float* __restrict__ B,
                             float* __restrict__ Out) {
    __shared__ float As[16][65];
    __shared__ float Bs[16][64];
    int m0 = blockIdx.x * 64, j0 = blockIdx.y * 64;
    int tid = threadIdx.x;
    int tr = tid >> 4, tc = tid & 15;
    int r0 = tr * 4, c0 = tc * 4;
    float acc[4][4] = {};
    for (int kc = 0; kc < DD; kc += 16) {
        __syncthreads();
#pragma unroll
        for (int e = 0; e < 4; e++) {
            int idx = tid + e * 256;
            int m = idx >> 4, kk = idx & 15;
            As[kk][m] = A[(m0 + m) * DD + kc + kk];
        }
#pragma unroll
        for (int e = 0; e < 4; e++) {
            int idx = tid + e * 256;
            int kk = idx >> 6, j = idx & 63;
            Bs[kk][j] = B[(kc + kk) * DD + j0 + j];
        }
        __syncthreads();
#pragma unroll
        for (int kk = 0; kk < 16; kk++) {
            float a0 = As[kk][r0], a1 = As[kk][r0 + 1], a2 = As[kk][r0 + 2], a3 = As[kk][r0 + 3];
            float b0 = Bs[kk][c0], b1 = Bs[kk][c0 + 1], b2 = Bs[kk][c0 + 2], b3 = Bs[kk][c0 + 3];
            acc[0][0] += a0 * b0; acc[0][1] += a0 * b1; acc[0][2] += a0 * b2; acc[0][3] += a0 * b3;
            acc[1][0] += a1 * b0; acc[1][1] += a1 * b1; acc[1][2] += a1 * b2; acc[1][3] += a1 * b3;
            acc[2][0] += a2 * b0; acc[2][1] += a2 * b1; acc[2][2] += a2 * b2; acc[2][3] += a2 * b3;
            acc[3][0] += a3 * b0; acc[3][1] += a3 * b1; acc[3][2] += a3 * b2; acc[3][3] += a3 * b3;
        }
    }
#pragma unroll
    for (int i = 0; i < 4; i++)
#pragma unroll
        for (int j = 0; j < 4; j++)
            Out[(m0 + r0 + i) * DD + j0 + c0 + j] = acc[i][j];
}

// ================= main HMMA kernel: one CTA per pair, N=512 =================
// smem layout (bytes)
#define OFF_A    0          // 8 x 16384 = 131072 (A subtile per kc)
#define OFF_B    131072     // 2 x 16384 = 32768
#define OFF_C1   163840     // 2 x 17408 = 34816
#define OFF_META 198656
// meta float offsets
#define M_MU   0      // 128
#define M_IV   128    // 128
#define M_TS   256    // [2][512]
#define M_LW   1280   // 512
#define M_LB   1792   // 512
#define M_S1W  2304   // 512
#define M_BBW  2816   // 512
#define M_QW   3328   // [2][512]
// pool (prologue-only, overlaid by red in epilogue)
#define M_Q10  4352   // 512
#define M_Q11  4864   // 512
#define M_S1   5376   // 512
#define M_BB   5888   // 512
#define M_RED  4352   // [2][128][8] = 2048, alias of Q10/Q11
#define META_FLOATS 6400
#define SMEM_TC (OFF_META + META_FLOATS * 4)   // 224256

__device__ __forceinline__ void cp_B(uint32_t sb, int t, int tid) {
    int ch = t >> 3, kc = t & 7;
    uint32_t bh = sb + OFF_B + (t & 1) * 16384;
    const char* gh = (const char*)g_w2th + ((size_t)ch * 128) * 1024 + (size_t)kc * 128;
#pragma unroll
    for (int i = 0; i < 4; i++) {
        int u = tid + i * 256;
        int row = u >> 3, c16 = u & 7;
        uint32_t o = (uint32_t)(row * 128 + c16 * 16);
        cp16(bh + SWZ(o), gh + (size_t)row * 1024 + c16 * 16);
    }
    asm volatile("cp.async.commit_group;" ::: "memory");
}

__device__ __forceinline__ void cp_C1(uint32_t sb, int p, int kc, int tid) {
    uint32_t cb = sb + OFF_C1 + p * 17408;
    const char* gc = (const char*)g_C1 + (size_t)kc * 256;
#pragma unroll
    for (int i = 0; i < 4; i++) {
        int u = tid + i * 256;
        int w = u >> 4, c16 = u & 15;
        cp16(cb + (uint32_t)(w * 272 + c16 * 16), gc + (size_t)w * 2048 + c16 * 16);
    }
    asm volatile("cp.async.commit_group;" ::: "memory");
}

// build residual A subtile kc: 0.5*h*erf(h/sqrt2), fp16, rows 0..127 x k 64
__device__ __forceinline__ void buildA(char* smem, int p, int kc, int tid,
                                       const float* meta) {
    int r = tid >> 1, w = r & 63, rn = r >> 6;
    int kh = (tid & 1) * 32;
    float mu = meta[M_MU + r], iv = meta[M_IV + r];
    const float* Q1p = meta + (rn ? M_Q11 : M_Q10);
    const float* s1s = meta + M_S1;
    const float* bbs = meta + M_BB;
    const float* c1p = (const float*)(smem + OFF_C1 + p * 17408) + w * 68 + kh;
    char* ah = smem + OFF_A + kc * 16384;
#pragma unroll
    for (int kk = 0; kk < 32; kk += 2) {
        int j = kc * 64 + kh + kk;
        float ha = iv * (Q1p[j] + c1p[kk] - mu * s1s[j]) + bbs[j];
        float hb = iv * (Q1p[j + 1] + c1p[kk + 1] - mu * s1s[j + 1]) + bbs[j + 1];
        float ga = 0.5f * ha * erff(ha * 0.70710678118654752f);
        float gb = 0.5f * hb * erff(hb * 0.70710678118654752f);
        __half2 hp = __floats2half2_rn(ga, gb);
        uint32_t o = (uint32_t)(r * 128 + (kh + kk) * 2);
        *(__half2*)(ah + SWZ(o)) = hp;
    }
}

__global__ void __launch_bounds__(256, 1)
k_tc4(const float* __restrict__ q, const float* __restrict__ b2,
      const float* __restrict__ ln2w, const float* __restrict__ ln2b,
      float* __restrict__ out) {
    extern __shared__ char smem[];
    const uint32_t sb = smem_u32(smem);
    const int tid = threadIdx.x, lane = tid & 31, wid = tid >> 5;
    const int pair = blockIdx.x;
    const int n0 = pair * 2;
    float* meta = (float*)(smem + OFF_META);

    // ---- prologue meta loads ----
    for (int j = tid; j < DD; j += 256) {
        float b2j = b2[j];
        meta[M_TS + j]       = b2j + q[n0 * DD + j];
        meta[M_TS + 512 + j] = b2j + q[(n0 + 1) * DD + j];
        meta[M_LW + j] = ln2w[j];
        meta[M_LB + j] = ln2b[j];
        meta[M_S1W + j] = g_s1w[j];
        meta[M_BBW + j] = g_bbw[j];
        meta[M_QW + j]       = g_QW[n0 * DD + j];
        meta[M_QW + 512 + j] = g_QW[(n0 + 1) * DD + j];
        meta[M_Q10 + j] = g_Q1[n0 * DD + j];
        meta[M_Q11 + j] = g_Q1[(n0 + 1) * DD + j];
        meta[M_S1 + j] = g_s1[j];
        meta[M_BB + j] = g_bb[j];
    }
    if (tid < 128) {
        int rn = tid >> 6, w = tid & 63;
        float sx  = g_qsum[n0 + rn] + g_csum[w];
        float sxx = g_qssq[n0 + rn] + g_cssq[w];
        float m = sx * (1.f / 1024.f);
        float var = sxx * (1.f / 1024.f) - m * m;
        meta[M_MU + tid] = m;
        meta[M_IV + tid] = rsqrtf(var + LN_EPS);
    }
    __syncthreads();

    // ---- build A: stream C1 chunks, gelu-residual into 8 subtiles ----
    cp_C1(sb, 0, 0, tid);
    for (int kc = 0; kc < 8; kc++) {
        asm volatile("cp.async.wait_group 0;" ::: "memory");
        __syncthreads();
        if (kc < 7) cp_C1(sb, (kc + 1) & 1, kc + 1, tid);
        buildA(smem, kc & 1, kc, tid, meta);
    }
    cp_B(sb, 0, tid);   // first B tile
    __syncthreads();    // A fully written before ldsm

    // ---- mainloop: 4 chunks x 8 kc ----
    const int wm = wid & 3, wn = wid >> 2;
    const int arow = ((lane >> 3) & 1) * 8 + (lane & 7);
    const int acol = lane >> 4;
    const int brow = (lane >> 4) * 8 + (lane & 7);
    const int bcol = (lane >> 3) & 1;
    const int qr = lane >> 2, qc = lane & 3;

    float d[16][4];
#pragma unroll
    for (int i = 0; i < 16; i++)
#pragma unroll
        for (int j = 0; j < 4; j++) d[i][j] = 0.f;
    float pm[4][6];
#pragma unroll
    for (int i = 0; i < 4; i++)
#pragma unroll
        for (int m = 0; m < 6; m++) pm[i][m] = 0.f;

    for (int t = 0; t < 32; t++) {
        const int kc = t & 7;
        if (t < 31) cp_B(sb, t + 1, tid);
        asm volatile("cp.async.wait_group 1;" ::: "memory");
        if (t == 31) { asm volatile("cp.async.wait_group 0;" ::: "memory"); }
        __syncthreads();
        uint32_t Ah = sb + OFF_A + kc * 16384;
        uint32_t Bh = sb + OFF_B + (t & 1) * 16384;
#pragma unroll
        for (int s = 0; s < 4; s++) {
            uint32_t ahi[2][4], bhi[4][4];
#pragma unroll
            for (int tm = 0; tm < 2; tm++) {
                uint32_t o = (uint32_t)((32 * wm + 16 * tm + arow) * 128 + (2 * s + acol) * 16);
                ldsm4(ahi[tm], Ah + SWZ(o));
            }
#pragma unroll
            for (int u = 0; u < 4; u++) {
                uint32_t o = (uint32_t)((64 * wn + 16 * u + brow) * 128 + (2 * s + bcol) * 16);
                ldsm4(bhi[u], Bh + SWZ(o));
            }
#pragma unroll
            for (int tm = 0; tm < 2; tm++)
#pragma unroll
                for (int u = 0; u < 4; u++) {
                    mma16816h(d[tm * 8 + 2 * u],     ahi[tm], &bhi[u][0]);
                    mma16816h(d[tm * 8 + 2 * u + 1], ahi[tm], &bhi[u][2]);
                }
        }
        __syncthreads();

        if (kc == 7) {
            // ---- per-chunk epilogue: accumulate 6 moments ----
            const int ch = t >> 3, j0 = ch * 128;
#pragma unroll
            for (int tm = 0; tm < 2; tm++)
#pragma unroll
                for (int h = 0; h < 2; h++) {
                    int row = 32 * wm + 16 * tm + 8 * h + qr;
                    int w = row & 63, rn = row >> 6;
                    float mur = meta[M_MU + row], ivr = meta[M_IV + row];
                    float p0 = 0.f, p1 = 0.f, pA = 0.f, pB = 0.f, pC = 0.f, pE = 0.f;
#pragma unroll
                    for (int nt = 0; nt < 8; nt++)
#pragma unroll
                        for (int c = 0; c < 2; c++) {
                            int col = j0 + 64 * wn + 8 * nt + qc * 2 + c;
                            float Hl = ivr * (meta[M_QW + rn * 512 + col] + g_CW[w * DD + col]
                                              - mur * meta[M_S1W + col]) + meta[M_BBW + col];
                            float v = d[tm * 8 + nt][h * 2 + c] + 0.5f * Hl
                                    + meta[M_TS + rn * 512 + col];
                            float wj = meta[M_LW + col], bj = meta[M_LB + col];
                            float chv = g_chatT[col * NW + w];
                            float vw = v * wj;
                            p0 += v;        p1 += v * v;
                            pA += vw * chv; pB += vw * vw;
                            pC += vw * wj;  pE += vw * bj;
                        }
                    int i = tm * 2 + h;
                    pm[i][0] += p0; pm[i][1] += p1; pm[i][2] += pA;
                    pm[i][3] += pB; pm[i][4] += pC; pm[i][5] += pE;
                }
            if (t < 31) {
#pragma unroll
                for (int i = 0; i < 16; i++)
#pragma unroll
                    for (int j = 0; j < 4; j++) d[i][j] = 0.f;
            }
        }
    }

    // ---- final reduce: quad shuffle, smem across wn, output ----
    float* sred = meta + M_RED;
#pragma unroll
    for (int tm = 0; tm < 2; tm++)
#pragma unroll
        for (int h = 0; h < 2; h++) {
            int i = tm * 2 + h;
            int row = 32 * wm + 16 * tm + 8 * h + qr;
#pragma unroll
            for (int o = 1; o <= 2; o <<= 1)
#pragma unroll
                for (int m = 0; m < 6; m++)
                    pm[i][m] += __shfl_down_sync(0xffffffffu, pm[i][m], o, 4);
            if (qc == 0) {
                float* rp = sred + (wn * 128 + row) * 8;
#pragma unroll
                for (int m = 0; m < 6; m++) rp[m] = pm[i][m];
            }
        }
    __syncthreads();
    if (tid < 128) {
        int row = tid, w = row & 63, nn = n0 + (row >> 6);
        float m0 = sred[row * 8 + 0] + sred[(128 + row) * 8 + 0];
        float m1 = sred[row * 8 + 1] + sred[(128 + row) * 8 + 1];
        float A  = sred[row * 8 + 2] + sred[(128 + row) * 8 + 2];
        float B  = sred[row * 8 + 3] + sred[(128 + row) * 8 + 3];
        float C  = sred[row * 8 + 4] + sred[(128 + row) * 8 + 4];
        float E  = sred[row * 8 + 5] + sred[(128 + row) * 8 + 5];
        float mu2 = m0 * (1.f / DD);
        float var = m1 * (1.f / DD) - mu2 * mu2;
        float k = rsqrtf(var + LN_EPS);
        float sww = g_scal[0], swb = g_scal[1], sbb = g_scal[2];
        float doty = k * (A - mu2 * g_swc[w]) + g_sbc[w];
        float ny2 = k * k * (B - 2.f * mu2 * C + mu2 * mu2 * sww)
                  + 2.f * k * (E - mu2 * swb) + sbb;
        float ny = sqrtf(fmaxf(ny2, 0.f));
        out[nn * NW + w] = TEMP_SC * doty / fmaxf(ny, 1e-12f);
    }
}

// ================= launch =================
extern "C" void kernel_launch(void* const* d_in, const int* in_sizes, int n_in,
                              void* d_out, int out_size) {
    const float* q    = (const float*)d_in[0];
    const float* cm   = (const float*)d_in[1];
    const float* ln1w = (const float*)d_in[2];
    const float* ln1b = (const float*)d_in[3];
    const float* w1   = (const float*)d_in[4];
    const float* b1   = (const float*)d_in[5];
    const float* w2   = (const float*)d_in[6];
    const float* b2   = (const float*)d_in[7];
    const float* ln2w = (const float*)d_in[8];
    const float* ln2b = (const float*)d_in[9];
    float* out = (float*)d_out;

    float *pQ1, *pC1, *pQW, *pCW;
    cudaGetSymbolAddress((void**)&pQ1, g_Q1);
    cudaGetSymbolAddress((void**)&pC1, g_C1);
    cudaGetSymbolAddress((void**)&pQW, g_QW);
    cudaGetSymbolAddress((void**)&pCW, g_CW);

    cudaFuncSetAttribute(k_tc4, cudaFuncAttributeMaxDynamicSharedMemorySize, SMEM_TC);

    k_rowstats_q<<<NQ, 256>>>(q);
    k_prep_c<<<NW, 256>>>(cm, ln2w, ln2b);
    k_s1bb<<<2, 256>>>(w1, ln1w, ln1b, b1);
    k_scal<<<1, 256>>>(ln2w, ln2b);
    k_w2h<<<dim3(16, 16), dim3(32, 8)>>>(w2);
    k_gemm_fold<<<dim3(NQ / 64, DD / 64), 256>>>(q,  NQ, w1, 0,   ln1w, pQ1);
    k_gemm_fold<<<dim3(NW / 64, DD / 64), 256>>>(cm, NW, w1, 512, ln1w, pC1);
    k_vw2<<<2, 256>>>(w2);
    k_gemm_plain<<<dim3(NQ / 64, DD / 64), 256>>>(pQ1, w2, pQW);
    k_gemm_plain<<<dim3(NW / 64, DD / 64), 256>>>(pC1, w2, pCW);
    k_tc4<<<NQ / 2, 256, SMEM_TC>>>(q, b2, ln2w, ln2b, out);
}

// round 8
// speedup vs baseline: 4.5425x; 1.1803x over previous
#include <cuda_runtime.h>
#include <cuda_fp16.h>
#include <math.h>
#include <stdint.h>
#include <cstdint>

#define NQ 2048
#define NW 64
#define DD 512
#define D2 1024
#define TEMP_SC 16.0f
#define LN_EPS 1e-5f

// ---------------- scratch ----------------
__device__ float g_Q1[NQ * DD];
__device__ float g_C1[NW * DD];
__device__ float g_QW[NQ * DD];        // Q1 @ w2
__device__ float g_CW[NW * DD];        // C1 @ w2
__device__ float g_s1[DD];
__device__ float g_bb[DD];
__device__ float g_s1w[DD];            // s1 @ w2
__device__ float g_bbw[DD];            // bb @ w2
__device__ float g_qsum[NQ];
__device__ float g_qssq[NQ];
__device__ float g_csum[NW];
__device__ float g_cssq[NW];
__device__ float g_chatT[DD * NW];     // [j][w]
__device__ float g_swc[NW];
__device__ float g_sbc[NW];
__device__ float g_scal[3];
__device__ __align__(128) __half g_w2th[DD * DD];  // w2^T [j][k] fp16
__device__ __align__(128) __half g_c1h[NW * DD];   // C1 fp16 [w][j]
__device__ __align__(128) __half g_cwh[DD * NW];   // 0.5*CW^T fp16 [j][w']

#define SWZ(o) ((o) ^ (((o) >> 3) & 0x70))

// ================= helpers =================
__device__ __forceinline__ uint32_t smem_u32(const void* p) {
    uint32_t a;
    asm("{ .reg .u64 t; cvta.to.shared.u64 t, %1; cvt.u32.u64 %0, t; }" : "=r"(a) : "l"(p));
    return a;
}
__device__ __forceinline__ void cp16(uint32_t s, const void* g) {
    asm volatile("cp.async.cg.shared.global [%0], [%1], 16;" :: "r"(s), "l"(g));
}
__device__ __forceinline__ void ldsm4(uint32_t* r, uint32_t a) {
    asm volatile("ldmatrix.sync.aligned.m8n8.x4.shared.b16 {%0,%1,%2,%3}, [%4];"
                 : "=r"(r[0]), "=r"(r[1]), "=r"(r[2]), "=r"(r[3]) : "r"(a));
}
__device__ __forceinline__ void mma16816h(float* d, const uint32_t* a, const uint32_t* b) {
    asm volatile("mma.sync.aligned.m16n8k16.row.col.f32.f16.f16.f32 "
                 "{%0,%1,%2,%3}, {%4,%5,%6,%7}, {%8,%9}, {%0,%1,%2,%3};"
                 : "+f"(d[0]), "+f"(d[1]), "+f"(d[2]), "+f"(d[3])
                 : "r"(a[0]), "r"(a[1]), "r"(a[2]), "r"(a[3]), "r"(b[0]), "r"(b[1]));
}

// ================= phase A =================
__global__ void k_rowstats_q(const float* __restrict__ q) {
    int n = blockIdx.x, tid = threadIdx.x;
    float s = 0.f, ss = 0.f;
    for (int j = tid; j < DD; j += 256) { float v = q[n * DD + j]; s += v; ss += v * v; }
    __shared__ float sA[8], sB[8];
    int lane = tid & 31, wid = tid >> 5;
#pragma unroll
    for (int o = 16; o; o >>= 1) {
        s  += __shfl_down_sync(0xffffffffu, s, o);
        ss += __shfl_down_sync(0xffffffffu, ss, o);
    }
    if (lane == 0) { sA[wid] = s; sB[wid] = ss; }
    __syncthreads();
    if (tid == 0) {
        float a = 0.f, b = 0.f;
#pragma unroll
        for (int i = 0; i < 8; i++) { a += sA[i]; b += sB[i]; }
        g_qsum[n] = a; g_qssq[n] = b;
    }
}

__global__ void k_prep_c(const float* __restrict__ cm,
                         const float* __restrict__ ln2w,
                         const float* __restrict__ ln2b) {
    int w = blockIdx.x, tid = threadIdx.x;
    float s = 0.f, ss = 0.f, sw = 0.f, sb = 0.f;
    for (int j = tid; j < DD; j += 256) {
        float v = cm[w * DD + j];
        s += v; ss += v * v; sw += ln2w[j] * v; sb += ln2b[j] * v;
    }
    __shared__ float sA[8], sB[8], sC[8], sD[8];
    __shared__ float rbc;
    int lane = tid & 31, wid = tid >> 5;
#pragma unroll
    for (int o = 16; o; o >>= 1) {
        s  += __shfl_down_sync(0xffffffffu, s,  o);
        ss += __shfl_down_sync(0xffffffffu, ss, o);
        sw += __shfl_down_sync(0xffffffffu, sw, o);
        sb += __shfl_down_sync(0xffffffffu, sb, o);
    }
    if (lane == 0) { sA[wid] = s; sB[wid] = ss; sC[wid] = sw; sD[wid] = sb; }
    __syncthreads();
    if (tid == 0) {
        float a = 0.f, b = 0.f, c = 0.f, d = 0.f;
#pragma unroll
        for (int i = 0; i < 8; i++) { a += sA[i]; b += sB[i]; c += sC[i]; d += sD[i]; }
        g_csum[w] = a; g_cssq[w] = b;
        float r = 1.f / fmaxf(sqrtf(b), 1e-12f);
        rbc = r; g_swc[w] = r * c; g_sbc[w] = r * d;
    }
    __syncthreads();
    float r = rbc;
    for (int j = tid; j < DD; j += 256)
        g_chatT[j * NW + w] = cm[w * DD + j] * r;
}

__global__ void k_s1bb(const float* __restrict__ w1, const float* __restrict__ ln1w,
                       const float* __restrict__ ln1b, const float* __restrict__ b1) {
    int j = blockIdx.x * blockDim.x + threadIdx.x;
    if (j < DD) {
        float a = 0.f, b = 0.f;
        for (int i = 0; i < D2; i++) {
            float wv = w1[i * DD + j];
            a += ln1w[i] * wv; b += ln1b[i] * wv;
        }
        g_s1[j] = a; g_bb[j] = b1[j] + b;
    }
}

__global__ void k_vw2(const float* __restrict__ w2) {
    int j = blockIdx.x * blockDim.x + threadIdx.x;
    if (j < DD) {
        float a = 0.f, b = 0.f;
        for (int k = 0; k < DD; k++) {
            float wv = w2[k * DD + j];
            a += g_s1[k] * wv; b += g_bb[k] * wv;
        }
        g_s1w[j] = a; g_bbw[j] = b;
    }
}

__global__ void k_scal(const float* __restrict__ ln2w, const float* __restrict__ ln2b) {
    int tid = threadIdx.x;
    float a = 0.f, b = 0.f, c = 0.f;
    for (int j = tid; j < DD; j += 256) {
        float w = ln2w[j], bb = ln2b[j];
        a += w * w; b += w * bb; c += bb * bb;
    }
    __shared__ float sA[8], sB[8], sC[8];
    int lane = tid & 31, wid = tid >> 5;
#pragma unroll
    for (int o = 16; o; o >>= 1) {
        a += __shfl_down_sync(0xffffffffu, a, o);
        b += __shfl_down_sync(0xffffffffu, b, o);
        c += __shfl_down_sync(0xffffffffu, c, o);
    }
    if (lane == 0) { sA[wid] = a; sB[wid] = b; sC[wid] = c; }
    __syncthreads();
    if (tid == 0) {
        float x = 0.f, y = 0.f, z = 0.f;
#pragma unroll
        for (int i = 0; i < 8; i++) { x += sA[i]; y += sB[i]; z += sC[i]; }
        g_scal[0] = x; g_scal[1] = y; g_scal[2] = z;
    }
}

// w2 transpose to fp16 [j][k]
__global__ void k_w2h(const float* __restrict__ w2) {
    __shared__ float t[32][33];
    int bx = blockIdx.x * 32, by = blockIdx.y * 32;
    int tx = threadIdx.x, ty = threadIdx.y;
#pragma unroll
    for (int i = 0; i < 4; i++)
        t[ty + i * 8][tx] = w2[(by + ty + i * 8) * DD + bx + tx];
    __syncthreads();
#pragma unroll
    for (int i = 0; i < 4; i++) {
        int j = bx + ty + i * 8, k = by + tx;
        g_w2th[j * DD + k] = __float2half(t[tx][ty + i * 8]);
    }
}

// merged fold GEMM: bx<32 -> q-part, bx==32 -> c-part
__global__ void k_gemm_fold2(const float* __restrict__ q, const float* __restrict__ cm,
                             const float* __restrict__ w1, const float* __restrict__ lnw,
                             float* __restrict__ Q1, float* __restrict__ C1) {
    __shared__ float As[16][65];
    __shared__ float Bs[16][64];
    int bx = blockIdx.x;
    const float* A; float* Out; int m0, rowoff;
    if (bx < 32) { A = q; Out = Q1; m0 = bx * 64; rowoff = 0; }
    else         { A = cm; Out = C1; m0 = 0; rowoff = 512; }
    int j0 = blockIdx.y * 64;
    int tid = threadIdx.x;
    int tr = tid >> 4, tc = tid & 15;
    int r0 = tr * 4, c0 = tc * 4;
    float acc[4][4] = {};
    for (int kc = 0; kc < DD; kc += 16) {
        __syncthreads();
#pragma unroll
        for (int e = 0; e < 4; e++) {
            int idx = tid + e * 256;
            int m = idx >> 4, kk = idx & 15;
            As[kk][m] = A[(m0 + m) * DD + kc + kk] * lnw[rowoff + kc + kk];
        }
#pragma unroll
        for (int e = 0; e < 4; e++) {
            int idx = tid + e * 256;
            int kk = idx >> 6, j = idx & 63;
            Bs[kk][j] = w1[(rowoff + kc + kk) * DD + j0 + j];
        }
        __syncthreads();
#pragma unroll
        for (int kk = 0; kk < 16; kk++) {
            float a0 = As[kk][r0], a1 = As[kk][r0 + 1], a2 = As[kk][r0 + 2], a3 = As[kk][r0 + 3];
            float b0 = Bs[kk][c0], b1 = Bs[kk][c0 + 1], b2 = Bs[kk][c0 + 2], b3 = Bs[kk][c0 + 3];
            acc[0][0] += a0 * b0; acc[0][1] += a0 * b1; acc[0][2] += a0 * b2; acc[0][3] += a0 * b3;
            acc[1][0] += a1 * b0; acc[1][1] += a1 * b1; acc[1][2] += a1 * b2; acc[1][3] += a1 * b3;
            acc[2][0] += a2 * b0; acc[2][1] += a2 * b1; acc[2][2] += a2 * b2; acc[2][3] += a2 * b3;
            acc[3][0] += a3 * b0; acc[3][1] += a3 * b1; acc[3][2] += a3 * b2; acc[3][3] += a3 * b3;
        }
    }
#pragma unroll
    for (int i = 0; i < 4; i++)
#pragma unroll
        for (int j = 0; j < 4; j++)
            Out[(m0 + r0 + i) * DD + j0 + c0 + j] = acc[i][j];
}

// merged plain GEMM vs w2: bx<32 -> Q1->QW, bx==32 -> C1->CW
__global__ void k_gemm_plain2(const float* __restrict__ Q1, const float* __restrict__ C1,
                              const float* __restrict__ w2,
                              float* __restrict__ QW, float* __restrict__ CW) {
    __shared__ float As[16][65];
    __shared__ float Bs[16][64];
    int bx = blockIdx.x;
    const float* A; float* Out; int m0;
    if (bx < 32) { A = Q1; Out = QW; m0 = bx * 64; }
    else         { A = C1; Out = CW; m0 = 0; }
    int j0 = blockIdx.y * 64;
    int tid = threadIdx.x;
    int tr = tid >> 4, tc = tid & 15;
    int r0 = tr * 4, c0 = tc * 4;
    float acc[4][4] = {};
    for (int kc = 0; kc < DD; kc += 16) {
        __syncthreads();
#pragma unroll
        for (int e = 0; e < 4; e++) {
            int idx = tid + e * 256;
            int m = idx >> 4, kk = idx & 15;
            As[kk][m] = A[(m0 + m) * DD + kc + kk];
        }
#pragma unroll
        for (int e = 0; e < 4; e++) {
            int idx = tid + e * 256;
            int kk = idx >> 6, j = idx & 63;
            Bs[kk][j] = w2[(kc + kk) * DD + j0 + j];
        }
        __syncthreads();
#pragma unroll
        for (int kk = 0; kk < 16; kk++) {
            float a0 = As[kk][r0], a1 = As[kk][r0 + 1], a2 = As[kk][r0 + 2], a3 = As[kk][r0 + 3];
            float b0 = Bs[kk][c0], b1 = Bs[kk][c0 + 1], b2 = Bs[kk][c0 + 2], b3 = Bs[kk][c0 + 3];
            acc[0][0] += a0 * b0; acc[0][1] += a0 * b1; acc[0][2] += a0 * b2; acc[0][3] += a0 * b3;
            acc[1][0] += a1 * b0; acc[1][1] += a1 * b1; acc[1][2] += a1 * b2; acc[1][3] += a1 * b3;
            acc[2][0] += a2 * b0; acc[2][1] += a2 * b1; acc[2][2] += a2 * b2; acc[2][3] += a2 * b3;
            acc[3][0] += a3 * b0; acc[3][1] += a3 * b1; acc[3][2] += a3 * b2; acc[3][3] += a3 * b3;
        }
    }
#pragma unroll
    for (int i = 0; i < 4; i++)
#pragma unroll
        for (int j = 0; j < 4; j++)
            Out[(m0 + r0 + i) * DD + j0 + c0 + j] = acc[i][j];
}

// converts: b<64 -> C1 fp16; b>=64 -> 0.5*CW^T fp16
__global__ void k_conv() {
    int b = blockIdx.x, tid = threadIdx.x;
    if (b < 64) {
        for (int j = tid; j < DD; j += 256)
            g_c1h[b * DD + j] = __float2half(g_C1[b * DD + j]);
    } else {
        int base = (b - 64) * 512;
        for (int e = tid; e < 512; e += 256) {
            int idx = base + e;
            int j = idx >> 6, w = idx & 63;
            g_cwh[idx] = __float2half(0.5f * g_CW[w * DD + j]);
        }
    }
}

// ================= main HMMA kernel: K=576 (CW folded), no epilogue globals =================
#define OFF_A    0          // 9 x 16384 = 147456 (8 residual kc + 1 ext chunk)
#define OFF_B    147456     // 2 x 16384 = 32768 (also Q1/s1/bb pool during build)
#define OFF_CHAT 180224     // 34816: c1h staging during build; chat chunk in mainloop; red at end
#define OFF_META 215040
#define M_MU   0
#define M_IV   128
#define M_U1   256
#define M_U2   768    // [2][512]
#define M_U3   1792   // [2][512]
#define M_LW   2816
#define M_LB   3328
#define SMEM_TC 230400
// pool (in OFF_B region, build-phase only)
#define P_Q10  0
#define P_Q11  512
#define P_S1   1024
#define P_BB   1536

__device__ __forceinline__ void cp_chat(uint32_t sb, int ch, int tid) {
    int j0 = ch * 128;
#pragma unroll
    for (int i = 0; i < 8; i++) {
        int u = tid + i * 256;
        int row = u >> 4, c16 = u & 15;
        cp16(sb + OFF_CHAT + (uint32_t)(row * 272 + c16 * 16),
             (const char*)g_chatT + (size_t)(j0 + row) * 256 + c16 * 16);
    }
}

// load B tile t (t = ch*9 + kc); kc==8 pulls the CW ext rows; kc==1 piggybacks chat(ch)
__device__ __forceinline__ void cp_B(uint32_t sb, int t, int tid) {
    int ch = t / 9, kc = t - ch * 9;
    int j0 = ch * 128;
    uint32_t bh = sb + OFF_B + (t & 1) * 16384;
    if (kc < 8) {
        const char* gh = (const char*)g_w2th + (size_t)j0 * 1024 + (size_t)kc * 128;
#pragma unroll
        for (int i = 0; i < 4; i++) {
            int u = tid + i * 256;
            int row = u >> 3, c16 = u & 7;
            uint32_t o = (uint32_t)(row * 128 + c16 * 16);
            cp16(bh + SWZ(o), gh + (size_t)row * 1024 + c16 * 16);
        }
    } else {
        const char* gh = (const char*)g_cwh + (size_t)j0 * 128;
#pragma unroll
        for (int i = 0; i < 4; i++) {
            int u = tid + i * 256;
            int row = u >> 3, c16 = u & 7;
            uint32_t o = (uint32_t)(row * 128 + c16 * 16);
            cp16(bh + SWZ(o), gh + (size_t)row * 128 + c16 * 16);
        }
    }
    if (kc == 1) cp_chat(sb, ch, tid);   // epilogue(ch-1) already done; consumed at kc==8
    asm volatile("cp.async.commit_group;" ::: "memory");
}

__device__ __forceinline__ void cp_c1h(uint32_t sb, int p, int kc, int tid) {
    uint32_t cb = sb + OFF_CHAT + p * 9216;
    const char* gc = (const char*)g_c1h + (size_t)kc * 128;
#pragma unroll
    for (int i = 0; i < 2; i++) {
        int u = tid + i * 256;
        int w = u >> 3, c16 = u & 7;
        cp16(cb + (uint32_t)(w * 144 + c16 * 16), gc + (size_t)w * 1024 + c16 * 16);
    }
    asm volatile("cp.async.commit_group;" ::: "memory");
}

// build residual A subtile kc: 0.5*h*erf(h/sqrt2), fp16
__device__ __forceinline__ void buildA(char* smem, int p, int kc, int tid,
                                       const float* meta, const float* pool) {
    int r = tid >> 1, w = r & 63, rn = r >> 6;
    int kh = (tid & 1) * 32;
    float mu = meta[M_MU + r], iv = meta[M_IV + r];
    const float* Q1p = pool + (rn ? P_Q11 : P_Q10);
    const float* s1s = pool + P_S1;
    const float* bbs = pool + P_BB;
    const __half* c1p = (const __half*)(smem + OFF_CHAT + p * 9216 + w * 144) + kh;
    char* ah = smem + OFF_A + kc * 16384;
#pragma unroll
    for (int kk = 0; kk < 32; kk += 2) {
        int j = kc * 64 + kh + kk;
        float2 cf = __half22float2(*(const __half2*)(c1p + kk));
        float ha = iv * (Q1p[j] + cf.x - mu * s1s[j]) + bbs[j];
        float hb = iv * (Q1p[j + 1] + cf.y - mu * s1s[j + 1]) + bbs[j + 1];
        float ga = 0.5f * ha * erff(ha * 0.70710678118654752f);
        float gb = 0.5f * hb * erff(hb * 0.70710678118654752f);
        __half2 hp = __floats2half2_rn(ga, gb);
        uint32_t o = (uint32_t)(r * 128 + (kh + kk) * 2);
        *(__half2*)(ah + SWZ(o)) = hp;
    }
}

__global__ void __launch_bounds__(256, 1)
k_tc5(const float* __restrict__ q, const float* __restrict__ b2,
      const float* __restrict__ ln2w, const float* __restrict__ ln2b,
      float* __restrict__ out) {
    extern __shared__ char smem[];
    const uint32_t sb = smem_u32(smem);
    const int tid = threadIdx.x, lane = tid & 31, wid = tid >> 5;
    const int pair = blockIdx.x;
    const int n0 = pair * 2;
    float* meta = (float*)(smem + OFF_META);
    float* pool = (float*)(smem + OFF_B);
    float* chs = (float*)(smem + OFF_CHAT);

    // ---- prologue: meta + pool ----
    for (int j = tid; j < DD; j += 256) {
        meta[M_U1 + j] = 0.5f * g_s1w[j];
        meta[M_U2 + j]       = 0.5f * g_QW[n0 * DD + j];
        meta[M_U2 + 512 + j] = 0.5f * g_QW[(n0 + 1) * DD + j];
        float hb = b2[j] + 0.5f * g_bbw[j];
        meta[M_U3 + j]       = q[n0 * DD + j] + hb;
        meta[M_U3 + 512 + j] = q[(n0 + 1) * DD + j] + hb;
        meta[M_LW + j] = ln2w[j];
        meta[M_LB + j] = ln2b[j];
        pool[P_Q10 + j] = g_Q1[n0 * DD + j];
        pool[P_Q11 + j] = g_Q1[(n0 + 1) * DD + j];
        pool[P_S1 + j] = g_s1[j];
        pool[P_BB + j] = g_bb[j];
    }
    if (tid < 128) {
        int rn = tid >> 6, w = tid & 63;
        float sx  = g_qsum[n0 + rn] + g_csum[w];
        float sxx = g_qssq[n0 + rn] + g_cssq[w];
        float m = sx * (1.f / 1024.f);
        float var = sxx * (1.f / 1024.f) - m * m;
        meta[M_MU + tid] = m;
        meta[M_IV + tid] = rsqrtf(var + LN_EPS);
    }
    __syncthreads();

    // ---- A ext chunk (kc=8): zero then scatter ivr at col w(row) ----
    {
        char* ext = smem + OFF_A + 8 * 16384;
#pragma unroll
        for (int i = 0; i < 4; i++)
            *(float4*)(ext + tid * 16 + i * 4096) = make_float4(0.f, 0.f, 0.f, 0.f);
        __syncthreads();
        if (tid < 128) {
            int row = tid, w = row & 63;
            uint32_t o = (uint32_t)(row * 128 + w * 2);
            *(__half*)(ext + SWZ(o)) = __float2half(meta[M_IV + row]);
        }
    }

    // ---- build A residual chunks (c1h staged in CHAT region) ----
    cp_c1h(sb, 0, 0, tid);
    for (int kc = 0; kc < 8; kc++) {
        asm volatile("cp.async.wait_group 0;" ::: "memory");
        __syncthreads();
        if (kc < 7) cp_c1h(sb, (kc + 1) & 1, kc + 1, tid);
        buildA(smem, kc & 1, kc, tid, meta, pool);
    }
    __syncthreads();                  // build done; B/CHAT regions reusable
    cp_chat(sb, 0, tid);              // chat for chunk 0
    cp_B(sb, 0, tid);                 // B tile 0 (commits both)
    __syncthreads();

    // ---- mainloop: 4 chunks x 9 kc ----
    const int wm = wid & 3, wn = wid >> 2;
    const int arow = ((lane >> 3) & 1) * 8 + (lane & 7);
    const int acol = lane >> 4;
    const int brow = (lane >> 4) * 8 + (lane & 7);
    const int bcol = (lane >> 3) & 1;
    const int qr = lane >> 2, qc = lane & 3;

    float d[16][4];
#pragma unroll
    for (int i = 0; i < 16; i++)
#pragma unroll
        for (int j = 0; j < 4; j++) d[i][j] = 0.f;
    float pm[4][6];
#pragma unroll
    for (int i = 0; i < 4; i++)
#pragma unroll
        for (int m = 0; m < 6; m++) pm[i][m] = 0.f;

    for (int t = 0; t < 36; t++) {
        const int ch = t / 9, kc = t - ch * 9;
        if (t < 35) cp_B(sb, t + 1, tid);
        if (t < 35) { asm volatile("cp.async.wait_group 1;" ::: "memory"); }
        else        { asm volatile("cp.async.wait_group 0;" ::: "memory"); }
        __syncthreads();
        uint32_t Ah = sb + OFF_A + kc * 16384;
        uint32_t Bh = sb + OFF_B + (t & 1) * 16384;
#pragma unroll
        for (int s = 0; s < 4; s++) {
            uint32_t ahi[2][4], bhi[4][4];
#pragma unroll
            for (int tm = 0; tm < 2; tm++) {
                uint32_t o = (uint32_t)((32 * wm + 16 * tm + arow) * 128 + (2 * s + acol) * 16);
                ldsm4(ahi[tm], Ah + SWZ(o));
            }
#pragma unroll
            for (int u = 0; u < 4; u++) {
                uint32_t o = (uint32_t)((64 * wn + 16 * u + brow) * 128 + (2 * s + bcol) * 16);
                ldsm4(bhi[u], Bh + SWZ(o));
            }
#pragma unroll
            for (int tm = 0; tm < 2; tm++)
#pragma unroll
                for (int u = 0; u < 4; u++) {
                    mma16816h(d[tm * 8 + 2 * u],     ahi[tm], &bhi[u][0]);
                    mma16816h(d[tm * 8 + 2 * u + 1], ahi[tm], &bhi[u][2]);
                }
        }
        __syncthreads();

        if (kc == 8) {
            const int j0 = ch * 128;
#pragma unroll
            for (int tm = 0; tm < 2; tm++)
#pragma unroll
                for (int h = 0; h < 2; h++) {
                    int row = 32 * wm + 16 * tm + 8 * h + qr;
                    int w = row & 63, rn = row >> 6;
                    float ivr = meta[M_IV + row];
                    float a = -ivr * meta[M_MU + row];
                    float p0 = 0.f, p1 = 0.f, pA = 0.f, pB = 0.f, pC = 0.f, pE = 0.f;
#pragma unroll
                    for (int nt = 0; nt < 8; nt++) {
                        int cl0 = 64 * wn + 8 * nt + qc * 2;
                        int col0 = j0 + cl0;
                        float2 U1 = *(const float2*)&meta[M_U1 + col0];
                        float2 U2 = *(const float2*)&meta[M_U2 + rn * 512 + col0];
                        float2 U3 = *(const float2*)&meta[M_U3 + rn * 512 + col0];
                        float2 LWv = *(const float2*)&meta[M_LW + col0];
                        float2 LBv = *(const float2*)&meta[M_LB + col0];
                        float ch0 = chs[cl0 * 68 + w];
                        float ch1 = chs[(cl0 + 1) * 68 + w];
                        float v0 = d[tm * 8 + nt][h * 2]     + a * U1.x + ivr * U2.x + U3.x;
                        float v1 = d[tm * 8 + nt][h * 2 + 1] + a * U1.y + ivr * U2.y + U3.y;
                        float vw0 = v0 * LWv.x, vw1 = v1 * LWv.y;
                        p0 += v0 + v1;
                        p1 += v0 * v0 + v1 * v1;
                        pA += vw0 * ch0 + vw1 * ch1;
                        pB += vw0 * vw0 + vw1 * vw1;
                        pC += vw0 * LWv.x + vw1 * LWv.y;
                        pE += vw0 * LBv.x + vw1 * LBv.y;
                    }
                    int i = tm * 2 + h;
                    pm[i][0] += p0; pm[i][1] += p1; pm[i][2] += pA;
                    pm[i][3] += pB; pm[i][4] += pC; pm[i][5] += pE;
                }
            if (t < 35) {
#pragma unroll
                for (int i = 0; i < 16; i++)
#pragma unroll
                    for (int j = 0; j < 4; j++) d[i][j] = 0.f;
            }
        }
    }

    // ---- final reduce (red aliases CHAT region) ----
    __syncthreads();
    float* sred = (float*)(smem + OFF_CHAT);
#pragma unroll
    for (int tm = 0; tm < 2; tm++)
#pragma unroll
        for (int h = 0; h < 2; h++) {
            int i = tm * 2 + h;
            int row = 32 * wm + 16 * tm + 8 * h + qr;
#pragma unroll
            for (int o = 1; o <= 2; o <<= 1)
#pragma unroll
                for (int m = 0; m < 6; m++)
                    pm[i][m] += __shfl_down_sync(0xffffffffu, pm[i][m], o, 4);
            if (qc == 0) {
                float* rp = sred + (wn * 128 + row) * 8;
#pragma unroll
                for (int m = 0; m < 6; m++) rp[m] = pm[i][m];
            }
        }
    __syncthreads();
    if (tid < 128) {
        int row = tid, w = row & 63, nn = n0 + (row >> 6);
        float m0 = sred[row * 8 + 0] + sred[(128 + row) * 8 + 0];
        float m1 = sred[row * 8 + 1] + sred[(128 + row) * 8 + 1];
        float A  = sred[row * 8 + 2] + sred[(128 + row) * 8 + 2];
        float B  = sred[row * 8 + 3] + sred[(128 + row) * 8 + 3];
        float C  = sred[row * 8 + 4] + sred[(128 + row) * 8 + 4];
        float E  = sred[row * 8 + 5] + sred[(128 + row) * 8 + 5];
        float mu2 = m0 * (1.f / DD);
        float var = m1 * (1.f / DD) - mu2 * mu2;
        float k = rsqrtf(var + LN_EPS);
        float sww = g_scal[0], swb = g_scal[1], sbb = g_scal[2];
        float doty = k * (A - mu2 * g_swc[w]) + g_sbc[w];
        float ny2 = k * k * (B - 2.f * mu2 * C + mu2 * mu2 * sww)
                  + 2.f * k * (E - mu2 * swb) + sbb;
        float ny = sqrtf(fmaxf(ny2, 0.f));
        out[nn * NW + w] = TEMP_SC * doty / fmaxf(ny, 1e-12f);
    }
}

// ================= launch =================
extern "C" void kernel_launch(void* const* d_in, const int* in_sizes, int n_in,
                              void* d_out, int out_size) {
    const float* q    = (const float*)d_in[0];
    const float* cm   = (const float*)d_in[1];
    const float* ln1w = (const float*)d_in[2];
    const float* ln1b = (const float*)d_in[3];
    const float* w1   = (const float*)d_in[4];
    const float* b1   = (const float*)d_in[5];
    const float* w2   = (const float*)d_in[6];
    const float* b2   = (const float*)d_in[7];
    const float* ln2w = (const float*)d_in[8];
    const float* ln2b = (const float*)d_in[9];
    float* out = (float*)d_out;

    float *pQ1, *pC1, *pQW, *pCW;
    cudaGetSymbolAddress((void**)&pQ1, g_Q1);
    cudaGetSymbolAddress((void**)&pC1, g_C1);
    cudaGetSymbolAddress((void**)&pQW, g_QW);
    cudaGetSymbolAddress((void**)&pCW, g_CW);

    cudaFuncSetAttribute(k_tc5, cudaFuncAttributeMaxDynamicSharedMemorySize, SMEM_TC);

    k_rowstats_q<<<NQ, 256>>>(q);
    k_prep_c<<<NW, 256>>>(cm, ln2w, ln2b);
    k_s1bb<<<2, 256>>>(w1, ln1w, ln1b, b1);
    k_scal<<<1, 256>>>(ln2w, ln2b);
    k_w2h<<<dim3(16, 16), dim3(32, 8)>>>(w2);
    k_gemm_fold2<<<dim3(33, 8), 256>>>(q, cm, w1, ln1w, pQ1, pC1);
    k_vw2<<<2, 256>>>(w2);
    k_gemm_plain2<<<dim3(33, 8), 256>>>(pQ1, pC1, w2, pQW, pCW);
    k_conv<<<128, 256>>>();
    k_tc5<<<NQ / 2, 256, SMEM_TC>>>(q, b2, ln2w, ln2b, out);
}

// round 9
// speedup vs baseline: 4.6501x; 1.0237x over previous
#include <cuda_runtime.h>
#include <cuda_fp16.h>
#include <math.h>
#include <stdint.h>
#include <cstdint>

#define NQ 2048
#define NW 64
#define DD 512
#define D2 1024
#define TEMP_SC 16.0f
#define LN_EPS 1e-5f

// ---------------- scratch ----------------
__device__ float g_Q1[NQ * DD];
__device__ float g_C1[NW * DD];
__device__ float g_QW[NQ * DD];        // Q1 @ w2
__device__ float g_s1[DD];
__device__ float g_bb[DD];
__device__ float g_s1w[DD];            // s1 @ w2
__device__ float g_bbw[DD];            // bb @ w2
__device__ float g_qsum[NQ];
__device__ float g_qssq[NQ];
__device__ float g_csum[NW];
__device__ float g_cssq[NW];
__device__ float g_chatT[DD * NW];     // [j][w]
__device__ float g_swc[NW];
__device__ float g_sbc[NW];
__device__ float g_scal[3];
__device__ __align__(128) __half g_w2th[DD * DD];  // w2^T [j][k] fp16
__device__ __align__(128) __half g_c1h[NW * DD];   // C1 fp16 [w][j]
__device__ __align__(128) __half g_cwh[DD * NW];   // 0.5*CW^T fp16 [j][w']

#define SWZ(o) ((o) ^ (((o) >> 3) & 0x70))

// ================= helpers =================
__device__ __forceinline__ uint32_t smem_u32(const void* p) {
    uint32_t a;
    asm("{ .reg .u64 t; cvta.to.shared.u64 t, %1; cvt.u32.u64 %0, t; }" : "=r"(a) : "l"(p));
    return a;
}
__device__ __forceinline__ void cp16(uint32_t s, const void* g) {
    asm volatile("cp.async.cg.shared.global [%0], [%1], 16;" :: "r"(s), "l"(g));
}
__device__ __forceinline__ void ldsm4(uint32_t* r, uint32_t a) {
    asm volatile("ldmatrix.sync.aligned.m8n8.x4.shared.b16 {%0,%1,%2,%3}, [%4];"
                 : "=r"(r[0]), "=r"(r[1]), "=r"(r[2]), "=r"(r[3]) : "r"(a));
}
__device__ __forceinline__ void mma16816h(float* d, const uint32_t* a, const uint32_t* b) {
    asm volatile("mma.sync.aligned.m16n8k16.row.col.f32.f16.f16.f32 "
                 "{%0,%1,%2,%3}, {%4,%5,%6,%7}, {%8,%9}, {%0,%1,%2,%3};"
                 : "+f"(d[0]), "+f"(d[1]), "+f"(d[2]), "+f"(d[3])
                 : "r"(a[0]), "r"(a[1]), "r"(a[2]), "r"(a[3]), "r"(b[0]), "r"(b[1]));
}

// ================= phase A =================
// merged stats: blocks [0,2048)=q rowstats; [2048,2112)=class prep; 2112=ln2 scalars
__global__ void k_stats(const float* __restrict__ q, const float* __restrict__ cm,
                        const float* __restrict__ ln2w, const float* __restrict__ ln2b) {
    int b = blockIdx.x, tid = threadIdx.x;
    int lane = tid & 31, wid = tid >> 5;
    if (b < NQ) {
        float s = 0.f, ss = 0.f;
        for (int j = tid; j < DD; j += 256) { float v = q[b * DD + j]; s += v; ss += v * v; }
        __shared__ float sA[8], sB[8];
#pragma unroll
        for (int o = 16; o; o >>= 1) {
            s  += __shfl_down_sync(0xffffffffu, s, o);
            ss += __shfl_down_sync(0xffffffffu, ss, o);
        }
        if (lane == 0) { sA[wid] = s; sB[wid] = ss; }
        __syncthreads();
        if (tid == 0) {
            float a = 0.f, bb = 0.f;
#pragma unroll
            for (int i = 0; i < 8; i++) { a += sA[i]; bb += sB[i]; }
            g_qsum[b] = a; g_qssq[b] = bb;
        }
        return;
    }
    if (b < 2112) {
        int w = b - 2048;
        float s = 0.f, ss = 0.f, sw = 0.f, sb = 0.f;
        for (int j = tid; j < DD; j += 256) {
            float v = cm[w * DD + j];
            s += v; ss += v * v; sw += ln2w[j] * v; sb += ln2b[j] * v;
        }
        __shared__ float sA[8], sB[8], sC[8], sD[8];
        __shared__ float rbc;
#pragma unroll
        for (int o = 16; o; o >>= 1) {
            s  += __shfl_down_sync(0xffffffffu, s,  o);
            ss += __shfl_down_sync(0xffffffffu, ss, o);
            sw += __shfl_down_sync(0xffffffffu, sw, o);
            sb += __shfl_down_sync(0xffffffffu, sb, o);
        }
        if (lane == 0) { sA[wid] = s; sB[wid] = ss; sC[wid] = sw; sD[wid] = sb; }
        __syncthreads();
        if (tid == 0) {
            float a = 0.f, bb = 0.f, c = 0.f, d = 0.f;
#pragma unroll
            for (int i = 0; i < 8; i++) { a += sA[i]; bb += sB[i]; c += sC[i]; d += sD[i]; }
            g_csum[w] = a; g_cssq[w] = bb;
            float r = 1.f / fmaxf(sqrtf(bb), 1e-12f);
            rbc = r; g_swc[w] = r * c; g_sbc[w] = r * d;
        }
        __syncthreads();
        float r = rbc;
        for (int j = tid; j < DD; j += 256)
            g_chatT[j * NW + w] = cm[w * DD + j] * r;
        return;
    }
    {
        float a = 0.f, bb = 0.f, c = 0.f;
        for (int j = tid; j < DD; j += 256) {
            float w = ln2w[j], z = ln2b[j];
            a += w * w; bb += w * z; c += z * z;
        }
        __shared__ float sA[8], sB[8], sC[8];
#pragma unroll
        for (int o = 16; o; o >>= 1) {
            a  += __shfl_down_sync(0xffffffffu, a,  o);
            bb += __shfl_down_sync(0xffffffffu, bb, o);
            c  += __shfl_down_sync(0xffffffffu, c,  o);
        }
        if (lane == 0) { sA[wid] = a; sB[wid] = bb; sC[wid] = c; }
        __syncthreads();
        if (tid == 0) {
            float x = 0.f, y = 0.f, z = 0.f;
#pragma unroll
            for (int i = 0; i < 8; i++) { x += sA[i]; y += sB[i]; z += sC[i]; }
            g_scal[0] = x; g_scal[1] = y; g_scal[2] = z;
        }
    }
}

// column-weighted sums: oa[j] = sum_i va[i]*W[i,j]; ob[j] = (addb?addb[j]:0) + sum_i vb[i]*W[i,j]
__global__ void k_colsum(const float* __restrict__ W, int R,
                         const float* __restrict__ va, const float* __restrict__ vb,
                         const float* __restrict__ addb,
                         float* __restrict__ oa, float* __restrict__ ob) {
    __shared__ float sa[16][17], sbm[16][17];
    int jl = threadIdx.x & 15, ti = threadIdx.x >> 4;
    int j = blockIdx.x * 16 + jl;
    float a = 0.f, b = 0.f;
    for (int i = ti; i < R; i += 16) {
        float wv = W[i * DD + j];
        a += va[i] * wv; b += vb[i] * wv;
    }
    sa[ti][jl] = a; sbm[ti][jl] = b;
    __syncthreads();
    if (ti == 0) {
#pragma unroll
        for (int k = 1; k < 16; k++) { a += sa[k][jl]; b += sbm[k][jl]; }
        oa[j] = a;
        ob[j] = (addb ? addb[j] : 0.f) + b;
    }
}

// w2 transpose to fp16 [j][k]
__global__ void k_w2h(const float* __restrict__ w2) {
    __shared__ float t[32][33];
    int bx = blockIdx.x * 32, by = blockIdx.y * 32;
    int tx = threadIdx.x, ty = threadIdx.y;
#pragma unroll
    for (int i = 0; i < 4; i++)
        t[ty + i * 8][tx] = w2[(by + ty + i * 8) * DD + bx + tx];
    __syncthreads();
#pragma unroll
    for (int i = 0; i < 4; i++) {
        int j = bx + ty + i * 8, k = by + tx;
        g_w2th[j * DD + k] = __float2half(t[tx][ty + i * 8]);
    }
}

// merged fold GEMM: bx<32 -> q-part (Q1), bx==32 -> c-part (C1 fp32 + fp16)
__global__ void k_gemm_fold2(const float* __restrict__ q, const float* __restrict__ cm,
                             const float* __restrict__ w1, const float* __restrict__ lnw,
                             float* __restrict__ Q1, float* __restrict__ C1) {
    __shared__ float As[16][65];
    __shared__ float Bs[16][64];
    int bx = blockIdx.x;
    const float* A; int m0, rowoff;
    if (bx < 32) { A = q; m0 = bx * 64; rowoff = 0; }
    else         { A = cm; m0 = 0; rowoff = 512; }
    int j0 = blockIdx.y * 64;
    int tid = threadIdx.x;
    int tr = tid >> 4, tc = tid & 15;
    int r0 = tr * 4, c0 = tc * 4;
    float acc[4][4] = {};
    for (int kc = 0; kc < DD; kc += 16) {
        __syncthreads();
#pragma unroll
        for (int e = 0; e < 4; e++) {
            int idx = tid + e * 256;
            int m = idx >> 4, kk = idx & 15;
            As[kk][m] = A[(m0 + m) * DD + kc + kk] * lnw[rowoff + kc + kk];
        }
#pragma unroll
        for (int e = 0; e < 4; e++) {
            int idx = tid + e * 256;
            int kk = idx >> 6, j = idx & 63;
            Bs[kk][j] = w1[(rowoff + kc + kk) * DD + j0 + j];
        }
        __syncthreads();
#pragma unroll
        for (int kk = 0; kk < 16; kk++) {
            float a0 = As[kk][r0], a1 = As[kk][r0 + 1], a2 = As[kk][r0 + 2], a3 = As[kk][r0 + 3];
            float b0 = Bs[kk][c0], b1 = Bs[kk][c0 + 1], b2 = Bs[kk][c0 + 2], b3 = Bs[kk][c0 + 3];
            acc[0][0] += a0 * b0; acc[0][1] += a0 * b1; acc[0][2] += a0 * b2; acc[0][3] += a0 * b3;
            acc[1][0] += a1 * b0; acc[1][1] += a1 * b1; acc[1][2] += a1 * b2; acc[1][3] += a1 * b3;
            acc[2][0] += a2 * b0; acc[2][1] += a2 * b1; acc[2][2] += a2 * b2; acc[2][3] += a2 * b3;
            acc[3][0] += a3 * b0; acc[3][1] += a3 * b1; acc[3][2] += a3 * b2; acc[3][3] += a3 * b3;
        }
    }
    if (bx < 32) {
#pragma unroll
        for (int i = 0; i < 4; i++)
#pragma unroll
            for (int j = 0; j < 4; j++)
                Q1[(m0 + r0 + i) * DD + j0 + c0 + j] = acc[i][j];
    } else {
#pragma unroll
        for (int i = 0; i < 4; i++)
#pragma unroll
            for (int j = 0; j < 4; j++) {
                int idx = (r0 + i) * DD + j0 + c0 + j;
                C1[idx] = acc[i][j];
                g_c1h[idx] = __float2half(acc[i][j]);
            }
    }
}

// merged plain GEMM vs w2: bx<32 -> Q1@w2 = QW (fp32); bx==32 -> C1@w2 -> g_cwh (0.5x, fp16, transposed)
__global__ void k_gemm_plain2(const float* __restrict__ Q1, const float* __restrict__ C1,
                              const float* __restrict__ w2, float* __restrict__ QW) {
    __shared__ float As[16][65];
    __shared__ float Bs[16][64];
    int bx = blockIdx.x;
    const float* A; int m0;
    if (bx < 32) { A = Q1; m0 = bx * 64; }
    else         { A = C1; m0 = 0; }
    int j0 = blockIdx.y * 64;
    int tid = threadIdx.x;
    int tr = tid >> 4, tc = tid & 15;
    int r0 = tr * 4, c0 = tc * 4;
    float acc[4][4] = {};
    for (int kc = 0; kc < DD; kc += 16) {
        __syncthreads();
#pragma unroll
        for (int e = 0; e < 4; e++) {
            int idx = tid + e * 256;
            int m = idx >> 4, kk = idx & 15;
            As[kk][m] = A[(m0 + m) * DD + kc + kk];
        }
#pragma unroll
        for (int e = 0; e < 4; e++) {
            int idx = tid + e * 256;
            int kk = idx >> 6, j = idx & 63;
            Bs[kk][j] = w2[(kc + kk) * DD + j0 + j];
        }
        __syncthreads();
#pragma unroll
        for (int kk = 0; kk < 16; kk++) {
            float a0 = As[kk][r0], a1 = As[kk][r0 + 1], a2 = As[kk][r0 + 2], a3 = As[kk][r0 + 3];
            float b0 = Bs[kk][c0], b1 = Bs[kk][c0 + 1], b2 = Bs[kk][c0 + 2], b3 = Bs[kk][c0 + 3];
            acc[0][0] += a0 * b0; acc[0][1] += a0 * b1; acc[0][2] += a0 * b2; acc[0][3] += a0 * b3;
            acc[1][0] += a1 * b0; acc[1][1] += a1 * b1; acc[1][2] += a1 * b2; acc[1][3] += a1 * b3;
            acc[2][0] += a2 * b0; acc[2][1] += a2 * b1; acc[2][2] += a2 * b2; acc[2][3] += a2 * b3;
            acc[3][0] += a3 * b0; acc[3][1] += a3 * b1; acc[3][2] += a3 * b2; acc[3][3] += a3 * b3;
        }
    }
    if (bx < 32) {
#pragma unroll
        for (int i = 0; i < 4; i++)
#pragma unroll
            for (int j = 0; j < 4; j++)
                QW[(m0 + r0 + i) * DD + j0 + c0 + j] = acc[i][j];
    } else {
#pragma unroll
        for (int i = 0; i < 4; i++)
#pragma unroll
            for (int j = 0; j < 4; j++)
                g_cwh[(j0 + c0 + j) * NW + (r0 + i)] = __float2half(0.5f * acc[i][j]);
    }
}

// ================= main HMMA kernel: K=576, build overlapped with MMA =================
#define OFF_A    0          // 9 x 16384 = 147456 (8 residual kc + 1 ext chunk)
#define OFF_B    147456     // 2 x 16384 = 32768
#define OFF_CHAT 180224     // 34816: chat chunk in mainloop; red at end
#define OFF_META 215040
#define M_MU   0
#define M_IV   128
#define M_U1   256
#define M_U2   768    // [2][512]
#define M_U3   1792   // [2][512]
#define M_LW   2816
#define M_LB   3328
#define SMEM_TC 230400

__device__ __forceinline__ void cp_chat(uint32_t sb, int ch, int tid) {
    int j0 = ch * 128;
#pragma unroll
    for (int i = 0; i < 8; i++) {
        int u = tid + i * 256;
        int row = u >> 4, c16 = u & 15;
        cp16(sb + OFF_CHAT + (uint32_t)(row * 272 + c16 * 16),
             (const char*)g_chatT + (size_t)(j0 + row) * 256 + c16 * 16);
    }
}

// load B tile t (t = ch*9 + kc); kc==8 pulls CW ext rows; kc==1 piggybacks chat(ch)
__device__ __forceinline__ void cp_B(uint32_t sb, int t, int tid) {
    int ch = t / 9, kc = t - ch * 9;
    int j0 = ch * 128;
    uint32_t bh = sb + OFF_B + (t & 1) * 16384;
    if (kc < 8) {
        const char* gh = (const char*)g_w2th + (size_t)j0 * 1024 + (size_t)kc * 128;
#pragma unroll
        for (int i = 0; i < 4; i++) {
            int u = tid + i * 256;
            int row = u >> 3, c16 = u & 7;
            uint32_t o = (uint32_t)(row * 128 + c16 * 16);
            cp16(bh + SWZ(o), gh + (size_t)row * 1024 + c16 * 16);
        }
    } else {
        const char* gh = (const char*)g_cwh + (size_t)j0 * 128;
#pragma unroll
        for (int i = 0; i < 4; i++) {
            int u = tid + i * 256;
            int row = u >> 3, c16 = u & 7;
            uint32_t o = (uint32_t)(row * 128 + c16 * 16);
            cp16(bh + SWZ(o), gh + (size_t)row * 128 + c16 * 16);
        }
    }
    if (kc == 1) cp_chat(sb, ch, tid);
    asm volatile("cp.async.commit_group;" ::: "memory");
}

// build residual A subtile kc from L2-resident globals: 0.5*h*erf(h/sqrt2), fp16
__device__ __forceinline__ void buildA(char* smem, int kc, int tid,
                                       const float* meta, int n0) {
    int r = tid >> 1, w = r & 63, rn = r >> 6;
    int kh = (tid & 1) * 32;
    float mu = meta[M_MU + r], iv = meta[M_IV + r];
    const float* Q1p = g_Q1 + (size_t)(n0 + rn) * DD + kc * 64 + kh;
    const float* s1p = g_s1 + kc * 64 + kh;
    const float* bbp = g_bb + kc * 64 + kh;
    const __half* c1p = g_c1h + (size_t)w * DD + kc * 64 + kh;
    char* ah = smem + OFF_A + kc * 16384;
#pragma unroll
    for (int kk = 0; kk < 32; kk += 2) {
        float2 qv = *(const float2*)(Q1p + kk);
        float2 sv = *(const float2*)(s1p + kk);
        float2 bv = *(const float2*)(bbp + kk);
        float2 cf = __half22float2(*(const __half2*)(c1p + kk));
        float ha = iv * (qv.x + cf.x - mu * sv.x) + bv.x;
        float hb = iv * (qv.y + cf.y - mu * sv.y) + bv.y;
        float ga = 0.5f * ha * erff(ha * 0.70710678118654752f);
        float gb = 0.5f * hb * erff(hb * 0.70710678118654752f);
        __half2 hp = __floats2half2_rn(ga, gb);
        uint32_t o = (uint32_t)(r * 128 + (kh + kk) * 2);
        *(__half2*)(ah + SWZ(o)) = hp;
    }
}

__global__ void __launch_bounds__(256, 1)
k_tc6(const float* __restrict__ q, const float* __restrict__ b2,
      const float* __restrict__ ln2w, const float* __restrict__ ln2b,
      float* __restrict__ out) {
    extern __shared__ char smem[];
    const uint32_t sb = smem_u32(smem);
    const int tid = threadIdx.x, lane = tid & 31, wid = tid >> 5;
    const int pair = blockIdx.x;
    const int n0 = pair * 2;
    float* meta = (float*)(smem + OFF_META);
    float* chs = (float*)(smem + OFF_CHAT);

    // ---- prologue: meta ----
    for (int j = tid; j < DD; j += 256) {
        meta[M_U1 + j] = 0.5f * g_s1w[j];
        meta[M_U2 + j]       = 0.5f * g_QW[n0 * DD + j];
        meta[M_U2 + 512 + j] = 0.5f * g_QW[(n0 + 1) * DD + j];
        float hb = b2[j] + 0.5f * g_bbw[j];
        meta[M_U3 + j]       = q[n0 * DD + j] + hb;
        meta[M_U3 + 512 + j] = q[(n0 + 1) * DD + j] + hb;
        meta[M_LW + j] = ln2w[j];
        meta[M_LB + j] = ln2b[j];
    }
    if (tid < 128) {
        int rn = tid >> 6, w = tid & 63;
        float sx  = g_qsum[n0 + rn] + g_csum[w];
        float sxx = g_qssq[n0 + rn] + g_cssq[w];
        float m = sx * (1.f / 1024.f);
        float var = sxx * (1.f / 1024.f) - m * m;
        meta[M_MU + tid] = m;
        meta[M_IV + tid] = rsqrtf(var + LN_EPS);
    }
    __syncthreads();

    // ---- ext chunk (kc=8): zero then scatter ivr at col w(row) ----
    {
        char* ext = smem + OFF_A + 8 * 16384;
#pragma unroll
        for (int i = 0; i < 4; i++)
            *(float4*)(ext + tid * 16 + i * 4096) = make_float4(0.f, 0.f, 0.f, 0.f);
        __syncthreads();
        if (tid < 128) {
            int row = tid, w = row & 63;
            uint32_t o = (uint32_t)(row * 128 + w * 2);
            *(__half*)(ext + SWZ(o)) = __float2half(meta[M_IV + row]);
        }
    }

    // ---- build A[0]; stage B tile 0 ----
    buildA(smem, 0, tid, meta, n0);
    cp_B(sb, 0, tid);
    __syncthreads();

    // ---- mainloop: 4 chunks x 9 kc; build A[1..7] overlapped with chunk-0 MMAs ----
    const int wm = wid & 3, wn = wid >> 2;
    const int arow = ((lane >> 3) & 1) * 8 + (lane & 7);
    const int acol = lane >> 4;
    const int brow = (lane >> 4) * 8 + (lane & 7);
    const int bcol = (lane >> 3) & 1;
    const int qr = lane >> 2, qc = lane & 3;

    float d[16][4];
#pragma unroll
    for (int i = 0; i < 16; i++)
#pragma unroll
        for (int j = 0; j < 4; j++) d[i][j] = 0.f;
    float pm[4][6];
#pragma unroll
    for (int i = 0; i < 4; i++)
#pragma unroll
        for (int m = 0; m < 6; m++) pm[i][m] = 0.f;

    for (int t = 0; t < 36; t++) {
        const int ch = t / 9, kc = t - ch * 9;
        if (t < 35) cp_B(sb, t + 1, tid);
        if (t < 35) { asm volatile("cp.async.wait_group 1;" ::: "memory"); }
        else        { asm volatile("cp.async.wait_group 0;" ::: "memory"); }
        __syncthreads();
        uint32_t Ah = sb + OFF_A + kc * 16384;
        uint32_t Bh = sb + OFF_B + (t & 1) * 16384;
#pragma unroll
        for (int s = 0; s < 4; s++) {
            uint32_t ahi[2][4], bhi[4][4];
#pragma unroll
            for (int tm = 0; tm < 2; tm++) {
                uint32_t o = (uint32_t)((32 * wm + 16 * tm + arow) * 128 + (2 * s + acol) * 16);
                ldsm4(ahi[tm], Ah + SWZ(o));
            }
#pragma unroll
            for (int u = 0; u < 4; u++) {
                uint32_t o = (uint32_t)((64 * wn + 16 * u + brow) * 128 + (2 * s + bcol) * 16);
                ldsm4(bhi[u], Bh + SWZ(o));
            }
#pragma unroll
            for (int tm = 0; tm < 2; tm++)
#pragma unroll
                for (int u = 0; u < 4; u++) {
                    mma16816h(d[tm * 8 + 2 * u],     ahi[tm], &bhi[u][0]);
                    mma16816h(d[tm * 8 + 2 * u + 1], ahi[tm], &bhi[u][2]);
                }
        }
        // overlap: gelu-build of next A subtile issues while tensor pipe drains
        if (ch == 0 && kc < 7) buildA(smem, kc + 1, tid, meta, n0);
        __syncthreads();

        if (kc == 8) {
            const int j0 = ch * 128;
#pragma unroll
            for (int tm = 0; tm < 2; tm++)
#pragma unroll
                for (int h = 0; h < 2; h++) {
                    int row = 32 * wm + 16 * tm + 8 * h + qr;
                    int w = row & 63, rn = row >> 6;
                    float ivr = meta[M_IV + row];
                    float a = -ivr * meta[M_MU + row];
                    float p0 = 0.f, p1 = 0.f, pA = 0.f, pB = 0.f, pC = 0.f, pE = 0.f;
#pragma unroll
                    for (int nt = 0; nt < 8; nt++) {
                        int cl0 = 64 * wn + 8 * nt + qc * 2;
                        int col0 = j0 + cl0;
                        float2 U1 = *(const float2*)&meta[M_U1 + col0];
                        float2 U2 = *(const float2*)&meta[M_U2 + rn * 512 + col0];
                        float2 U3 = *(const float2*)&meta[M_U3 + rn * 512 + col0];
                        float2 LWv = *(const float2*)&meta[M_LW + col0];
                        float2 LBv = *(const float2*)&meta[M_LB + col0];
                        float ch0 = chs[cl0 * 68 + w];
                        float ch1 = chs[(cl0 + 1) * 68 + w];
                        float v0 = d[tm * 8 + nt][h * 2]     + a * U1.x + ivr * U2.x + U3.x;
                        float v1 = d[tm * 8 + nt][h * 2 + 1] + a * U1.y + ivr * U2.y + U3.y;
                        float vw0 = v0 * LWv.x, vw1 = v1 * LWv.y;
                        p0 += v0 + v1;
                        p1 += v0 * v0 + v1 * v1;
                        pA += vw0 * ch0 + vw1 * ch1;
                        pB += vw0 * vw0 + vw1 * vw1;
                        pC += vw0 * LWv.x + vw1 * LWv.y;
                        pE += vw0 * LBv.x + vw1 * LBv.y;
                    }
                    int i = tm * 2 + h;
                    pm[i][0] += p0; pm[i][1] += p1; pm[i][2] += pA;
                    pm[i][3] += pB; pm[i][4] += pC; pm[i][5] += pE;
                }
            if (t < 35) {
#pragma unroll
                for (int i = 0; i < 16; i++)
#pragma unroll
                    for (int j = 0; j < 4; j++) d[i][j] = 0.f;
            }
        }
    }

    // ---- final reduce (red aliases CHAT region) ----
    __syncthreads();
    float* sred = (float*)(smem + OFF_CHAT);
#pragma unroll
    for (int tm = 0; tm < 2; tm++)
#pragma unroll
        for (int h = 0; h < 2; h++) {
            int i = tm * 2 + h;
            int row = 32 * wm + 16 * tm + 8 * h + qr;
#pragma unroll
            for (int o = 1; o <= 2; o <<= 1)
#pragma unroll
                for (int m = 0; m < 6; m++)
                    pm[i][m] += __shfl_down_sync(0xffffffffu, pm[i][m], o, 4);
            if (qc == 0) {
                float* rp = sred + (wn * 128 + row) * 8;
#pragma unroll
                for (int m = 0; m < 6; m++) rp[m] = pm[i][m];
            }
        }
    __syncthreads();
    if (tid < 128) {
        int row = tid, w = row & 63, nn = n0 + (row >> 6);
        float m0 = sred[row * 8 + 0] + sred[(128 + row) * 8 + 0];
        float m1 = sred[row * 8 + 1] + sred[(128 + row) * 8 + 1];
        float A  = sred[row * 8 + 2] + sred[(128 + row) * 8 + 2];
        float B  = sred[row * 8 + 3] + sred[(128 + row) * 8 + 3];
        float C  = sred[row * 8 + 4] + sred[(128 + row) * 8 + 4];
        float E  = sred[row * 8 + 5] + sred[(128 + row) * 8 + 5];
        float mu2 = m0 * (1.f / DD);
        float var = m1 * (1.f / DD) - mu2 * mu2;
        float k = rsqrtf(var + LN_EPS);
        float sww = g_scal[0], swb = g_scal[1], sbb = g_scal[2];
        float doty = k * (A - mu2 * g_swc[w]) + g_sbc[w];
        float ny2 = k * k * (B - 2.f * mu2 * C + mu2 * mu2 * sww)
                  + 2.f * k * (E - mu2 * swb) + sbb;
        float ny = sqrtf(fmaxf(ny2, 0.f));
        out[nn * NW + w] = TEMP_SC * doty / fmaxf(ny, 1e-12f);
    }
}

// ================= launch =================
extern "C" void kernel_launch(void* const* d_in, const int* in_sizes, int n_in,
                              void* d_out, int out_size) {
    const float* q    = (const float*)d_in[0];
    const float* cm   = (const float*)d_in[1];
    const float* ln1w = (const float*)d_in[2];
    const float* ln1b = (const float*)d_in[3];
    const float* w1   = (const float*)d_in[4];
    const float* b1   = (const float*)d_in[5];
    const float* w2   = (const float*)d_in[6];
    const float* b2   = (const float*)d_in[7];
    const float* ln2w = (const float*)d_in[8];
    const float* ln2b = (const float*)d_in[9];
    float* out = (float*)d_out;

    float *pQ1, *pC1, *pQW, *pS1, *pBB, *pS1W, *pBBW;
    cudaGetSymbolAddress((void**)&pQ1, g_Q1);
    cudaGetSymbolAddress((void**)&pC1, g_C1);
    cudaGetSymbolAddress((void**)&pQW, g_QW);
    cudaGetSymbolAddress((void**)&pS1, g_s1);
    cudaGetSymbolAddress((void**)&pBB, g_bb);
    cudaGetSymbolAddress((void**)&pS1W, g_s1w);
    cudaGetSymbolAddress((void**)&pBBW, g_bbw);

    cudaFuncSetAttribute(k_tc6, cudaFuncAttributeMaxDynamicSharedMemorySize, SMEM_TC);

    k_stats<<<2113, 256>>>(q, cm, ln2w, ln2b);
    k_w2h<<<dim3(16, 16), dim3(32, 8)>>>(w2);
    k_colsum<<<32, 256>>>(w1, D2, ln1w, ln1b, b1, pS1, pBB);
    k_gemm_fold2<<<dim3(33, 8), 256>>>(q, cm, w1, ln1w, pQ1, pC1);
    k_colsum<<<32, 256>>>(w2, DD, pS1, pBB, (const float*)nullptr, pS1W, pBBW);
    k_gemm_plain2<<<dim3(33, 8), 256>>>(pQ1, pC1, w2, pQW);
    k_tc6<<<NQ / 2, 256, SMEM_TC>>>(q, b2, ln2w, ln2b, out);
}

// round 11
// speedup vs baseline: 4.8316x; 1.0390x over previous
#include <cuda_runtime.h>
#include <cuda_fp16.h>
#include <math.h>
#include <stdint.h>
#include <cstdint>

#define NQ 2048
#define NW 64
#define DD 512
#define D2 1024
#define TEMP_SC 16.0f
#define LN_EPS 1e-5f

// ---------------- scratch ----------------
__device__ float g_Q1[NQ * DD];
__device__ float g_C1[NW * DD];
__device__ float g_QW[NQ * DD];        // Q1 @ w2
__device__ float g_s1[DD];
__device__ float g_bb[DD];
__device__ float g_s1w[DD];            // s1 @ w2
__device__ float g_bbw[DD];            // bb @ w2
__device__ float g_qsum[NQ];
__device__ float g_qssq[NQ];
__device__ float g_csum[NW];
__device__ float g_cssq[NW];
__device__ float g_chatT[DD * NW];     // [j][w]
__device__ float g_swc[NW];
__device__ float g_sbc[NW];
__device__ float g_scal[3];
__device__ __align__(128) __half g_w2th[DD * DD];  // w2^T [j][k] fp16
__device__ __align__(128) __half g_c1h[NW * DD];   // C1 fp16 [w][j]
__device__ __align__(128) __half g_cwh[DD * NW];   // 0.5*CW^T fp16 [j][w']

#define SWZ(o) ((o) ^ (((o) >> 3) & 0x70))

// ================= helpers =================
__device__ __forceinline__ uint32_t smem_u32(const void* p) {
    uint32_t a;
    asm("{ .reg .u64 t; cvta.to.shared.u64 t, %1; cvt.u32.u64 %0, t; }" : "=r"(a) : "l"(p));
    return a;
}
__device__ __forceinline__ void cp16(uint32_t s, const void* g) {
    asm volatile("cp.async.cg.shared.global [%0], [%1], 16;" :: "r"(s), "l"(g));
}
__device__ __forceinline__ void ldsm4(uint32_t* r, uint32_t a) {
    asm volatile("ldmatrix.sync.aligned.m8n8.x4.shared.b16 {%0,%1,%2,%3}, [%4];"
                 : "=r"(r[0]), "=r"(r[1]), "=r"(r[2]), "=r"(r[3]) : "r"(a));
}
__device__ __forceinline__ void mma16816h(float* d, const uint32_t* a, const uint32_t* b) {
    asm volatile("mma.sync.aligned.m16n8k16.row.col.f32.f16.f16.f32 "
                 "{%0,%1,%2,%3}, {%4,%5,%6,%7}, {%8,%9}, {%0,%1,%2,%3};"
                 : "+f"(d[0]), "+f"(d[1]), "+f"(d[2]), "+f"(d[3])
                 : "r"(a[0]), "r"(a[1]), "r"(a[2]), "r"(a[3]), "r"(b[0]), "r"(b[1]));
}

// ================= phase A =================
// merged stats: blocks [0,2048)=q rowstats; [2048,2112)=class prep; 2112=ln2 scalars
__global__ void k_stats(const float* __restrict__ q, const float* __restrict__ cm,
                        const float* __restrict__ ln2w, const float* __restrict__ ln2b) {
    int b = blockIdx.x, tid = threadIdx.x;
    int lane = tid & 31, wid = tid >> 5;
    if (b < NQ) {
        float s = 0.f, ss = 0.f;
        for (int j = tid; j < DD; j += 256) { float v = q[b * DD + j]; s += v; ss += v * v; }
        __shared__ float sA[8], sB[8];
#pragma unroll
        for (int o = 16; o; o >>= 1) {
            s  += __shfl_down_sync(0xffffffffu, s, o);
            ss += __shfl_down_sync(0xffffffffu, ss, o);
        }
        if (lane == 0) { sA[wid] = s; sB[wid] = ss; }
        __syncthreads();
        if (tid == 0) {
            float a = 0.f, bb = 0.f;
#pragma unroll
            for (int i = 0; i < 8; i++) { a += sA[i]; bb += sB[i]; }
            g_qsum[b] = a; g_qssq[b] = bb;
        }
        return;
    }
    if (b < 2112) {
        int w = b - 2048;
        float s = 0.f, ss = 0.f, sw = 0.f, sb = 0.f;
        for (int j = tid; j < DD; j += 256) {
            float v = cm[w * DD + j];
            s += v; ss += v * v; sw += ln2w[j] * v; sb += ln2b[j] * v;
        }
        __shared__ float sA[8], sB[8], sC[8], sD[8];
        __shared__ float rbc;
#pragma unroll
        for (int o = 16; o; o >>= 1) {
            s  += __shfl_down_sync(0xffffffffu, s,  o);
            ss += __shfl_down_sync(0xffffffffu, ss, o);
            sw += __shfl_down_sync(0xffffffffu, sw, o);
            sb += __shfl_down_sync(0xffffffffu, sb, o);
        }
        if (lane == 0) { sA[wid] = s; sB[wid] = ss; sC[wid] = sw; sD[wid] = sb; }
        __syncthreads();
        if (tid == 0) {
            float a = 0.f, bb = 0.f, c = 0.f, d = 0.f;
#pragma unroll
            for (int i = 0; i < 8; i++) { a += sA[i]; bb += sB[i]; c += sC[i]; d += sD[i]; }
            g_csum[w] = a; g_cssq[w] = bb;
            float r = 1.f / fmaxf(sqrtf(bb), 1e-12f);
            rbc = r; g_swc[w] = r * c; g_sbc[w] = r * d;
        }
        __syncthreads();
        float r = rbc;
        for (int j = tid; j < DD; j += 256)
            g_chatT[j * NW + w] = cm[w * DD + j] * r;
        return;
    }
    {
        float a = 0.f, bb = 0.f, c = 0.f;
        for (int j = tid; j < DD; j += 256) {
            float w = ln2w[j], z = ln2b[j];
            a += w * w; bb += w * z; c += z * z;
        }
        __shared__ float sA[8], sB[8], sC[8];
#pragma unroll
        for (int o = 16; o; o >>= 1) {
            a  += __shfl_down_sync(0xffffffffu, a,  o);
            bb += __shfl_down_sync(0xffffffffu, bb, o);
            c  += __shfl_down_sync(0xffffffffu, c,  o);
        }
        if (lane == 0) { sA[wid] = a; sB[wid] = bb; sC[wid] = c; }
        __syncthreads();
        if (tid == 0) {
            float x = 0.f, y = 0.f, z = 0.f;
#pragma unroll
            for (int i = 0; i < 8; i++) { x += sA[i]; y += sB[i]; z += sC[i]; }
            g_scal[0] = x; g_scal[1] = y; g_scal[2] = z;
        }
    }
}

// column-weighted sums
__global__ void k_colsum(const float* __restrict__ W, int R,
                         const float* __restrict__ va, const float* __restrict__ vb,
                         const float* __restrict__ addb,
                         float* __restrict__ oa, float* __restrict__ ob) {
    __shared__ float sa[16][17], sbm[16][17];
    int jl = threadIdx.x & 15, ti = threadIdx.x >> 4;
    int j = blockIdx.x * 16 + jl;
    float a = 0.f, b = 0.f;
    for (int i = ti; i < R; i += 16) {
        float wv = W[i * DD + j];
        a += va[i] * wv; b += vb[i] * wv;
    }
    sa[ti][jl] = a; sbm[ti][jl] = b;
    __syncthreads();
    if (ti == 0) {
#pragma unroll
        for (int k = 1; k < 16; k++) { a += sa[k][jl]; b += sbm[k][jl]; }
        oa[j] = a;
        ob[j] = (addb ? addb[j] : 0.f) + b;
    }
}

// w2 transpose to fp16 [j][k]
__global__ void k_w2h(const float* __restrict__ w2) {
    __shared__ float t[32][33];
    int bx = blockIdx.x * 32, by = blockIdx.y * 32;
    int tx = threadIdx.x, ty = threadIdx.y;
#pragma unroll
    for (int i = 0; i < 4; i++)
        t[ty + i * 8][tx] = w2[(by + ty + i * 8) * DD + bx + tx];
    __syncthreads();
#pragma unroll
    for (int i = 0; i < 4; i++) {
        int j = bx + ty + i * 8, k = by + tx;
        g_w2th[j * DD + k] = __float2half(t[tx][ty + i * 8]);
    }
}

// merged fold GEMM (float4 smem reads): bx<32 -> Q1; bx==32 -> C1 fp32+fp16
__global__ void k_gemm_fold2(const float* __restrict__ q, const float* __restrict__ cm,
                             const float* __restrict__ w1, const float* __restrict__ lnw,
                             float* __restrict__ Q1, float* __restrict__ C1) {
    __shared__ __align__(16) float As[16][68];
    __shared__ __align__(16) float Bs[16][64];
    int bx = blockIdx.x;
    const float* A; int m0, rowoff;
    if (bx < 32) { A = q; m0 = bx * 64; rowoff = 0; }
    else         { A = cm; m0 = 0; rowoff = 512; }
    int j0 = blockIdx.y * 64;
    int tid = threadIdx.x;
    int tr = tid >> 4, tc = tid & 15;
    int r0 = tr * 4, c0 = tc * 4;
    float acc[4][4] = {};
    for (int kc = 0; kc < DD; kc += 16) {
        __syncthreads();
#pragma unroll
        for (int e = 0; e < 4; e++) {
            int idx = tid + e * 256;
            int m = idx >> 4, kk = idx & 15;
            As[kk][m] = A[(m0 + m) * DD + kc + kk] * lnw[rowoff + kc + kk];
        }
#pragma unroll
        for (int e = 0; e < 4; e++) {
            int idx = tid + e * 256;
            int kk = idx >> 6, j = idx & 63;
            Bs[kk][j] = w1[(rowoff + kc + kk) * DD + j0 + j];
        }
        __syncthreads();
#pragma unroll
        for (int kk = 0; kk < 16; kk++) {
            float4 av = *(const float4*)&As[kk][r0];
            float4 bv = *(const float4*)&Bs[kk][c0];
            acc[0][0] += av.x * bv.x; acc[0][1] += av.x * bv.y; acc[0][2] += av.x * bv.z; acc[0][3] += av.x * bv.w;
            acc[1][0] += av.y * bv.x; acc[1][1] += av.y * bv.y; acc[1][2] += av.y * bv.z; acc[1][3] += av.y * bv.w;
            acc[2][0] += av.z * bv.x; acc[2][1] += av.z * bv.y; acc[2][2] += av.z * bv.z; acc[2][3] += av.z * bv.w;
            acc[3][0] += av.w * bv.x; acc[3][1] += av.w * bv.y; acc[3][2] += av.w * bv.z; acc[3][3] += av.w * bv.w;
        }
    }
    if (bx < 32) {
#pragma unroll
        for (int i = 0; i < 4; i++)
#pragma unroll
            for (int j = 0; j < 4; j++)
                Q1[(m0 + r0 + i) * DD + j0 + c0 + j] = acc[i][j];
    } else {
#pragma unroll
        for (int i = 0; i < 4; i++)
#pragma unroll
            for (int j = 0; j < 4; j++) {
                int idx = (r0 + i) * DD + j0 + c0 + j;
                C1[idx] = acc[i][j];
                g_c1h[idx] = __float2half(acc[i][j]);
            }
    }
}

// merged plain GEMM vs w2 (float4 smem reads): bx<32 -> QW; bx==32 -> g_cwh (0.5x, transposed)
__global__ void k_gemm_plain2(const float* __restrict__ Q1, const float* __restrict__ C1,
                              const float* __restrict__ w2, float* __restrict__ QW) {
    __shared__ __align__(16) float As[16][68];
    __shared__ __align__(16) float Bs[16][64];
    int bx = blockIdx.x;
    const float* A; int m0;
    if (bx < 32) { A = Q1; m0 = bx * 64; }
    else         { A = C1; m0 = 0; }
    int j0 = blockIdx.y * 64;
    int tid = threadIdx.x;
    int tr = tid >> 4, tc = tid & 15;
    int r0 = tr * 4, c0 = tc * 4;
    float acc[4][4] = {};
    for (int kc = 0; kc < DD; kc += 16) {
        __syncthreads();
#pragma unroll
        for (int e = 0; e < 4; e++) {
            int idx = tid + e * 256;
            int m = idx >> 4, kk = idx & 15;
            As[kk][m] = A[(m0 + m) * DD + kc + kk];
        }
#pragma unroll
        for (int e = 0; e < 4; e++) {
            int idx = tid + e * 256;
            int kk = idx >> 6, j = idx & 63;
            Bs[kk][j] = w2[(kc + kk) * DD + j0 + j];
        }
        __syncthreads();
#pragma unroll
        for (int kk = 0; kk < 16; kk++) {
            float4 av = *(const float4*)&As[kk][r0];
            float4 bv = *(const float4*)&Bs[kk][c0];
            acc[0][0] += av.x * bv.x; acc[0][1] += av.x * bv.y; acc[0][2] += av.x * bv.z; acc[0][3] += av.x * bv.w;
            acc[1][0] += av.y * bv.x; acc[1][1] += av.y * bv.y; acc[1][2] += av.y * bv.z; acc[1][3] += av.y * bv.w;
            acc[2][0] += av.z * bv.x; acc[2][1] += av.z * bv.y; acc[2][2] += av.z * bv.z; acc[2][3] += av.z * bv.w;
            acc[3][0] += av.w * bv.x; acc[3][1] += av.w * bv.y; acc[3][2] += av.w * bv.z; acc[3][3] += av.w * bv.w;
        }
    }
    if (bx < 32) {
#pragma unroll
        for (int i = 0; i < 4; i++)
#pragma unroll
            for (int j = 0; j < 4; j++)
                QW[(m0 + r0 + i) * DD + j0 + c0 + j] = acc[i][j];
    } else {
#pragma unroll
        for (int i = 0; i < 4; i++)
#pragma unroll
            for (int j = 0; j < 4; j++)
                g_cwh[(j0 + c0 + j) * NW + (r0 + i)] = __float2half(0.5f * acc[i][j]);
    }
}

// ================= main HMMA kernel: K=512, CW in epilogue, build overlapped =================
#define OFF_A    0          // 8 x 16384 = 131072
#define OFF_B    131072     // 2 x 16384 = 32768
#define OFF_CHAT 163840     // 34816: chat chunk (stride 272B); red at end
#define OFF_CWH  198656     // 18432: cwh chunk (fp16, stride 144B = 72 halves)
#define OFF_META 217088
#define M_MU   0
#define M_IV   128
#define M_U1   256
#define M_U2   768    // [2][512]
#define M_U3   1792   // [2][512]
#define M_LW   2816
#define M_LB   3328   // +512 -> 3840 floats = 15360 B
#define SMEM_TC 232448   // == 227 KB opt-in cap

__device__ __forceinline__ void cp_chat(uint32_t sb, int ch, int tid) {
    int j0 = ch * 128;
#pragma unroll
    for (int i = 0; i < 8; i++) {
        int u = tid + i * 256;
        int row = u >> 4, c16 = u & 15;
        cp16(sb + OFF_CHAT + (uint32_t)(row * 272 + c16 * 16),
             (const char*)g_chatT + (size_t)(j0 + row) * 256 + c16 * 16);
    }
    // cwh: 128 rows x 128 B, smem stride 144 B (16-aligned)
#pragma unroll
    for (int i = 0; i < 4; i++) {
        int u = tid + i * 256;
        int row = u >> 3, c16 = u & 7;
        cp16(sb + OFF_CWH + (uint32_t)(row * 144 + c16 * 16),
             (const char*)g_cwh + (size_t)(j0 + row) * 128 + c16 * 16);
    }
}

// load B tile t (t = ch*8 + kc); kc==1 piggybacks chat+cwh(ch)
__device__ __forceinline__ void cp_B(uint32_t sb, int t, int tid) {
    int ch = t >> 3, kc = t & 7;
    int j0 = ch * 128;
    uint32_t bh = sb + OFF_B + (t & 1) * 16384;
    const char* gh = (const char*)g_w2th + (size_t)j0 * 1024 + (size_t)kc * 128;
#pragma unroll
    for (int i = 0; i < 4; i++) {
        int u = tid + i * 256;
        int row = u >> 3, c16 = u & 7;
        uint32_t o = (uint32_t)(row * 128 + c16 * 16);
        cp16(bh + SWZ(o), gh + (size_t)row * 1024 + c16 * 16);
    }
    if (kc == 1) cp_chat(sb, ch, tid);
    asm volatile("cp.async.commit_group;" ::: "memory");
}

// build residual A subtile kc from L2-resident globals: 0.5*h*erf(h/sqrt2), fp16
__device__ __forceinline__ void buildA(char* smem, int kc, int tid,
                                       const float* meta, int n0) {
    int r = tid >> 1, w = r & 63, rn = r >> 6;
    int kh = (tid & 1) * 32;
    float mu = meta[M_MU + r], iv = meta[M_IV + r];
    const float* Q1p = g_Q1 + (size_t)(n0 + rn) * DD + kc * 64 + kh;
    const float* s1p = g_s1 + kc * 64 + kh;
    const float* bbp = g_bb + kc * 64 + kh;
    const __half* c1p = g_c1h + (size_t)w * DD + kc * 64 + kh;
    char* ah = smem + OFF_A + kc * 16384;
#pragma unroll
    for (int kk = 0; kk < 32; kk += 2) {
        float2 qv = *(const float2*)(Q1p + kk);
        float2 sv = *(const float2*)(s1p + kk);
        float2 bv = *(const float2*)(bbp + kk);
        float2 cf = __half22float2(*(const __half2*)(c1p + kk));
        float ha = iv * (qv.x + cf.x - mu * sv.x) + bv.x;
        float hb = iv * (qv.y + cf.y - mu * sv.y) + bv.y;
        float ga = 0.5f * ha * erff(ha * 0.70710678118654752f);
        float gb = 0.5f * hb * erff(hb * 0.70710678118654752f);
        __half2 hp = __floats2half2_rn(ga, gb);
        uint32_t o = (uint32_t)(r * 128 + (kh + kk) * 2);
        *(__half2*)(ah + SWZ(o)) = hp;
    }
}

__global__ void __launch_bounds__(256, 1)
k_tc7(const float* __restrict__ q, const float* __restrict__ b2,
      const float* __restrict__ ln2w, const float* __restrict__ ln2b,
      float* __restrict__ out) {
    extern __shared__ char smem[];
    const uint32_t sb = smem_u32(smem);
    const int tid = threadIdx.x, lane = tid & 31, wid = tid >> 5;
    const int pair = blockIdx.x;
    const int n0 = pair * 2;
    float* meta = (float*)(smem + OFF_META);
    float* chs = (float*)(smem + OFF_CHAT);
    const __half* cwhs = (const __half*)(smem + OFF_CWH);

    // ---- prologue: meta ----
    for (int j = tid; j < DD; j += 256) {
        meta[M_U1 + j] = 0.5f * g_s1w[j];
        meta[M_U2 + j]       = 0.5f * g_QW[n0 * DD + j];
        meta[M_U2 + 512 + j] = 0.5f * g_QW[(n0 + 1) * DD + j];
        float hb = b2[j] + 0.5f * g_bbw[j];
        meta[M_U3 + j]       = q[n0 * DD + j] + hb;
        meta[M_U3 + 512 + j] = q[(n0 + 1) * DD + j] + hb;
        meta[M_LW + j] = ln2w[j];
        meta[M_LB + j] = ln2b[j];
    }
    if (tid < 128) {
        int rn = tid >> 6, w = tid & 63;
        float sx  = g_qsum[n0 + rn] + g_csum[w];
        float sxx = g_qssq[n0 + rn] + g_cssq[w];
        float m = sx * (1.f / 1024.f);
        float var = sxx * (1.f / 1024.f) - m * m;
        meta[M_MU + tid] = m;
        meta[M_IV + tid] = rsqrtf(var + LN_EPS);
    }
    __syncthreads();

    // ---- build A[0]; stage chat/cwh(0) + B tile 0 ----
    buildA(smem, 0, tid, meta, n0);
    cp_chat(sb, 0, tid);
    cp_B(sb, 0, tid);
    __syncthreads();

    // ---- mainloop: 4 chunks x 8 kc ----
    const int wm = wid & 3, wn = wid >> 2;
    const int arow = ((lane >> 3) & 1) * 8 + (lane & 7);
    const int acol = lane >> 4;
    const int brow = (lane >> 4) * 8 + (lane & 7);
    const int bcol = (lane >> 3) & 1;
    const int qr = lane >> 2, qc = lane & 3;

    float d[16][4];
#pragma unroll
    for (int i = 0; i < 16; i++)
#pragma unroll
        for (int j = 0; j < 4; j++) d[i][j] = 0.f;
    float pm[4][6];
#pragma unroll
    for (int i = 0; i < 4; i++)
#pragma unroll
        for (int m = 0; m < 6; m++) pm[i][m] = 0.f;

    for (int t = 0; t < 32; t++) {
        const int ch = t >> 3, kc = t & 7;
        if (t < 31) cp_B(sb, t + 1, tid);
        if (t < 31) { asm volatile("cp.async.wait_group 1;" ::: "memory"); }
        else        { asm volatile("cp.async.wait_group 0;" ::: "memory"); }
        __syncthreads();
        uint32_t Ah = sb + OFF_A + kc * 16384;
        uint32_t Bh = sb + OFF_B + (t & 1) * 16384;
#pragma unroll
        for (int s = 0; s < 4; s++) {
            uint32_t ahi[2][4], bhi[4][4];
#pragma unroll
            for (int tm = 0; tm < 2; tm++) {
                uint32_t o = (uint32_t)((32 * wm + 16 * tm + arow) * 128 + (2 * s + acol) * 16);
                ldsm4(ahi[tm], Ah + SWZ(o));
            }
#pragma unroll
            for (int u = 0; u < 4; u++) {
                uint32_t o = (uint32_t)((64 * wn + 16 * u + brow) * 128 + (2 * s + bcol) * 16);
                ldsm4(bhi[u], Bh + SWZ(o));
            }
#pragma unroll
            for (int tm = 0; tm < 2; tm++)
#pragma unroll
                for (int u = 0; u < 4; u++) {
                    mma16816h(d[tm * 8 + 2 * u],     ahi[tm], &bhi[u][0]);
                    mma16816h(d[tm * 8 + 2 * u + 1], ahi[tm], &bhi[u][2]);
                }
        }
        // overlap: gelu-build of next A subtile while tensor pipe drains
        if (ch == 0 && kc < 7) buildA(smem, kc + 1, tid, meta, n0);
        __syncthreads();

        if (kc == 7) {
            const int j0 = ch * 128;
#pragma unroll
            for (int tm = 0; tm < 2; tm++)
#pragma unroll
                for (int h = 0; h < 2; h++) {
                    int row = 32 * wm + 16 * tm + 8 * h + qr;
                    int w = row & 63, rn = row >> 6;
                    float ivr = meta[M_IV + row];
                    float a = -ivr * meta[M_MU + row];
                    float p0 = 0.f, p1 = 0.f, pA = 0.f, pB = 0.f, pC = 0.f, pE = 0.f;
#pragma unroll
                    for (int nt = 0; nt < 8; nt++) {
                        int cl0 = 64 * wn + 8 * nt + qc * 2;
                        int col0 = j0 + cl0;
                        float2 U1 = *(const float2*)&meta[M_U1 + col0];
                        float2 U2 = *(const float2*)&meta[M_U2 + rn * 512 + col0];
                        float2 U3 = *(const float2*)&meta[M_U3 + rn * 512 + col0];
                        float2 LWv = *(const float2*)&meta[M_LW + col0];
                        float2 LBv = *(const float2*)&meta[M_LB + col0];
                        float ch0 = chs[cl0 * 68 + w];
                        float ch1 = chs[(cl0 + 1) * 68 + w];
                        float cw0 = __half2float(cwhs[cl0 * 72 + w]);
                        float cw1 = __half2float(cwhs[(cl0 + 1) * 72 + w]);
                        float v0 = d[tm * 8 + nt][h * 2]     + a * U1.x + ivr * (U2.x + cw0) + U3.x;
                        float v1 = d[tm * 8 + nt][h * 2 + 1] + a * U1.y + ivr * (U2.y + cw1) + U3.y;
                        float vw0 = v0 * LWv.x, vw1 = v1 * LWv.y;
                        p0 += v0 + v1;
                        p1 += v0 * v0 + v1 * v1;
                        pA += vw0 * ch0 + vw1 * ch1;
                        pB += vw0 * vw0 + vw1 * vw1;
                        pC += vw0 * LWv.x + vw1 * LWv.y;
                        pE += vw0 * LBv.x + vw1 * LBv.y;
                    }
                    int i = tm * 2 + h;
                    pm[i][0] += p0; pm[i][1] += p1; pm[i][2] += pA;
                    pm[i][3] += pB; pm[i][4] += pC; pm[i][5] += pE;
                }
            if (t < 31) {
#pragma unroll
                for (int i = 0; i < 16; i++)
#pragma unroll
                    for (int j = 0; j < 4; j++) d[i][j] = 0.f;
            }
        }
    }

    // ---- final reduce (red aliases CHAT region) ----
    __syncthreads();
    float* sred = (float*)(smem + OFF_CHAT);
#pragma unroll
    for (int tm = 0; tm < 2; tm++)
#pragma unroll
        for (int h = 0; h < 2; h++) {
            int i = tm * 2 + h;
            int row = 32 * wm + 16 * tm + 8 * h + qr;
#pragma unroll
            for (int o = 1; o <= 2; o <<= 1)
#pragma unroll
                for (int m = 0; m < 6; m++)
                    pm[i][m] += __shfl_down_sync(0xffffffffu, pm[i][m], o, 4);
            if (qc == 0) {
                float* rp = sred + (wn * 128 + row) * 8;
#pragma unroll
                for (int m = 0; m < 6; m++) rp[m] = pm[i][m];
            }
        }
    __syncthreads();
    if (tid < 128) {
        int row = tid, w = row & 63, nn = n0 + (row >> 6);
        float m0 = sred[row * 8 + 0] + sred[(128 + row) * 8 + 0];
        float m1 = sred[row * 8 + 1] + sred[(128 + row) * 8 + 1];
        float A  = sred[row * 8 + 2] + sred[(128 + row) * 8 + 2];
        float B  = sred[row * 8 + 3] + sred[(128 + row) * 8 + 3];
        float C  = sred[row * 8 + 4] + sred[(128 + row) * 8 + 4];
        float E  = sred[row * 8 + 5] + sred[(128 + row) * 8 + 5];
        float mu2 = m0 * (1.f / DD);
        float var = m1 * (1.f / DD) - mu2 * mu2;
        float k = rsqrtf(var + LN_EPS);
        float sww = g_scal[0], swb = g_scal[1], sbb = g_scal[2];
        float doty = k * (A - mu2 * g_swc[w]) + g_sbc[w];
        float ny2 = k * k * (B - 2.f * mu2 * C + mu2 * mu2 * sww)
                  + 2.f * k * (E - mu2 * swb) + sbb;
        float ny = sqrtf(fmaxf(ny2, 0.f));
        out[nn * NW + w] = TEMP_SC * doty / fmaxf(ny, 1e-12f);
    }
}

// ================= launch =================
extern "C" void kernel_launch(void* const* d_in, const int* in_sizes, int n_in,
                              void* d_out, int out_size) {
    const float* q    = (const float*)d_in[0];
    const float* cm   = (const float*)d_in[1];
    const float* ln1w = (const float*)d_in[2];
    const float* ln1b = (const float*)d_in[3];
    const float* w1   = (const float*)d_in[4];
    const float* b1   = (const float*)d_in[5];
    const float* w2   = (const float*)d_in[6];
    const float* b2   = (const float*)d_in[7];
    const float* ln2w = (const float*)d_in[8];
    const float* ln2b = (const float*)d_in[9];
    float* out = (float*)d_out;

    float *pQ1, *pC1, *pQW, *pS1, *pBB, *pS1W, *pBBW;
    cudaGetSymbolAddress((void**)&pQ1, g_Q1);
    cudaGetSymbolAddress((void**)&pC1, g_C1);
    cudaGetSymbolAddress((void**)&pQW, g_QW);
    cudaGetSymbolAddress((void**)&pS1, g_s1);
    cudaGetSymbolAddress((void**)&pBB, g_bb);
    cudaGetSymbolAddress((void**)&pS1W, g_s1w);
    cudaGetSymbolAddress((void**)&pBBW, g_bbw);

    cudaFuncSetAttribute(k_tc7, cudaFuncAttributeMaxDynamicSharedMemorySize, SMEM_TC);

    k_stats<<<2113, 256>>>(q, cm, ln2w, ln2b);
    k_w2h<<<dim3(16, 16), dim3(32, 8)>>>(w2);
    k_colsum<<<32, 256>>>(w1, D2, ln1w, ln1b, b1, pS1, pBB);
    k_gemm_fold2<<<dim3(33, 8), 256>>>(q, cm, w1, ln1w, pQ1, pC1);
    k_colsum<<<32, 256>>>(w2, DD, pS1, pBB, (const float*)nullptr, pS1W, pBBW);
    k_gemm_plain2<<<dim3(33, 8), 256>>>(pQ1, pC1, w2, pQW);
    k_tc7<<<NQ / 2, 256, SMEM_TC>>>(q, b2, ln2w, ln2b, out);
}